// round 10
// baseline (speedup 1.0000x reference)
#include <cuda_runtime.h>
#include <cstdint>

// Shapes (fixed)
#define BB   8
#define SS   512
#define MEM_ 512
#define LL   4
#define EE   512
#define HH   8
#define DH_  64
#define OBS_ 128
#define KK   1024   // MEM + S
#define LW   (EE*EE)

// ---------------- scratch (static device globals) -----------------------------
__device__ float g_x [BB*SS*EE];
__device__ float g_h [BB*SS*EE];
__device__ float g_hn[BB*SS*EE];
__device__ float g_t [BB*SS*EE];
__device__ float g_vk[BB*KK*EE];
__device__ float g_q [BB*SS*EE];
__device__ float g_k [BB*KK*EE];
__device__ float g_v [BB*KK*EE];
__device__ float g_o [BB*SS*EE];
__device__ float g_r [KK*EE];
__device__ float g_pe[KK*EE];
__device__ float g_sc[(long)BB*HH*SS*KK];   // final scores / probs (in-place)
__device__ float g_P [(long)BB*HH*SS*KK];   // rel-position term (unshifted)

// ---------------- helpers ------------------------------------------------------
__device__ __forceinline__ uint32_t f2tf32(float x) {
    uint32_t o;
    asm("cvt.rna.tf32.f32 %0, %1;" : "=r"(o) : "f"(x));
    return o;
}
__device__ __forceinline__ uint32_t smem_u32(const void* p) {
    uint32_t a;
    asm("{ .reg .u64 t; cvta.to.shared.u64 t, %1; cvt.u32.u64 %0, t; }"
        : "=r"(a) : "l"(p));
    return a;
}
__device__ __forceinline__ void cp_async16(uint32_t dst, const void* src) {
    asm volatile("cp.async.cg.shared.global [%0], [%1], 16;"
                 :: "r"(dst), "l"(src) : "memory");
}
__device__ __forceinline__ void cp_commit() {
    asm volatile("cp.async.commit_group;" ::: "memory");
}
__device__ __forceinline__ void cp_wait1() {
    asm volatile("cp.async.wait_group 1;" ::: "memory");
}
__device__ __forceinline__ void mma_tf32(float* d, const uint32_t* a, const uint32_t* b) {
    asm volatile(
        "mma.sync.aligned.m16n8k8.row.col.f32.tf32.tf32.f32 "
        "{%0,%1,%2,%3}, {%4,%5,%6,%7}, {%8,%9}, {%0,%1,%2,%3};"
        : "+f"(d[0]), "+f"(d[1]), "+f"(d[2]), "+f"(d[3])
        : "r"(a[0]), "r"(a[1]), "r"(a[2]), "r"(a[3]), "r"(b[0]), "r"(b[1]));
}
__device__ __forceinline__ float gelu_f(float x) {
    return 0.5f * x * (1.0f + tanhf(0.7978845608028654f * (x + 0.044715f * x * x * x)));
}

#define AS_STRIDE 36
#define BS_STRIDE 72
#define A_BUF (128 * AS_STRIDE)
#define B_BUF (32 * BS_STRIDE)

// ---------------- 128x128 tile cp.async tf32 GEMM (N multiple of 128) ----------
#define BS2_ST 136
#define B2_BUF (32 * BS2_ST)
#define STAGE2_FLOATS (A_BUF + B2_BUF)
#define CB_SMEM_BYTES (2 * STAGE2_FLOATS * 4)

template<int EPI>
__global__ __launch_bounds__(256)
void mma_gemm_cb(const float* __restrict__ A, long a_o, long a_i, int lda,
                 const float* __restrict__ B, long b_o, long b_i, int ldb,
                 float* __restrict__ C, long c_o, long c_i, int ldc,
                 const float* __restrict__ bias, const float* __restrict__ resid,
                 int Hd, int Kd) {
    extern __shared__ float smem[];
    const uint32_t sbase = smem_u32(smem);

    const int tid = threadIdx.x;
    const int z = blockIdx.z;
    const int m0 = blockIdx.y * 128;
    const int n0 = blockIdx.x * 128;

    const long aoff = ((long)(z / Hd)) * a_o + (long)(z % Hd) * a_i;
    const long boff = ((long)(z / Hd)) * b_o + (long)(z % Hd) * b_i;
    const long coff = ((long)(z / Hd)) * c_o + (long)(z % Hd) * c_i;
    const float* Ap = A + aoff + (long)m0 * lda;
    const float* Bp = B + boff + (long)n0;

    const int lane = tid & 31, w = tid >> 5;
    const int g = lane >> 2, t4 = lane & 3;
    const int wm = (w & 3) * 32;
    const int wn = (w >> 2) * 64;

    const int a_row = tid >> 3, a_c4 = (tid & 7) * 4;
    const int b_row = tid >> 5, b_c4 = (tid & 31) * 4;

    auto issue_stage = [&](int c, int s) {
        uint32_t sa = sbase + (uint32_t)(s * STAGE2_FLOATS) * 4u;
        uint32_t sb = sa + (uint32_t)A_BUF * 4u;
#pragma unroll
        for (int i = 0; i < 4; i++) {
            int row = a_row + i * 32;
            cp_async16(sa + (uint32_t)(row * AS_STRIDE + a_c4) * 4u,
                       Ap + (long)row * lda + c * 32 + a_c4);
        }
#pragma unroll
        for (int i = 0; i < 4; i++) {
            int kr = b_row + i * 8;
            cp_async16(sb + (uint32_t)(kr * BS2_ST + b_c4) * 4u,
                       Bp + (long)(c * 32 + kr) * ldb + b_c4);
        }
    };

    const int nch = Kd / 32;
    issue_stage(0, 0);
    cp_commit();

    float acc[2][8][4] = {};

    for (int c = 0; c < nch; c++) {
        if (c + 1 < nch) issue_stage(c + 1, (c + 1) & 1);
        cp_commit();
        cp_wait1();
        __syncthreads();

        const float* cA = smem + (c & 1) * STAGE2_FLOATS;
        const float* cB = cA + A_BUF;
#pragma unroll
        for (int ks = 0; ks < 4; ks++) {
            const int k = ks * 8;
            uint32_t af[2][4], bfr[8][2];
#pragma unroll
            for (int mt = 0; mt < 2; mt++) {
                const float* p = cA + (wm + mt * 16 + g) * AS_STRIDE + k + t4;
                af[mt][0] = f2tf32(p[0]);
                af[mt][1] = f2tf32(p[8 * AS_STRIDE]);
                af[mt][2] = f2tf32(p[4]);
                af[mt][3] = f2tf32(p[8 * AS_STRIDE + 4]);
            }
#pragma unroll
            for (int nt = 0; nt < 8; nt++) {
                const float* p = cB + (k + t4) * BS2_ST + wn + nt * 8 + g;
                bfr[nt][0] = f2tf32(p[0]);
                bfr[nt][1] = f2tf32(p[4 * BS2_ST]);
            }
#pragma unroll
            for (int mt = 0; mt < 2; mt++)
#pragma unroll
                for (int nt = 0; nt < 8; nt++)
                    mma_tf32(acc[mt][nt], af[mt], bfr[nt]);
        }
        __syncthreads();
    }

#pragma unroll
    for (int mt = 0; mt < 2; mt++) {
#pragma unroll
        for (int half = 0; half < 2; half++) {
            const int row = m0 + wm + mt * 16 + g + half * 8;
            float* Cr = C + coff + (long)row * ldc + n0;
            const float* Rr = (EPI == 3) ? (resid + coff + (long)row * ldc + n0) : nullptr;
#pragma unroll
            for (int nt = 0; nt < 8; nt++) {
                const int cn = wn + nt * 8 + t4 * 2;
                float2 o;
                o.x = acc[mt][nt][half * 2 + 0];
                o.y = acc[mt][nt][half * 2 + 1];
                if (EPI >= 1) {
                    float2 b2 = *(const float2*)(bias + n0 + cn);
                    o.x += b2.x; o.y += b2.y;
                }
                if (EPI == 2) { o.x = gelu_f(o.x); o.y = gelu_f(o.y); }
                if (EPI == 3) {
                    float2 r2 = *(const float2*)(Rr + cn);
                    o.x += r2.x; o.y += r2.y;
                }
                *(float2*)(Cr + cn) = o;
            }
        }
    }
}

// ---------------- 128x64 cp.async GEMM (probs@V: N=64) -------------------------
#define PIPE 2
#define STAGE_FLOATS (A_BUF + B_BUF)
#define CA_SMEM_BYTES (PIPE * STAGE_FLOATS * 4)

template<int EPI>
__global__ __launch_bounds__(256)
void mma_gemm_ca(const float* __restrict__ A, long a_o, long a_i, int lda,
                 const float* __restrict__ B, long b_o, long b_i, int ldb,
                 float* __restrict__ C, long c_o, long c_i, int ldc,
                 const float* __restrict__ bias, const float* __restrict__ resid,
                 int Hd, int Kd) {
    extern __shared__ float smem[];
    const uint32_t sbase = smem_u32(smem);

    const int tid = threadIdx.x;
    const int z = blockIdx.z;
    const int m0 = blockIdx.y * 128;
    const int n0 = blockIdx.x * 64;

    const long aoff = ((long)(z / Hd)) * a_o + (long)(z % Hd) * a_i;
    const long boff = ((long)(z / Hd)) * b_o + (long)(z % Hd) * b_i;
    const long coff = ((long)(z / Hd)) * c_o + (long)(z % Hd) * c_i;
    const float* Ap = A + aoff + (long)m0 * lda;
    const float* Bp = B + boff + (long)n0;

    const int lane = tid & 31, w = tid >> 5;
    const int g = lane >> 2, t4 = lane & 3;
    const int m_base = (w & 3) * 32;
    const int n_base = (w >> 2) * 32;

    const int a_row = tid >> 3, a_c4 = (tid & 7) * 4;
    const int b_kr = tid >> 4, b_c4 = (tid & 15) * 4;

    auto issue_stage = [&](int c, int s) {
        uint32_t sa = sbase + (uint32_t)(s * STAGE_FLOATS) * 4u;
        uint32_t sb = sa + (uint32_t)A_BUF * 4u;
#pragma unroll
        for (int i = 0; i < 4; i++) {
            int row = a_row + i * 32;
            cp_async16(sa + (uint32_t)(row * AS_STRIDE + a_c4) * 4u,
                       Ap + (long)row * lda + c * 32 + a_c4);
        }
#pragma unroll
        for (int i = 0; i < 2; i++) {
            int kr = b_kr + i * 16;
            cp_async16(sb + (uint32_t)(kr * BS_STRIDE + b_c4) * 4u,
                       Bp + (long)(c * 32 + kr) * ldb + b_c4);
        }
    };

    const int nch = Kd / 32;
    issue_stage(0, 0);
    cp_commit();

    float acc[2][4][4] = {};

    for (int c = 0; c < nch; c++) {
        if (c + 1 < nch) issue_stage(c + 1, (c + 1) & 1);
        cp_commit();
        cp_wait1();
        __syncthreads();

        const float* cA = smem + (c & 1) * STAGE_FLOATS;
        const float* cB = cA + A_BUF;
#pragma unroll
        for (int ks = 0; ks < 4; ks++) {
            const int k = ks * 8;
            uint32_t af[2][4], bfr[4][2];
#pragma unroll
            for (int mt = 0; mt < 2; mt++) {
                const float* p = cA + (m_base + mt * 16 + g) * AS_STRIDE + k + t4;
                af[mt][0] = f2tf32(p[0]);
                af[mt][1] = f2tf32(p[8 * AS_STRIDE]);
                af[mt][2] = f2tf32(p[4]);
                af[mt][3] = f2tf32(p[8 * AS_STRIDE + 4]);
            }
#pragma unroll
            for (int nt = 0; nt < 4; nt++) {
                const float* p = cB + (k + t4) * BS_STRIDE + n_base + nt * 8 + g;
                bfr[nt][0] = f2tf32(p[0]);
                bfr[nt][1] = f2tf32(p[4 * BS_STRIDE]);
            }
#pragma unroll
            for (int mt = 0; mt < 2; mt++)
#pragma unroll
                for (int nt = 0; nt < 4; nt++)
                    mma_tf32(acc[mt][nt], af[mt], bfr[nt]);
        }
        __syncthreads();
    }

#pragma unroll
    for (int mt = 0; mt < 2; mt++) {
#pragma unroll
        for (int half = 0; half < 2; half++) {
            const int row = m0 + m_base + mt * 16 + g + half * 8;
            float* Cr = C + coff + (long)row * ldc + n0;
            const float* Rr = (EPI == 3) ? (resid + coff + (long)row * ldc + n0) : nullptr;
#pragma unroll
            for (int nt = 0; nt < 4; nt++) {
                const int cn = n_base + nt * 8 + t4 * 2;
                float2 o;
                o.x = acc[mt][nt][half * 2 + 0];
                o.y = acc[mt][nt][half * 2 + 1];
                if (EPI >= 1) {
                    float2 b2 = *(const float2*)(bias + n0 + cn);
                    o.x += b2.x; o.y += b2.y;
                }
                if (EPI == 2) { o.x = gelu_f(o.x); o.y = gelu_f(o.y); }
                if (EPI == 3) {
                    float2 r2 = *(const float2*)(Rr + cn);
                    o.x += r2.x; o.y += r2.y;
                }
                *(float2*)(Cr + cn) = o;
            }
        }
    }
}

// ---------------- score GEMM (BTR+AADD), optional fused rel-shift P add --------
// FUSEP=1: C[i,j] = acc + Pmat[i, j + S-1 - i]  (valid exactly where j<=MEM+i)
#define SMEM_FLOATS (2 * (A_BUF + B_BUF))
#define SMEM_BYTES (SMEM_FLOATS * 4)

template<int FUSEP>
__global__ __launch_bounds__(256)
void mma_gemm_sc(const float* __restrict__ A, long a_o, long a_i, int lda,
                 const float* __restrict__ B, long b_o, long b_i, int ldb,
                 float* __restrict__ C, long c_o, long c_i, int ldc,
                 const float* __restrict__ addv, const float* __restrict__ Pmat,
                 int Hd, int Kd) {
    extern __shared__ float smem[];
    float* sA = smem;
    float* sB = smem + 2 * A_BUF;

    const int tid = threadIdx.x;
    const int z = blockIdx.z;
    const int m0 = blockIdx.y * 128;
    const int n0 = blockIdx.x * 64;

    const long aoff = ((long)(z / Hd)) * a_o + (long)(z % Hd) * a_i;
    const long boff = ((long)(z / Hd)) * b_o + (long)(z % Hd) * b_i;
    const long coff = ((long)(z / Hd)) * c_o + (long)(z % Hd) * c_i;
    const float* Ap = A + aoff + (long)m0 * lda;
    const float* Bp = B + boff + (long)n0 * ldb;
    const float* av = addv + (z % Hd) * DH_;

    const int lane = tid & 31, w = tid >> 5;
    const int g = lane >> 2, t4 = lane & 3;
    const int m_base = (w & 3) * 32;
    const int n_base = (w >> 2) * 32;

    float ra[16], rb[8];

    auto fetch = [&](int c) {
#pragma unroll
        for (int i = 0; i < 4; i++) {
            int q = tid + i * 256;
            int row = q >> 3, c4 = q & 7;
            float4 v = *(const float4*)(Ap + (long)row * lda + c * 32 + c4 * 4);
            float4 a4 = *(const float4*)(av + c * 32 + c4 * 4);
            v.x = (v.x + a4.x) * 0.125f; v.y = (v.y + a4.y) * 0.125f;
            v.z = (v.z + a4.z) * 0.125f; v.w = (v.w + a4.w) * 0.125f;
            ra[i*4+0] = v.x; ra[i*4+1] = v.y; ra[i*4+2] = v.z; ra[i*4+3] = v.w;
        }
#pragma unroll
        for (int i = 0; i < 2; i++) {
            int q = tid + i * 256;
            int nn = q >> 3, kc4 = q & 7;
            float4 v = *(const float4*)(Bp + (long)nn * ldb + c * 32 + kc4 * 4);
            rb[i*4+0] = v.x; rb[i*4+1] = v.y; rb[i*4+2] = v.z; rb[i*4+3] = v.w;
        }
    };
    auto stage = [&](int bf) {
        float* dA = sA + bf * A_BUF;
        float* dB = sB + bf * B_BUF;
#pragma unroll
        for (int i = 0; i < 4; i++) {
            int q = tid + i * 256;
            int row = q >> 3, c4 = q & 7;
            uint32_t* d = (uint32_t*)(dA + row * AS_STRIDE + c4 * 4);
            d[0] = f2tf32(ra[i*4+0]); d[1] = f2tf32(ra[i*4+1]);
            d[2] = f2tf32(ra[i*4+2]); d[3] = f2tf32(ra[i*4+3]);
        }
#pragma unroll
        for (int i = 0; i < 2; i++) {
            int q = tid + i * 256;
            int nn = q >> 3, kc4 = q & 7;
#pragma unroll
            for (int j = 0; j < 4; j++)
                *(uint32_t*)(dB + (kc4 * 4 + j) * BS_STRIDE + nn) = f2tf32(rb[i*4+j]);
        }
    };

    float acc[2][4][4] = {};
    const int nch = Kd / 32;

    fetch(0); stage(0);
    __syncthreads();

    for (int c = 0; c < nch; c++) {
        const int bf = c & 1;
        if (c + 1 < nch) fetch(c + 1);

        const float* cA = sA + bf * A_BUF;
        const float* cB = sB + bf * B_BUF;
#pragma unroll
        for (int ks = 0; ks < 4; ks++) {
            const int k = ks * 8;
            uint32_t af[2][4], bfr[4][2];
#pragma unroll
            for (int mt = 0; mt < 2; mt++) {
                const float* p = cA + (m_base + mt * 16 + g) * AS_STRIDE + k + t4;
                af[mt][0] = __float_as_uint(p[0]);
                af[mt][1] = __float_as_uint(p[8 * AS_STRIDE]);
                af[mt][2] = __float_as_uint(p[4]);
                af[mt][3] = __float_as_uint(p[8 * AS_STRIDE + 4]);
            }
#pragma unroll
            for (int nt = 0; nt < 4; nt++) {
                const float* p = cB + (k + t4) * BS_STRIDE + n_base + nt * 8 + g;
                bfr[nt][0] = __float_as_uint(p[0]);
                bfr[nt][1] = __float_as_uint(p[4 * BS_STRIDE]);
            }
#pragma unroll
            for (int mt = 0; mt < 2; mt++)
#pragma unroll
                for (int nt = 0; nt < 4; nt++)
                    mma_tf32(acc[mt][nt], af[mt], bfr[nt]);
        }
        if (c + 1 < nch) stage((c + 1) & 1);
        __syncthreads();
    }

#pragma unroll
    for (int mt = 0; mt < 2; mt++) {
#pragma unroll
        for (int half = 0; half < 2; half++) {
            const int row = m0 + m_base + mt * 16 + g + half * 8;   // local i in [0,S)
            float* Cr = C + coff + (long)row * ldc + n0;
            const float* Pr = FUSEP ? (Pmat + coff + (long)row * KK) : nullptr;
            const int shift = (SS - 1) - row;                        // >= 0
#pragma unroll
            for (int nt = 0; nt < 4; nt++) {
                const int cn = n_base + nt * 8 + t4 * 2;
                float2 o;
                o.x = acc[mt][nt][half * 2 + 0];
                o.y = acc[mt][nt][half * 2 + 1];
                if (FUSEP) {
                    int p0 = n0 + cn + shift;
                    int p1 = p0 + 1;
                    if (p0 < KK) o.x += Pr[p0];
                    if (p1 < KK) o.y += Pr[p1];
                }
                *(float2*)(Cr + cn) = o;
            }
        }
    }
}

// ---------------- positional embedding ----------------------------------------
__global__ void pe_kernel(float* __restrict__ pe) {
    int idx = blockIdx.x * 256 + threadIdx.x;
    int m = idx >> 9, c = idx & 511;
    double pos  = (double)(KK - m);
    int    t2   = c & 255;
    double invf = exp(-((double)(2 * t2) / 512.0) * log(10000.0));
    double a    = pos * invf;
    pe[idx] = (float)((c < 256) ? sin(a) : cos(a));
}

// ---------------- layer norm ---------------------------------------------------
__device__ __forceinline__ void ln_row(const float* __restrict__ src,
                                       float* __restrict__ dst,
                                       const float* __restrict__ g,
                                       const float* __restrict__ be, int lane) {
    float4 vals[4];
    float s = 0.f, ss = 0.f;
#pragma unroll
    for (int t = 0; t < 4; t++) {
        vals[t] = *(const float4*)(src + lane * 4 + t * 128);
        s  += vals[t].x + vals[t].y + vals[t].z + vals[t].w;
        ss += vals[t].x*vals[t].x + vals[t].y*vals[t].y
            + vals[t].z*vals[t].z + vals[t].w*vals[t].w;
    }
#pragma unroll
    for (int o = 16; o; o >>= 1) {
        s  += __shfl_xor_sync(0xffffffffu, s,  o);
        ss += __shfl_xor_sync(0xffffffffu, ss, o);
    }
    float mean = s * (1.f / 512.f);
    float var  = ss * (1.f / 512.f) - mean * mean;
    float rstd = rsqrtf(var + 1e-6f);
#pragma unroll
    for (int t = 0; t < 4; t++) {
        int e = lane * 4 + t * 128;
        float4 o4;
        o4.x = (vals[t].x - mean) * rstd * g[e+0] + be[e+0];
        o4.y = (vals[t].y - mean) * rstd * g[e+1] + be[e+1];
        o4.z = (vals[t].z - mean) * rstd * g[e+2] + be[e+2];
        o4.w = (vals[t].w - mean) * rstd * g[e+3] + be[e+3];
        *(float4*)(dst + e) = o4;
    }
}

__global__ void ln_concat_k(const float* __restrict__ mem, const float* __restrict__ x,
                            const float* __restrict__ gam, const float* __restrict__ bet,
                            float* __restrict__ out, int l) {
    int row  = blockIdx.x * 8 + (threadIdx.x >> 5);
    int lane = threadIdx.x & 31;
    int b = row >> 10, j = row & 1023;
    const float* src = (j < MEM_)
        ? (mem + ((long)(b * MEM_ + j) * LL + l) * EE)
        : (x   +  (long)(b * SS + (j - MEM_)) * EE);
    ln_row(src, out + (long)row * EE, gam + l * EE, bet + l * EE, lane);
}

__global__ void ln_plain_k(const float* __restrict__ in,
                           const float* __restrict__ gam, const float* __restrict__ bet,
                           float* __restrict__ out, int l) {
    int row  = blockIdx.x * 8 + (threadIdx.x >> 5);
    int lane = threadIdx.x & 31;
    ln_row(in + (long)row * EE, out + (long)row * EE, gam + l * EE, bet + l * EE, lane);
}

// ---------------- masked softmax (scores already combined; warp per row) -------
__global__ __launch_bounds__(256)
void softmax_k(float* __restrict__ sc) {
    long row = (long)blockIdx.x * 8 + (threadIdx.x >> 5);
    int lane = threadIdx.x & 31;
    int i = (int)(row & (SS - 1));
    int jmax = MEM_ + i;
    float* srow = sc + row * KK;
    float v[32];
    float mx = -1e30f;
#pragma unroll
    for (int t = 0; t < 32; t++) {
        int j = t * 32 + lane;
        float x = (j <= jmax) ? srow[j] : -1e30f;
        v[t] = x;
        mx = fmaxf(mx, x);
    }
#pragma unroll
    for (int o = 16; o; o >>= 1) mx = fmaxf(mx, __shfl_xor_sync(0xffffffffu, mx, o));
    float s = 0.f;
#pragma unroll
    for (int t = 0; t < 32; t++) {
        float e = (v[t] > -1e29f) ? __expf(v[t] - mx) : 0.f;
        v[t] = e; s += e;
    }
#pragma unroll
    for (int o = 16; o; o >>= 1) s += __shfl_xor_sync(0xffffffffu, s, o);
    float inv = 1.f / s;
#pragma unroll
    for (int t = 0; t < 32; t++) srow[t * 32 + lane] = v[t] * inv;
}

// ---------------- host orchestration ------------------------------------------
extern "C" void kernel_launch(void* const* d_in, const int* in_sizes, int n_in,
                              void* d_out, int out_size) {
    (void)in_sizes; (void)n_in; (void)out_size;
    const float* obs    = (const float*)d_in[0];
    const float* mems   = (const float*)d_in[1];
    const float* W_enc  = (const float*)d_in[3];
    const float* b_enc  = (const float*)d_in[4];
    const float* ln1_s  = (const float*)d_in[5];
    const float* ln1_b  = (const float*)d_in[6];
    const float* Wq     = (const float*)d_in[7];
    const float* bq     = (const float*)d_in[8];
    const float* Wk     = (const float*)d_in[9];
    const float* bk     = (const float*)d_in[10];
    const float* Wv     = (const float*)d_in[11];
    const float* bv     = (const float*)d_in[12];
    const float* Wr     = (const float*)d_in[13];
    const float* ub     = (const float*)d_in[14];
    const float* vbias  = (const float*)d_in[15];
    const float* Wo     = (const float*)d_in[16];
    const float* bo     = (const float*)d_in[17];
    const float* ln2_s  = (const float*)d_in[18];
    const float* ln2_b  = (const float*)d_in[19];
    const float* W1     = (const float*)d_in[20];
    const float* b1     = (const float*)d_in[21];
    const float* W2     = (const float*)d_in[22];
    const float* b2     = (const float*)d_in[23];
    float* out = (float*)d_out;

    float *px, *ph, *phn, *pt, *pvk, *pq, *pk, *pv_, *po, *pr, *ppe, *psc, *pP;
    cudaGetSymbolAddress((void**)&px,  g_x);
    cudaGetSymbolAddress((void**)&ph,  g_h);
    cudaGetSymbolAddress((void**)&phn, g_hn);
    cudaGetSymbolAddress((void**)&pt,  g_t);
    cudaGetSymbolAddress((void**)&pvk, g_vk);
    cudaGetSymbolAddress((void**)&pq,  g_q);
    cudaGetSymbolAddress((void**)&pk,  g_k);
    cudaGetSymbolAddress((void**)&pv_, g_v);
    cudaGetSymbolAddress((void**)&po,  g_o);
    cudaGetSymbolAddress((void**)&pr,  g_r);
    cudaGetSymbolAddress((void**)&ppe, g_pe);
    cudaGetSymbolAddress((void**)&psc, g_sc);
    cudaGetSymbolAddress((void**)&pP,  g_P);

    cudaFuncSetAttribute(mma_gemm_cb<0>, cudaFuncAttributeMaxDynamicSharedMemorySize, CB_SMEM_BYTES);
    cudaFuncSetAttribute(mma_gemm_cb<1>, cudaFuncAttributeMaxDynamicSharedMemorySize, CB_SMEM_BYTES);
    cudaFuncSetAttribute(mma_gemm_cb<2>, cudaFuncAttributeMaxDynamicSharedMemorySize, CB_SMEM_BYTES);
    cudaFuncSetAttribute(mma_gemm_cb<3>, cudaFuncAttributeMaxDynamicSharedMemorySize, CB_SMEM_BYTES);
    cudaFuncSetAttribute(mma_gemm_ca<0>, cudaFuncAttributeMaxDynamicSharedMemorySize, CA_SMEM_BYTES);
    cudaFuncSetAttribute(mma_gemm_sc<0>, cudaFuncAttributeMaxDynamicSharedMemorySize, SMEM_BYTES);
    cudaFuncSetAttribute(mma_gemm_sc<1>, cudaFuncAttributeMaxDynamicSharedMemorySize, SMEM_BYTES);

    const long SE = (long)SS * EE, KE = (long)KK * EE, SK = (long)SS * KK;
    const long HSK = (long)HH * SK;

    // encoder: x = obs @ W_enc + b_enc
    mma_gemm_cb<1><<<dim3(4, 32, 1), 256, CB_SMEM_BYTES>>>(
        obs, 0, 0, OBS_, W_enc, 0, 0, EE, px, 0, 0, EE,
        b_enc, nullptr, 1, OBS_);
    pe_kernel<<<(KK * EE) / 256, 256>>>(ppe);

    for (int l = 0; l < LL; l++) {
        ln_concat_k<<<(BB * KK) / 8, 256>>>(mems, px, ln1_s, ln1_b, pvk, l);

        mma_gemm_cb<1><<<dim3(4, 64, 1), 256, CB_SMEM_BYTES>>>(
            pvk, 0, 0, EE, Wk + (long)l * LW, 0, 0, EE, pk, 0, 0, EE,
            bk + l * EE, nullptr, 1, EE);
        mma_gemm_cb<1><<<dim3(4, 64, 1), 256, CB_SMEM_BYTES>>>(
            pvk, 0, 0, EE, Wv + (long)l * LW, 0, 0, EE, pv_, 0, 0, EE,
            bv + l * EE, nullptr, 1, EE);
        mma_gemm_cb<1><<<dim3(4, 4, BB), 256, CB_SMEM_BYTES>>>(
            pvk + (long)MEM_ * EE, KE, 0, EE, Wq + (long)l * LW, 0, 0, EE,
            pq, SE, 0, EE, bq + l * EE, nullptr, 1, EE);
        mma_gemm_cb<0><<<dim3(4, 8, 1), 256, CB_SMEM_BYTES>>>(
            ppe, 0, 0, EE, Wr + (long)l * LW, 0, 0, EE, pr, 0, 0, EE,
            nullptr, nullptr, 1, EE);

        // P = ((q+v)*0.125) @ r^T   (must precede AC which consumes it)
        mma_gemm_sc<0><<<dim3(16, 4, BB*HH), 256, SMEM_BYTES>>>(
            pq, SE, DH_, EE, pr, 0, DH_, EE, pP, HSK, SK, KK,
            vbias + (long)l * EE, nullptr, HH, DH_);
        // sc = ((q+u)*0.125) @ k^T + shift(P)   (fused rel-shift add in epilogue)
        mma_gemm_sc<1><<<dim3(16, 4, BB*HH), 256, SMEM_BYTES>>>(
            pq, SE, DH_, EE, pk, KE, DH_, EE, psc, HSK, SK, KK,
            ub + (long)l * EE, pP, HH, DH_);

        softmax_k<<<(BB * HH * SS) / 8, 256>>>(psc);

        // o = probs @ v
        mma_gemm_ca<0><<<dim3(1, 4, BB*HH), 256, CA_SMEM_BYTES>>>(
            psc, HSK, SK, KK, pv_, KE, DH_, EE, po, SE, DH_, EE,
            nullptr, nullptr, HH, KK);

        mma_gemm_cb<3><<<dim3(4, 32, 1), 256, CB_SMEM_BYTES>>>(
            po, 0, 0, EE, Wo + (long)l * LW, 0, 0, EE, ph, 0, 0, EE,
            bo + l * EE, px, 1, EE);
        ln_plain_k<<<(BB * SS) / 8, 256>>>(ph, ln2_s, ln2_b, phn, l);
        mma_gemm_cb<2><<<dim3(4, 32, 1), 256, CB_SMEM_BYTES>>>(
            phn, 0, 0, EE, W1 + (long)l * LW, 0, 0, EE, pt, 0, 0, EE,
            b1 + l * EE, nullptr, 1, EE);
        float* xo = (l == LL - 1) ? out : px;
        mma_gemm_cb<3><<<dim3(4, 32, 1), 256, CB_SMEM_BYTES>>>(
            pt, 0, 0, EE, W2 + (long)l * LW, 0, 0, EE, xo, 0, 0, EE,
            b2 + l * EE, ph, 1, EE);
    }
}

// round 11
// speedup vs baseline: 1.1160x; 1.1160x over previous
#include <cuda_runtime.h>
#include <cstdint>

// Shapes (fixed)
#define BB   8
#define SS   512
#define MEM_ 512
#define LL   4
#define EE   512
#define HH   8
#define DH_  64
#define OBS_ 128
#define KK   1024   // MEM + S
#define LW   (EE*EE)

// ---------------- scratch (static device globals) -----------------------------
__device__ float g_x [BB*SS*EE];
__device__ float g_h [BB*SS*EE];
__device__ float g_hn[BB*SS*EE];
__device__ float g_t [BB*SS*EE];
__device__ float g_vk[BB*KK*EE];
__device__ float g_q [BB*SS*EE];
__device__ float g_k [BB*KK*EE];
__device__ float g_v [BB*KK*EE];
__device__ float g_o [BB*SS*EE];
__device__ float g_r [KK*EE];
__device__ float g_pe[KK*EE];
__device__ float g_sc[(long)BB*HH*SS*KK];   // AC scores / probs (in-place)
__device__ float g_P [(long)BB*HH*SS*KK];   // rel-position term (unshifted)
__device__ float g_cu[BB*HH*KK];            // 0.125 * u  @ k^T  per (b,h,j)
__device__ float g_cv[HH*KK];               // 0.125 * vb @ r^T  per (h,p)

// ---------------- helpers ------------------------------------------------------
__device__ __forceinline__ uint32_t f2tf32(float x) {
    uint32_t o;
    asm("cvt.rna.tf32.f32 %0, %1;" : "=r"(o) : "f"(x));
    return o;
}
__device__ __forceinline__ uint32_t smem_u32(const void* p) {
    uint32_t a;
    asm("{ .reg .u64 t; cvta.to.shared.u64 t, %1; cvt.u32.u64 %0, t; }"
        : "=r"(a) : "l"(p));
    return a;
}
__device__ __forceinline__ void cp_async16(uint32_t dst, const void* src) {
    asm volatile("cp.async.cg.shared.global [%0], [%1], 16;"
                 :: "r"(dst), "l"(src) : "memory");
}
__device__ __forceinline__ void cp_commit() {
    asm volatile("cp.async.commit_group;" ::: "memory");
}
__device__ __forceinline__ void cp_wait1() {
    asm volatile("cp.async.wait_group 1;" ::: "memory");
}
__device__ __forceinline__ void mma_tf32(float* d, const uint32_t* a, const uint32_t* b) {
    asm volatile(
        "mma.sync.aligned.m16n8k8.row.col.f32.tf32.tf32.f32 "
        "{%0,%1,%2,%3}, {%4,%5,%6,%7}, {%8,%9}, {%0,%1,%2,%3};"
        : "+f"(d[0]), "+f"(d[1]), "+f"(d[2]), "+f"(d[3])
        : "r"(a[0]), "r"(a[1]), "r"(a[2]), "r"(a[3]), "r"(b[0]), "r"(b[1]));
}
__device__ __forceinline__ float gelu_f(float x) {
    return 0.5f * x * (1.0f + tanhf(0.7978845608028654f * (x + 0.044715f * x * x * x)));
}

#define AS_STRIDE 36
#define BS_STRIDE 72
#define A_BUF (128 * AS_STRIDE)
#define B_BUF (32 * BS_STRIDE)

// ---------------- 128x128 tile cp.async tf32 GEMM (N multiple of 128) ----------
#define BS2_ST 136
#define B2_BUF (32 * BS2_ST)
#define STAGE2_FLOATS (A_BUF + B2_BUF)
#define CB_SMEM_BYTES (2 * STAGE2_FLOATS * 4)

template<int EPI>
__global__ __launch_bounds__(256)
void mma_gemm_cb(const float* __restrict__ A, long a_o, long a_i, int lda,
                 const float* __restrict__ B, long b_o, long b_i, int ldb,
                 float* __restrict__ C, long c_o, long c_i, int ldc,
                 const float* __restrict__ bias, const float* __restrict__ resid,
                 int Hd, int Kd) {
    extern __shared__ float smem[];
    const uint32_t sbase = smem_u32(smem);

    const int tid = threadIdx.x;
    const int z = blockIdx.z;
    const int m0 = blockIdx.y * 128;
    const int n0 = blockIdx.x * 128;

    const long aoff = ((long)(z / Hd)) * a_o + (long)(z % Hd) * a_i;
    const long boff = ((long)(z / Hd)) * b_o + (long)(z % Hd) * b_i;
    const long coff = ((long)(z / Hd)) * c_o + (long)(z % Hd) * c_i;
    const float* Ap = A + aoff + (long)m0 * lda;
    const float* Bp = B + boff + (long)n0;

    const int lane = tid & 31, w = tid >> 5;
    const int g = lane >> 2, t4 = lane & 3;
    const int wm = (w & 3) * 32;
    const int wn = (w >> 2) * 64;

    const int a_row = tid >> 3, a_c4 = (tid & 7) * 4;
    const int b_row = tid >> 5, b_c4 = (tid & 31) * 4;

    auto issue_stage = [&](int c, int s) {
        uint32_t sa = sbase + (uint32_t)(s * STAGE2_FLOATS) * 4u;
        uint32_t sb = sa + (uint32_t)A_BUF * 4u;
#pragma unroll
        for (int i = 0; i < 4; i++) {
            int row = a_row + i * 32;
            cp_async16(sa + (uint32_t)(row * AS_STRIDE + a_c4) * 4u,
                       Ap + (long)row * lda + c * 32 + a_c4);
        }
#pragma unroll
        for (int i = 0; i < 4; i++) {
            int kr = b_row + i * 8;
            cp_async16(sb + (uint32_t)(kr * BS2_ST + b_c4) * 4u,
                       Bp + (long)(c * 32 + kr) * ldb + b_c4);
        }
    };

    const int nch = Kd / 32;
    issue_stage(0, 0);
    cp_commit();

    float acc[2][8][4] = {};

    for (int c = 0; c < nch; c++) {
        if (c + 1 < nch) issue_stage(c + 1, (c + 1) & 1);
        cp_commit();
        cp_wait1();
        __syncthreads();

        const float* cA = smem + (c & 1) * STAGE2_FLOATS;
        const float* cB = cA + A_BUF;
#pragma unroll
        for (int ks = 0; ks < 4; ks++) {
            const int k = ks * 8;
            uint32_t af[2][4], bfr[8][2];
#pragma unroll
            for (int mt = 0; mt < 2; mt++) {
                const float* p = cA + (wm + mt * 16 + g) * AS_STRIDE + k + t4;
                af[mt][0] = f2tf32(p[0]);
                af[mt][1] = f2tf32(p[8 * AS_STRIDE]);
                af[mt][2] = f2tf32(p[4]);
                af[mt][3] = f2tf32(p[8 * AS_STRIDE + 4]);
            }
#pragma unroll
            for (int nt = 0; nt < 8; nt++) {
                const float* p = cB + (k + t4) * BS2_ST + wn + nt * 8 + g;
                bfr[nt][0] = f2tf32(p[0]);
                bfr[nt][1] = f2tf32(p[4 * BS2_ST]);
            }
#pragma unroll
            for (int mt = 0; mt < 2; mt++)
#pragma unroll
                for (int nt = 0; nt < 8; nt++)
                    mma_tf32(acc[mt][nt], af[mt], bfr[nt]);
        }
        __syncthreads();
    }

#pragma unroll
    for (int mt = 0; mt < 2; mt++) {
#pragma unroll
        for (int half = 0; half < 2; half++) {
            const int row = m0 + wm + mt * 16 + g + half * 8;
            float* Cr = C + coff + (long)row * ldc + n0;
            const float* Rr = (EPI == 3) ? (resid + coff + (long)row * ldc + n0) : nullptr;
#pragma unroll
            for (int nt = 0; nt < 8; nt++) {
                const int cn = wn + nt * 8 + t4 * 2;
                float2 o;
                o.x = acc[mt][nt][half * 2 + 0];
                o.y = acc[mt][nt][half * 2 + 1];
                if (EPI >= 1) {
                    float2 b2 = *(const float2*)(bias + n0 + cn);
                    o.x += b2.x; o.y += b2.y;
                }
                if (EPI == 2) { o.x = gelu_f(o.x); o.y = gelu_f(o.y); }
                if (EPI == 3) {
                    float2 r2 = *(const float2*)(Rr + cn);
                    o.x += r2.x; o.y += r2.y;
                }
                *(float2*)(Cr + cn) = o;
            }
        }
    }
}

// ---------------- score GEMM: C = 0.125 * A@B^T + colbias ----------------------
// A [m, dh] rows of q; B = k or r in NATIVE [keys, dh] layout (= col-major B for
// mma.row.col -> no transpose needed). Kd = 64 (2 chunks). Tile 128x128.
#define QK_A_BUF (128 * AS_STRIDE)
#define QK_STAGE (2 * QK_A_BUF)              // A tile + B tile, same shape
#define QK_SMEM_BYTES (2 * QK_STAGE * 4)

__global__ __launch_bounds__(256)
void mma_gemm_qk(const float* __restrict__ A, long a_o, long a_i,
                 const float* __restrict__ B, long b_o, long b_i,
                 float* __restrict__ C, long c_o, long c_i,
                 const float* __restrict__ cb, long cb_o, long cb_i,
                 int Hd) {
    extern __shared__ float smem[];
    const uint32_t sbase = smem_u32(smem);

    const int tid = threadIdx.x;
    const int z = blockIdx.z;
    const int m0 = blockIdx.y * 128;
    const int n0 = blockIdx.x * 128;

    const float* Ap = A + ((long)(z / Hd)) * a_o + (long)(z % Hd) * a_i
                        + (long)m0 * EE;
    const float* Bp = B + ((long)(z / Hd)) * b_o + (long)(z % Hd) * b_i
                        + (long)n0 * EE;
    const long coff = ((long)(z / Hd)) * c_o + (long)(z % Hd) * c_i;
    const float* cbp = cb + ((long)(z / Hd)) * cb_o + (long)(z % Hd) * cb_i + n0;

    const int lane = tid & 31, w = tid >> 5;
    const int g = lane >> 2, t4 = lane & 3;
    const int wm = (w & 3) * 32;
    const int wn = (w >> 2) * 64;

    const int a_row = tid >> 3, a_c4 = (tid & 7) * 4;

    auto issue_stage = [&](int c, int s) {
        uint32_t sa = sbase + (uint32_t)(s * QK_STAGE) * 4u;
        uint32_t sb = sa + (uint32_t)QK_A_BUF * 4u;
#pragma unroll
        for (int i = 0; i < 4; i++) {
            int row = a_row + i * 32;
            cp_async16(sa + (uint32_t)(row * AS_STRIDE + a_c4) * 4u,
                       Ap + (long)row * EE + c * 32 + a_c4);
            cp_async16(sb + (uint32_t)(row * AS_STRIDE + a_c4) * 4u,
                       Bp + (long)row * EE + c * 32 + a_c4);
        }
    };

    issue_stage(0, 0);
    cp_commit();

    float acc[2][8][4] = {};

#pragma unroll
    for (int c = 0; c < 2; c++) {                 // Kd = 64 fixed
        if (c == 0) issue_stage(1, 1);
        cp_commit();
        cp_wait1();
        __syncthreads();

        const float* cA = smem + (c & 1) * QK_STAGE;
        const float* cB = cA + QK_A_BUF;
#pragma unroll
        for (int ks = 0; ks < 4; ks++) {
            const int k = ks * 8;
            uint32_t af[2][4], bfr[8][2];
#pragma unroll
            for (int mt = 0; mt < 2; mt++) {
                const float* p = cA + (wm + mt * 16 + g) * AS_STRIDE + k + t4;
                af[mt][0] = f2tf32(p[0]);
                af[mt][1] = f2tf32(p[8 * AS_STRIDE]);
                af[mt][2] = f2tf32(p[4]);
                af[mt][3] = f2tf32(p[8 * AS_STRIDE + 4]);
            }
#pragma unroll
            for (int nt = 0; nt < 8; nt++) {
                // B fragment (col-major): b0=B[k+t4][n], b1=B[k+t4+4][n]; tile is n-major
                const float* p = cB + (wn + nt * 8 + g) * AS_STRIDE + k + t4;
                bfr[nt][0] = f2tf32(p[0]);
                bfr[nt][1] = f2tf32(p[4]);
            }
#pragma unroll
            for (int mt = 0; mt < 2; mt++)
#pragma unroll
                for (int nt = 0; nt < 8; nt++)
                    mma_tf32(acc[mt][nt], af[mt], bfr[nt]);
        }
        __syncthreads();
    }

#pragma unroll
    for (int mt = 0; mt < 2; mt++) {
#pragma unroll
        for (int half = 0; half < 2; half++) {
            const int row = m0 + wm + mt * 16 + g + half * 8;
            float* Cr = C + coff + (long)row * KK + n0;
#pragma unroll
            for (int nt = 0; nt < 8; nt++) {
                const int cn = wn + nt * 8 + t4 * 2;
                float2 b2 = *(const float2*)(cbp + cn);
                float2 o;
                o.x = acc[mt][nt][half * 2 + 0] * 0.125f + b2.x;
                o.y = acc[mt][nt][half * 2 + 1] * 0.125f + b2.y;
                *(float2*)(Cr + cn) = o;
            }
        }
    }
}

// ---------------- column-bias prep: out[b,h,j] = 0.125 * sum_d u[h,d]*k[b,j,h*64+d]
__global__ __launch_bounds__(256)
void bias_uk(const float* __restrict__ kmat, long bstride,
             const float* __restrict__ uvec,
             float* __restrict__ out, long obstride) {
    int b = blockIdx.y;
    int j = blockIdx.x * 8 + (threadIdx.x >> 5);
    int lane = threadIdx.x & 31;
    const float* krow = kmat + (long)b * bstride + (long)j * EE;
    float* orow = out + (long)b * obstride;
#pragma unroll
    for (int h = 0; h < HH; h++) {
        float s = krow[h * 64 + lane]      * uvec[h * 64 + lane]
                + krow[h * 64 + lane + 32] * uvec[h * 64 + lane + 32];
#pragma unroll
        for (int o = 16; o; o >>= 1) s += __shfl_xor_sync(0xffffffffu, s, o);
        if (lane == 0) orow[h * KK + j] = 0.125f * s;
    }
}

// ---------------- 128x64 cp.async GEMM (probs@V: N=64) -------------------------
#define PIPE 2
#define STAGE_FLOATS (A_BUF + B_BUF)
#define CA_SMEM_BYTES (PIPE * STAGE_FLOATS * 4)

template<int EPI>
__global__ __launch_bounds__(256)
void mma_gemm_ca(const float* __restrict__ A, long a_o, long a_i, int lda,
                 const float* __restrict__ B, long b_o, long b_i, int ldb,
                 float* __restrict__ C, long c_o, long c_i, int ldc,
                 const float* __restrict__ bias, const float* __restrict__ resid,
                 int Hd, int Kd) {
    extern __shared__ float smem[];
    const uint32_t sbase = smem_u32(smem);

    const int tid = threadIdx.x;
    const int z = blockIdx.z;
    const int m0 = blockIdx.y * 128;
    const int n0 = blockIdx.x * 64;

    const long aoff = ((long)(z / Hd)) * a_o + (long)(z % Hd) * a_i;
    const long boff = ((long)(z / Hd)) * b_o + (long)(z % Hd) * b_i;
    const long coff = ((long)(z / Hd)) * c_o + (long)(z % Hd) * c_i;
    const float* Ap = A + aoff + (long)m0 * lda;
    const float* Bp = B + boff + (long)n0;

    const int lane = tid & 31, w = tid >> 5;
    const int g = lane >> 2, t4 = lane & 3;
    const int m_base = (w & 3) * 32;
    const int n_base = (w >> 2) * 32;

    const int a_row = tid >> 3, a_c4 = (tid & 7) * 4;
    const int b_kr = tid >> 4, b_c4 = (tid & 15) * 4;

    auto issue_stage = [&](int c, int s) {
        uint32_t sa = sbase + (uint32_t)(s * STAGE_FLOATS) * 4u;
        uint32_t sb = sa + (uint32_t)A_BUF * 4u;
#pragma unroll
        for (int i = 0; i < 4; i++) {
            int row = a_row + i * 32;
            cp_async16(sa + (uint32_t)(row * AS_STRIDE + a_c4) * 4u,
                       Ap + (long)row * lda + c * 32 + a_c4);
        }
#pragma unroll
        for (int i = 0; i < 2; i++) {
            int kr = b_kr + i * 16;
            cp_async16(sb + (uint32_t)(kr * BS_STRIDE + b_c4) * 4u,
                       Bp + (long)(c * 32 + kr) * ldb + b_c4);
        }
    };

    const int nch = Kd / 32;
    issue_stage(0, 0);
    cp_commit();

    float acc[2][4][4] = {};

    for (int c = 0; c < nch; c++) {
        if (c + 1 < nch) issue_stage(c + 1, (c + 1) & 1);
        cp_commit();
        cp_wait1();
        __syncthreads();

        const float* cA = smem + (c & 1) * STAGE_FLOATS;
        const float* cB = cA + A_BUF;
#pragma unroll
        for (int ks = 0; ks < 4; ks++) {
            const int k = ks * 8;
            uint32_t af[2][4], bfr[4][2];
#pragma unroll
            for (int mt = 0; mt < 2; mt++) {
                const float* p = cA + (m_base + mt * 16 + g) * AS_STRIDE + k + t4;
                af[mt][0] = f2tf32(p[0]);
                af[mt][1] = f2tf32(p[8 * AS_STRIDE]);
                af[mt][2] = f2tf32(p[4]);
                af[mt][3] = f2tf32(p[8 * AS_STRIDE + 4]);
            }
#pragma unroll
            for (int nt = 0; nt < 4; nt++) {
                const float* p = cB + (k + t4) * BS_STRIDE + n_base + nt * 8 + g;
                bfr[nt][0] = f2tf32(p[0]);
                bfr[nt][1] = f2tf32(p[4 * BS_STRIDE]);
            }
#pragma unroll
            for (int mt = 0; mt < 2; mt++)
#pragma unroll
                for (int nt = 0; nt < 4; nt++)
                    mma_tf32(acc[mt][nt], af[mt], bfr[nt]);
        }
        __syncthreads();
    }

#pragma unroll
    for (int mt = 0; mt < 2; mt++) {
#pragma unroll
        for (int half = 0; half < 2; half++) {
            const int row = m0 + m_base + mt * 16 + g + half * 8;
            float* Cr = C + coff + (long)row * ldc + n0;
            const float* Rr = (EPI == 3) ? (resid + coff + (long)row * ldc + n0) : nullptr;
#pragma unroll
            for (int nt = 0; nt < 4; nt++) {
                const int cn = n_base + nt * 8 + t4 * 2;
                float2 o;
                o.x = acc[mt][nt][half * 2 + 0];
                o.y = acc[mt][nt][half * 2 + 1];
                if (EPI >= 1) {
                    float2 b2 = *(const float2*)(bias + n0 + cn);
                    o.x += b2.x; o.y += b2.y;
                }
                if (EPI == 2) { o.x = gelu_f(o.x); o.y = gelu_f(o.y); }
                if (EPI == 3) {
                    float2 r2 = *(const float2*)(Rr + cn);
                    o.x += r2.x; o.y += r2.y;
                }
                *(float2*)(Cr + cn) = o;
            }
        }
    }
}

// ---------------- positional embedding ----------------------------------------
__global__ void pe_kernel(float* __restrict__ pe) {
    int idx = blockIdx.x * 256 + threadIdx.x;
    int m = idx >> 9, c = idx & 511;
    double pos  = (double)(KK - m);
    int    t2   = c & 255;
    double invf = exp(-((double)(2 * t2) / 512.0) * log(10000.0));
    double a    = pos * invf;
    pe[idx] = (float)((c < 256) ? sin(a) : cos(a));
}

// ---------------- layer norm ---------------------------------------------------
__device__ __forceinline__ void ln_row(const float* __restrict__ src,
                                       float* __restrict__ dst,
                                       const float* __restrict__ g,
                                       const float* __restrict__ be, int lane) {
    float4 vals[4];
    float s = 0.f, ss = 0.f;
#pragma unroll
    for (int t = 0; t < 4; t++) {
        vals[t] = *(const float4*)(src + lane * 4 + t * 128);
        s  += vals[t].x + vals[t].y + vals[t].z + vals[t].w;
        ss += vals[t].x*vals[t].x + vals[t].y*vals[t].y
            + vals[t].z*vals[t].z + vals[t].w*vals[t].w;
    }
#pragma unroll
    for (int o = 16; o; o >>= 1) {
        s  += __shfl_xor_sync(0xffffffffu, s,  o);
        ss += __shfl_xor_sync(0xffffffffu, ss, o);
    }
    float mean = s * (1.f / 512.f);
    float var  = ss * (1.f / 512.f) - mean * mean;
    float rstd = rsqrtf(var + 1e-6f);
#pragma unroll
    for (int t = 0; t < 4; t++) {
        int e = lane * 4 + t * 128;
        float4 o4;
        o4.x = (vals[t].x - mean) * rstd * g[e+0] + be[e+0];
        o4.y = (vals[t].y - mean) * rstd * g[e+1] + be[e+1];
        o4.z = (vals[t].z - mean) * rstd * g[e+2] + be[e+2];
        o4.w = (vals[t].w - mean) * rstd * g[e+3] + be[e+3];
        *(float4*)(dst + e) = o4;
    }
}

__global__ void ln_concat_k(const float* __restrict__ mem, const float* __restrict__ x,
                            const float* __restrict__ gam, const float* __restrict__ bet,
                            float* __restrict__ out, int l) {
    int row  = blockIdx.x * 8 + (threadIdx.x >> 5);
    int lane = threadIdx.x & 31;
    int b = row >> 10, j = row & 1023;
    const float* src = (j < MEM_)
        ? (mem + ((long)(b * MEM_ + j) * LL + l) * EE)
        : (x   +  (long)(b * SS + (j - MEM_)) * EE);
    ln_row(src, out + (long)row * EE, gam + l * EE, bet + l * EE, lane);
}

__global__ void ln_plain_k(const float* __restrict__ in,
                           const float* __restrict__ gam, const float* __restrict__ bet,
                           float* __restrict__ out, int l) {
    int row  = blockIdx.x * 8 + (threadIdx.x >> 5);
    int lane = threadIdx.x & 31;
    ln_row(in + (long)row * EE, out + (long)row * EE, gam + l * EE, bet + l * EE, lane);
}

// ---------------- masked rel-shift softmax (warp per row, in-place) ------------
__global__ __launch_bounds__(256)
void softmax_k(float* __restrict__ sc, const float* __restrict__ P) {
    long row = (long)blockIdx.x * 8 + (threadIdx.x >> 5);
    int lane = threadIdx.x & 31;
    int i = (int)(row & (SS - 1));
    int jmax = MEM_ + i;
    float* srow = sc + row * KK;
    const float* prow = P + row * KK + (SS - 1 - i);
    float v[32];
    float mx = -1e30f;
#pragma unroll
    for (int t = 0; t < 32; t++) {
        int j = t * 32 + lane;
        float x = -1e30f;
        if (j <= jmax) x = srow[j] + prow[j];
        v[t] = x;
        mx = fmaxf(mx, x);
    }
#pragma unroll
    for (int o = 16; o; o >>= 1) mx = fmaxf(mx, __shfl_xor_sync(0xffffffffu, mx, o));
    float s = 0.f;
#pragma unroll
    for (int t = 0; t < 32; t++) {
        float e = (v[t] > -1e29f) ? __expf(v[t] - mx) : 0.f;
        v[t] = e; s += e;
    }
#pragma unroll
    for (int o = 16; o; o >>= 1) s += __shfl_xor_sync(0xffffffffu, s, o);
    float inv = 1.f / s;
#pragma unroll
    for (int t = 0; t < 32; t++) srow[t * 32 + lane] = v[t] * inv;
}

// ---------------- host orchestration ------------------------------------------
extern "C" void kernel_launch(void* const* d_in, const int* in_sizes, int n_in,
                              void* d_out, int out_size) {
    (void)in_sizes; (void)n_in; (void)out_size;
    const float* obs    = (const float*)d_in[0];
    const float* mems   = (const float*)d_in[1];
    const float* W_enc  = (const float*)d_in[3];
    const float* b_enc  = (const float*)d_in[4];
    const float* ln1_s  = (const float*)d_in[5];
    const float* ln1_b  = (const float*)d_in[6];
    const float* Wq     = (const float*)d_in[7];
    const float* bq     = (const float*)d_in[8];
    const float* Wk     = (const float*)d_in[9];
    const float* bk     = (const float*)d_in[10];
    const float* Wv     = (const float*)d_in[11];
    const float* bv     = (const float*)d_in[12];
    const float* Wr     = (const float*)d_in[13];
    const float* ub     = (const float*)d_in[14];
    const float* vbias  = (const float*)d_in[15];
    const float* Wo     = (const float*)d_in[16];
    const float* bo     = (const float*)d_in[17];
    const float* ln2_s  = (const float*)d_in[18];
    const float* ln2_b  = (const float*)d_in[19];
    const float* W1     = (const float*)d_in[20];
    const float* b1     = (const float*)d_in[21];
    const float* W2     = (const float*)d_in[22];
    const float* b2     = (const float*)d_in[23];
    float* out = (float*)d_out;

    float *px, *ph, *phn, *pt, *pvk, *pq, *pk, *pv_, *po, *pr, *ppe, *psc, *pP;
    float *pcu, *pcv;
    cudaGetSymbolAddress((void**)&px,  g_x);
    cudaGetSymbolAddress((void**)&ph,  g_h);
    cudaGetSymbolAddress((void**)&phn, g_hn);
    cudaGetSymbolAddress((void**)&pt,  g_t);
    cudaGetSymbolAddress((void**)&pvk, g_vk);
    cudaGetSymbolAddress((void**)&pq,  g_q);
    cudaGetSymbolAddress((void**)&pk,  g_k);
    cudaGetSymbolAddress((void**)&pv_, g_v);
    cudaGetSymbolAddress((void**)&po,  g_o);
    cudaGetSymbolAddress((void**)&pr,  g_r);
    cudaGetSymbolAddress((void**)&ppe, g_pe);
    cudaGetSymbolAddress((void**)&psc, g_sc);
    cudaGetSymbolAddress((void**)&pP,  g_P);
    cudaGetSymbolAddress((void**)&pcu, g_cu);
    cudaGetSymbolAddress((void**)&pcv, g_cv);

    cudaFuncSetAttribute(mma_gemm_cb<0>, cudaFuncAttributeMaxDynamicSharedMemorySize, CB_SMEM_BYTES);
    cudaFuncSetAttribute(mma_gemm_cb<1>, cudaFuncAttributeMaxDynamicSharedMemorySize, CB_SMEM_BYTES);
    cudaFuncSetAttribute(mma_gemm_cb<2>, cudaFuncAttributeMaxDynamicSharedMemorySize, CB_SMEM_BYTES);
    cudaFuncSetAttribute(mma_gemm_cb<3>, cudaFuncAttributeMaxDynamicSharedMemorySize, CB_SMEM_BYTES);
    cudaFuncSetAttribute(mma_gemm_ca<0>, cudaFuncAttributeMaxDynamicSharedMemorySize, CA_SMEM_BYTES);
    cudaFuncSetAttribute(mma_gemm_qk,    cudaFuncAttributeMaxDynamicSharedMemorySize, QK_SMEM_BYTES);

    const long SE = (long)SS * EE, KE = (long)KK * EE, SK = (long)SS * KK;
    const long HSK = (long)HH * SK;

    // encoder: x = obs @ W_enc + b_enc
    mma_gemm_cb<1><<<dim3(4, 32, 1), 256, CB_SMEM_BYTES>>>(
        obs, 0, 0, OBS_, W_enc, 0, 0, EE, px, 0, 0, EE,
        b_enc, nullptr, 1, OBS_);
    pe_kernel<<<(KK * EE) / 256, 256>>>(ppe);

    for (int l = 0; l < LL; l++) {
        ln_concat_k<<<(BB * KK) / 8, 256>>>(mems, px, ln1_s, ln1_b, pvk, l);

        mma_gemm_cb<1><<<dim3(4, 64, 1), 256, CB_SMEM_BYTES>>>(
            pvk, 0, 0, EE, Wk + (long)l * LW, 0, 0, EE, pk, 0, 0, EE,
            bk + l * EE, nullptr, 1, EE);
        mma_gemm_cb<1><<<dim3(4, 64, 1), 256, CB_SMEM_BYTES>>>(
            pvk, 0, 0, EE, Wv + (long)l * LW, 0, 0, EE, pv_, 0, 0, EE,
            bv + l * EE, nullptr, 1, EE);
        mma_gemm_cb<1><<<dim3(4, 4, BB), 256, CB_SMEM_BYTES>>>(
            pvk + (long)MEM_ * EE, KE, 0, EE, Wq + (long)l * LW, 0, 0, EE,
            pq, SE, 0, EE, bq + l * EE, nullptr, 1, EE);
        mma_gemm_cb<0><<<dim3(4, 8, 1), 256, CB_SMEM_BYTES>>>(
            ppe, 0, 0, EE, Wr + (long)l * LW, 0, 0, EE, pr, 0, 0, EE,
            nullptr, nullptr, 1, EE);

        // column-bias vectors: cu[b,h,j] = 0.125*u_h.k_bj ; cv[h,p] = 0.125*vb_h.r_p
        bias_uk<<<dim3(KK / 8, BB), 256>>>(pk, KE, ub + (long)l * EE,
                                           pcu, (long)HH * KK);
        bias_uk<<<dim3(KK / 8, 1), 256>>>(pr, 0, vbias + (long)l * EE,
                                          pcv, 0);

        // AC = 0.125*q@k^T + cu   (B in native layout, no transpose)
        mma_gemm_qk<<<dim3(8, 4, BB * HH), 256, QK_SMEM_BYTES>>>(
            pq, SE, DH_, pk, KE, DH_, psc, HSK, SK,
            pcu, (long)HH * KK, KK, HH);
        // P = 0.125*q@r^T + cv
        mma_gemm_qk<<<dim3(8, 4, BB * HH), 256, QK_SMEM_BYTES>>>(
            pq, SE, DH_, pr, 0, DH_, pP, HSK, SK,
            pcv, 0, KK, HH);

        softmax_k<<<(BB * HH * SS) / 8, 256>>>(psc, pP);

        // o = probs @ v
        mma_gemm_ca<0><<<dim3(1, 4, BB * HH), 256, CA_SMEM_BYTES>>>(
            psc, HSK, SK, KK, pv_, KE, DH_, EE, po, SE, DH_, EE,
            nullptr, nullptr, HH, KK);

        mma_gemm_cb<3><<<dim3(4, 32, 1), 256, CB_SMEM_BYTES>>>(
            po, 0, 0, EE, Wo + (long)l * LW, 0, 0, EE, ph, 0, 0, EE,
            bo + l * EE, px, 1, EE);
        ln_plain_k<<<(BB * SS) / 8, 256>>>(ph, ln2_s, ln2_b, phn, l);
        mma_gemm_cb<2><<<dim3(4, 32, 1), 256, CB_SMEM_BYTES>>>(
            phn, 0, 0, EE, W1 + (long)l * LW, 0, 0, EE, pt, 0, 0, EE,
            b1 + l * EE, nullptr, 1, EE);
        float* xo = (l == LL - 1) ? out : px;
        mma_gemm_cb<3><<<dim3(4, 32, 1), 256, CB_SMEM_BYTES>>>(
            pt, 0, 0, EE, W2 + (long)l * LW, 0, 0, EE, xo, 0, 0, EE,
            b2 + l * EE, ph, 1, EE);
    }
}

// round 12
// speedup vs baseline: 1.1582x; 1.0378x over previous
#include <cuda_runtime.h>
#include <cstdint>

// Shapes (fixed)
#define BB   8
#define SS   512
#define MEM_ 512
#define LL   4
#define EE   512
#define HH   8
#define DH_  64
#define OBS_ 128
#define KK   1024   // MEM + S
#define LW   (EE*EE)

// ---------------- scratch (static device globals) -----------------------------
__device__ float g_x [BB*SS*EE];
__device__ float g_h [BB*SS*EE];
__device__ float g_hn[BB*SS*EE];
__device__ float g_t [BB*SS*EE];
__device__ float g_vk[BB*KK*EE];
__device__ float g_q [BB*SS*EE];
__device__ float g_k [BB*KK*EE];
__device__ float g_v [BB*KK*EE];
__device__ float g_o [BB*SS*EE];
__device__ float g_r [KK*EE];
__device__ float g_pe[KK*EE];
__device__ float g_sc[(long)BB*HH*SS*KK];   // AC scores / probs (in-place)
__device__ float g_P [(long)BB*HH*SS*KK];   // rel-position term (unshifted)
__device__ float g_cu[BB*HH*KK];            // 0.125 * u  @ k^T  per (b,h,j)
__device__ float g_cv[HH*KK];               // 0.125 * vb @ r^T  per (h,p)

// ---------------- helpers ------------------------------------------------------
__device__ __forceinline__ uint32_t f2tf32(float x) {
    uint32_t o;
    asm("cvt.rna.tf32.f32 %0, %1;" : "=r"(o) : "f"(x));
    return o;
}
__device__ __forceinline__ uint32_t smem_u32(const void* p) {
    uint32_t a;
    asm("{ .reg .u64 t; cvta.to.shared.u64 t, %1; cvt.u32.u64 %0, t; }"
        : "=r"(a) : "l"(p));
    return a;
}
__device__ __forceinline__ void cp_async16(uint32_t dst, const void* src) {
    asm volatile("cp.async.cg.shared.global [%0], [%1], 16;"
                 :: "r"(dst), "l"(src) : "memory");
}
__device__ __forceinline__ void cp_commit() {
    asm volatile("cp.async.commit_group;" ::: "memory");
}
__device__ __forceinline__ void cp_wait1() {
    asm volatile("cp.async.wait_group 1;" ::: "memory");
}
__device__ __forceinline__ void mma_tf32(float* d, const uint32_t* a, const uint32_t* b) {
    asm volatile(
        "mma.sync.aligned.m16n8k8.row.col.f32.tf32.tf32.f32 "
        "{%0,%1,%2,%3}, {%4,%5,%6,%7}, {%8,%9}, {%0,%1,%2,%3};"
        : "+f"(d[0]), "+f"(d[1]), "+f"(d[2]), "+f"(d[3])
        : "r"(a[0]), "r"(a[1]), "r"(a[2]), "r"(a[3]), "r"(b[0]), "r"(b[1]));
}
__device__ __forceinline__ float gelu_f(float x) {
    return 0.5f * x * (1.0f + tanhf(0.7978845608028654f * (x + 0.044715f * x * x * x)));
}

#define AS_STRIDE 36
#define BS_STRIDE 72
#define A_BUF (128 * AS_STRIDE)
#define B_BUF (32 * BS_STRIDE)

// ---------------- 128x128 tile cp.async tf32 GEMM (N multiple of 128) ----------
#define BS2_ST 136
#define B2_BUF (32 * BS2_ST)
#define STAGE2_FLOATS (A_BUF + B2_BUF)
#define CB_SMEM_BYTES (2 * STAGE2_FLOATS * 4)

template<int EPI>
__global__ __launch_bounds__(256)
void mma_gemm_cb(const float* __restrict__ A, long a_o, long a_i, int lda,
                 const float* __restrict__ B, long b_o, long b_i, int ldb,
                 float* __restrict__ C, long c_o, long c_i, int ldc,
                 const float* __restrict__ bias, const float* __restrict__ resid,
                 int Hd, int Kd) {
    extern __shared__ float smem[];
    const uint32_t sbase = smem_u32(smem);

    const int tid = threadIdx.x;
    const int z = blockIdx.z;
    const int m0 = blockIdx.y * 128;
    const int n0 = blockIdx.x * 128;

    const long aoff = ((long)(z / Hd)) * a_o + (long)(z % Hd) * a_i;
    const long boff = ((long)(z / Hd)) * b_o + (long)(z % Hd) * b_i;
    const long coff = ((long)(z / Hd)) * c_o + (long)(z % Hd) * c_i;
    const float* Ap = A + aoff + (long)m0 * lda;
    const float* Bp = B + boff + (long)n0;

    const int lane = tid & 31, w = tid >> 5;
    const int g = lane >> 2, t4 = lane & 3;
    const int wm = (w & 3) * 32;
    const int wn = (w >> 2) * 64;

    const int a_row = tid >> 3, a_c4 = (tid & 7) * 4;
    const int b_row = tid >> 5, b_c4 = (tid & 31) * 4;

    auto issue_stage = [&](int c, int s) {
        uint32_t sa = sbase + (uint32_t)(s * STAGE2_FLOATS) * 4u;
        uint32_t sb = sa + (uint32_t)A_BUF * 4u;
#pragma unroll
        for (int i = 0; i < 4; i++) {
            int row = a_row + i * 32;
            cp_async16(sa + (uint32_t)(row * AS_STRIDE + a_c4) * 4u,
                       Ap + (long)row * lda + c * 32 + a_c4);
        }
#pragma unroll
        for (int i = 0; i < 4; i++) {
            int kr = b_row + i * 8;
            cp_async16(sb + (uint32_t)(kr * BS2_ST + b_c4) * 4u,
                       Bp + (long)(c * 32 + kr) * ldb + b_c4);
        }
    };

    const int nch = Kd / 32;
    issue_stage(0, 0);
    cp_commit();

    float acc[2][8][4] = {};

    for (int c = 0; c < nch; c++) {
        if (c + 1 < nch) issue_stage(c + 1, (c + 1) & 1);
        cp_commit();
        cp_wait1();
        __syncthreads();

        const float* cA = smem + (c & 1) * STAGE2_FLOATS;
        const float* cB = cA + A_BUF;
#pragma unroll
        for (int ks = 0; ks < 4; ks++) {
            const int k = ks * 8;
            uint32_t af[2][4], bfr[8][2];
#pragma unroll
            for (int mt = 0; mt < 2; mt++) {
                const float* p = cA + (wm + mt * 16 + g) * AS_STRIDE + k + t4;
                af[mt][0] = f2tf32(p[0]);
                af[mt][1] = f2tf32(p[8 * AS_STRIDE]);
                af[mt][2] = f2tf32(p[4]);
                af[mt][3] = f2tf32(p[8 * AS_STRIDE + 4]);
            }
#pragma unroll
            for (int nt = 0; nt < 8; nt++) {
                const float* p = cB + (k + t4) * BS2_ST + wn + nt * 8 + g;
                bfr[nt][0] = f2tf32(p[0]);
                bfr[nt][1] = f2tf32(p[4 * BS2_ST]);
            }
#pragma unroll
            for (int mt = 0; mt < 2; mt++)
#pragma unroll
                for (int nt = 0; nt < 8; nt++)
                    mma_tf32(acc[mt][nt], af[mt], bfr[nt]);
        }
        __syncthreads();
    }

#pragma unroll
    for (int mt = 0; mt < 2; mt++) {
#pragma unroll
        for (int half = 0; half < 2; half++) {
            const int row = m0 + wm + mt * 16 + g + half * 8;
            float* Cr = C + coff + (long)row * ldc + n0;
            const float* Rr = (EPI == 3) ? (resid + coff + (long)row * ldc + n0) : nullptr;
#pragma unroll
            for (int nt = 0; nt < 8; nt++) {
                const int cn = wn + nt * 8 + t4 * 2;
                float2 o;
                o.x = acc[mt][nt][half * 2 + 0];
                o.y = acc[mt][nt][half * 2 + 1];
                if (EPI >= 1) {
                    float2 b2 = *(const float2*)(bias + n0 + cn);
                    o.x += b2.x; o.y += b2.y;
                }
                if (EPI == 2) { o.x = gelu_f(o.x); o.y = gelu_f(o.y); }
                if (EPI == 3) {
                    float2 r2 = *(const float2*)(Rr + cn);
                    o.x += r2.x; o.y += r2.y;
                }
                *(float2*)(Cr + cn) = o;
            }
        }
    }
}

// ---------------- score GEMM: C = 0.125 * A@B^T + colbias ----------------------
// A [m, dh] rows of q; B = k or r in NATIVE [keys, dh] layout. Tile 128x128.
// MODE 0 (AC): tile dead iff n0 >= MEM + m0 + 128 (mask: j <= MEM+i)
// MODE 1 (P):  tile dead iff n0 + 127 < S-1 - (m0+127)  (read window p >= S-1-i)
#define QK_A_BUF (128 * AS_STRIDE)
#define QK_STAGE (2 * QK_A_BUF)
#define QK_SMEM_BYTES (2 * QK_STAGE * 4)

template<int MODE>
__global__ __launch_bounds__(256)
void mma_gemm_qk(const float* __restrict__ A, long a_o, long a_i,
                 const float* __restrict__ B, long b_o, long b_i,
                 float* __restrict__ C, long c_o, long c_i,
                 const float* __restrict__ cb, long cb_o, long cb_i,
                 int Hd) {
    const int m0 = blockIdx.y * 128;
    const int n0 = blockIdx.x * 128;
    if (MODE == 0) { if (n0 >= MEM_ + m0 + 128) return; }
    else           { if (n0 + 127 < (SS - 1) - (m0 + 127)) return; }

    extern __shared__ float smem[];
    const uint32_t sbase = smem_u32(smem);

    const int tid = threadIdx.x;
    const int z = blockIdx.z;

    const float* Ap = A + ((long)(z / Hd)) * a_o + (long)(z % Hd) * a_i
                        + (long)m0 * EE;
    const float* Bp = B + ((long)(z / Hd)) * b_o + (long)(z % Hd) * b_i
                        + (long)n0 * EE;
    const long coff = ((long)(z / Hd)) * c_o + (long)(z % Hd) * c_i;
    const float* cbp = cb + ((long)(z / Hd)) * cb_o + (long)(z % Hd) * cb_i + n0;

    const int lane = tid & 31, w = tid >> 5;
    const int g = lane >> 2, t4 = lane & 3;
    const int wm = (w & 3) * 32;
    const int wn = (w >> 2) * 64;

    const int a_row = tid >> 3, a_c4 = (tid & 7) * 4;

    auto issue_stage = [&](int c, int s) {
        uint32_t sa = sbase + (uint32_t)(s * QK_STAGE) * 4u;
        uint32_t sb = sa + (uint32_t)QK_A_BUF * 4u;
#pragma unroll
        for (int i = 0; i < 4; i++) {
            int row = a_row + i * 32;
            cp_async16(sa + (uint32_t)(row * AS_STRIDE + a_c4) * 4u,
                       Ap + (long)row * EE + c * 32 + a_c4);
            cp_async16(sb + (uint32_t)(row * AS_STRIDE + a_c4) * 4u,
                       Bp + (long)row * EE + c * 32 + a_c4);
        }
    };

    issue_stage(0, 0);
    cp_commit();

    float acc[2][8][4] = {};

#pragma unroll
    for (int c = 0; c < 2; c++) {                 // Kd = 64 fixed
        if (c == 0) issue_stage(1, 1);
        cp_commit();
        cp_wait1();
        __syncthreads();

        const float* cA = smem + (c & 1) * QK_STAGE;
        const float* cB = cA + QK_A_BUF;
#pragma unroll
        for (int ks = 0; ks < 4; ks++) {
            const int k = ks * 8;
            uint32_t af[2][4], bfr[8][2];
#pragma unroll
            for (int mt = 0; mt < 2; mt++) {
                const float* p = cA + (wm + mt * 16 + g) * AS_STRIDE + k + t4;
                af[mt][0] = f2tf32(p[0]);
                af[mt][1] = f2tf32(p[8 * AS_STRIDE]);
                af[mt][2] = f2tf32(p[4]);
                af[mt][3] = f2tf32(p[8 * AS_STRIDE + 4]);
            }
#pragma unroll
            for (int nt = 0; nt < 8; nt++) {
                const float* p = cB + (wn + nt * 8 + g) * AS_STRIDE + k + t4;
                bfr[nt][0] = f2tf32(p[0]);
                bfr[nt][1] = f2tf32(p[4]);
            }
#pragma unroll
            for (int mt = 0; mt < 2; mt++)
#pragma unroll
                for (int nt = 0; nt < 8; nt++)
                    mma_tf32(acc[mt][nt], af[mt], bfr[nt]);
        }
        __syncthreads();
    }

#pragma unroll
    for (int mt = 0; mt < 2; mt++) {
#pragma unroll
        for (int half = 0; half < 2; half++) {
            const int row = m0 + wm + mt * 16 + g + half * 8;
            float* Cr = C + coff + (long)row * KK + n0;
#pragma unroll
            for (int nt = 0; nt < 8; nt++) {
                const int cn = wn + nt * 8 + t4 * 2;
                float2 b2 = *(const float2*)(cbp + cn);
                float2 o;
                o.x = acc[mt][nt][half * 2 + 0] * 0.125f + b2.x;
                o.y = acc[mt][nt][half * 2 + 1] * 0.125f + b2.y;
                *(float2*)(Cr + cn) = o;
            }
        }
    }
}

// ---------------- column-bias prep: out[b,h,j] = 0.125 * sum_d u[h,d]*k[b,j,h*64+d]
__global__ __launch_bounds__(256)
void bias_uk(const float* __restrict__ kmat, long bstride,
             const float* __restrict__ uvec,
             float* __restrict__ out, long obstride) {
    int b = blockIdx.y;
    int j = blockIdx.x * 8 + (threadIdx.x >> 5);
    int lane = threadIdx.x & 31;
    const float* krow = kmat + (long)b * bstride + (long)j * EE;
    float* orow = out + (long)b * obstride;
#pragma unroll
    for (int h = 0; h < HH; h++) {
        float s = krow[h * 64 + lane]      * uvec[h * 64 + lane]
                + krow[h * 64 + lane + 32] * uvec[h * 64 + lane + 32];
#pragma unroll
        for (int o = 16; o; o >>= 1) s += __shfl_xor_sync(0xffffffffu, s, o);
        if (lane == 0) orow[h * KK + j] = 0.125f * s;
    }
}

// ---------------- 128x64 cp.async GEMM (probs@V; mask-trimmed K loop) ----------
#define PIPE 2
#define STAGE_FLOATS (A_BUF + B_BUF)
#define CA_SMEM_BYTES (PIPE * STAGE_FLOATS * 4)

// TRIM=1: probs columns beyond MEM + m0 + 127 are exact zeros -> skip chunks.
template<int EPI, int TRIM>
__global__ __launch_bounds__(256)
void mma_gemm_ca(const float* __restrict__ A, long a_o, long a_i, int lda,
                 const float* __restrict__ B, long b_o, long b_i, int ldb,
                 float* __restrict__ C, long c_o, long c_i, int ldc,
                 const float* __restrict__ bias, const float* __restrict__ resid,
                 int Hd, int Kd) {
    extern __shared__ float smem[];
    const uint32_t sbase = smem_u32(smem);

    const int tid = threadIdx.x;
    const int z = blockIdx.z;
    const int m0 = blockIdx.y * 128;
    const int n0 = blockIdx.x * 64;

    const long aoff = ((long)(z / Hd)) * a_o + (long)(z % Hd) * a_i;
    const long boff = ((long)(z / Hd)) * b_o + (long)(z % Hd) * b_i;
    const long coff = ((long)(z / Hd)) * c_o + (long)(z % Hd) * c_i;
    const float* Ap = A + aoff + (long)m0 * lda;
    const float* Bp = B + boff + (long)n0;

    const int lane = tid & 31, w = tid >> 5;
    const int g = lane >> 2, t4 = lane & 3;
    const int m_base = (w & 3) * 32;
    const int n_base = (w >> 2) * 32;

    const int a_row = tid >> 3, a_c4 = (tid & 7) * 4;
    const int b_kr = tid >> 4, b_c4 = (tid & 15) * 4;

    auto issue_stage = [&](int c, int s) {
        uint32_t sa = sbase + (uint32_t)(s * STAGE_FLOATS) * 4u;
        uint32_t sb = sa + (uint32_t)A_BUF * 4u;
#pragma unroll
        for (int i = 0; i < 4; i++) {
            int row = a_row + i * 32;
            cp_async16(sa + (uint32_t)(row * AS_STRIDE + a_c4) * 4u,
                       Ap + (long)row * lda + c * 32 + a_c4);
        }
#pragma unroll
        for (int i = 0; i < 2; i++) {
            int kr = b_kr + i * 16;
            cp_async16(sb + (uint32_t)(kr * BS_STRIDE + b_c4) * 4u,
                       Bp + (long)(c * 32 + kr) * ldb + b_c4);
        }
    };

    const int nch = TRIM ? ((MEM_ + m0 + 128) / 32) : (Kd / 32);
    issue_stage(0, 0);
    cp_commit();

    float acc[2][4][4] = {};

    for (int c = 0; c < nch; c++) {
        if (c + 1 < nch) issue_stage(c + 1, (c + 1) & 1);
        cp_commit();
        cp_wait1();
        __syncthreads();

        const float* cA = smem + (c & 1) * STAGE_FLOATS;
        const float* cB = cA + A_BUF;
#pragma unroll
        for (int ks = 0; ks < 4; ks++) {
            const int k = ks * 8;
            uint32_t af[2][4], bfr[4][2];
#pragma unroll
            for (int mt = 0; mt < 2; mt++) {
                const float* p = cA + (m_base + mt * 16 + g) * AS_STRIDE + k + t4;
                af[mt][0] = f2tf32(p[0]);
                af[mt][1] = f2tf32(p[8 * AS_STRIDE]);
                af[mt][2] = f2tf32(p[4]);
                af[mt][3] = f2tf32(p[8 * AS_STRIDE + 4]);
            }
#pragma unroll
            for (int nt = 0; nt < 4; nt++) {
                const float* p = cB + (k + t4) * BS_STRIDE + n_base + nt * 8 + g;
                bfr[nt][0] = f2tf32(p[0]);
                bfr[nt][1] = f2tf32(p[4 * BS_STRIDE]);
            }
#pragma unroll
            for (int mt = 0; mt < 2; mt++)
#pragma unroll
                for (int nt = 0; nt < 4; nt++)
                    mma_tf32(acc[mt][nt], af[mt], bfr[nt]);
        }
        __syncthreads();
    }

#pragma unroll
    for (int mt = 0; mt < 2; mt++) {
#pragma unroll
        for (int half = 0; half < 2; half++) {
            const int row = m0 + m_base + mt * 16 + g + half * 8;
            float* Cr = C + coff + (long)row * ldc + n0;
            const float* Rr = (EPI == 3) ? (resid + coff + (long)row * ldc + n0) : nullptr;
#pragma unroll
            for (int nt = 0; nt < 4; nt++) {
                const int cn = n_base + nt * 8 + t4 * 2;
                float2 o;
                o.x = acc[mt][nt][half * 2 + 0];
                o.y = acc[mt][nt][half * 2 + 1];
                if (EPI >= 1) {
                    float2 b2 = *(const float2*)(bias + n0 + cn);
                    o.x += b2.x; o.y += b2.y;
                }
                if (EPI == 2) { o.x = gelu_f(o.x); o.y = gelu_f(o.y); }
                if (EPI == 3) {
                    float2 r2 = *(const float2*)(Rr + cn);
                    o.x += r2.x; o.y += r2.y;
                }
                *(float2*)(Cr + cn) = o;
            }
        }
    }
}

// ---------------- positional embedding ----------------------------------------
__global__ void pe_kernel(float* __restrict__ pe) {
    int idx = blockIdx.x * 256 + threadIdx.x;
    int m = idx >> 9, c = idx & 511;
    double pos  = (double)(KK - m);
    int    t2   = c & 255;
    double invf = exp(-((double)(2 * t2) / 512.0) * log(10000.0));
    double a    = pos * invf;
    pe[idx] = (float)((c < 256) ? sin(a) : cos(a));
}

// ---------------- layer norm ---------------------------------------------------
__device__ __forceinline__ void ln_row(const float* __restrict__ src,
                                       float* __restrict__ dst,
                                       const float* __restrict__ g,
                                       const float* __restrict__ be, int lane) {
    float4 vals[4];
    float s = 0.f, ss = 0.f;
#pragma unroll
    for (int t = 0; t < 4; t++) {
        vals[t] = *(const float4*)(src + lane * 4 + t * 128);
        s  += vals[t].x + vals[t].y + vals[t].z + vals[t].w;
        ss += vals[t].x*vals[t].x + vals[t].y*vals[t].y
            + vals[t].z*vals[t].z + vals[t].w*vals[t].w;
    }
#pragma unroll
    for (int o = 16; o; o >>= 1) {
        s  += __shfl_xor_sync(0xffffffffu, s,  o);
        ss += __shfl_xor_sync(0xffffffffu, ss, o);
    }
    float mean = s * (1.f / 512.f);
    float var  = ss * (1.f / 512.f) - mean * mean;
    float rstd = rsqrtf(var + 1e-6f);
#pragma unroll
    for (int t = 0; t < 4; t++) {
        int e = lane * 4 + t * 128;
        float4 o4;
        o4.x = (vals[t].x - mean) * rstd * g[e+0] + be[e+0];
        o4.y = (vals[t].y - mean) * rstd * g[e+1] + be[e+1];
        o4.z = (vals[t].z - mean) * rstd * g[e+2] + be[e+2];
        o4.w = (vals[t].w - mean) * rstd * g[e+3] + be[e+3];
        *(float4*)(dst + e) = o4;
    }
}

__global__ void ln_concat_k(const float* __restrict__ mem, const float* __restrict__ x,
                            const float* __restrict__ gam, const float* __restrict__ bet,
                            float* __restrict__ out, int l) {
    int row  = blockIdx.x * 8 + (threadIdx.x >> 5);
    int lane = threadIdx.x & 31;
    int b = row >> 10, j = row & 1023;
    const float* src = (j < MEM_)
        ? (mem + ((long)(b * MEM_ + j) * LL + l) * EE)
        : (x   +  (long)(b * SS + (j - MEM_)) * EE);
    ln_row(src, out + (long)row * EE, gam + l * EE, bet + l * EE, lane);
}

__global__ void ln_plain_k(const float* __restrict__ in,
                           const float* __restrict__ gam, const float* __restrict__ bet,
                           float* __restrict__ out, int l) {
    int row  = blockIdx.x * 8 + (threadIdx.x >> 5);
    int lane = threadIdx.x & 31;
    ln_row(in + (long)row * EE, out + (long)row * EE, gam + l * EE, bet + l * EE, lane);
}

// ---------------- masked rel-shift softmax (warp per row, in-place) ------------
__global__ __launch_bounds__(256)
void softmax_k(float* __restrict__ sc, const float* __restrict__ P) {
    long row = (long)blockIdx.x * 8 + (threadIdx.x >> 5);
    int lane = threadIdx.x & 31;
    int i = (int)(row & (SS - 1));
    int jmax = MEM_ + i;
    float* srow = sc + row * KK;
    const float* prow = P + row * KK + (SS - 1 - i);
    float v[32];
    float mx = -1e30f;
#pragma unroll
    for (int t = 0; t < 32; t++) {
        int j = t * 32 + lane;
        float x = -1e30f;
        if (j <= jmax) x = srow[j] + prow[j];
        v[t] = x;
        mx = fmaxf(mx, x);
    }
#pragma unroll
    for (int o = 16; o; o >>= 1) mx = fmaxf(mx, __shfl_xor_sync(0xffffffffu, mx, o));
    float s = 0.f;
#pragma unroll
    for (int t = 0; t < 32; t++) {
        float e = (v[t] > -1e29f) ? __expf(v[t] - mx) : 0.f;
        v[t] = e; s += e;
    }
#pragma unroll
    for (int o = 16; o; o >>= 1) s += __shfl_xor_sync(0xffffffffu, s, o);
    float inv = 1.f / s;
#pragma unroll
    for (int t = 0; t < 32; t++) srow[t * 32 + lane] = v[t] * inv;
}

// ---------------- host orchestration ------------------------------------------
extern "C" void kernel_launch(void* const* d_in, const int* in_sizes, int n_in,
                              void* d_out, int out_size) {
    (void)in_sizes; (void)n_in; (void)out_size;
    const float* obs    = (const float*)d_in[0];
    const float* mems   = (const float*)d_in[1];
    const float* W_enc  = (const float*)d_in[3];
    const float* b_enc  = (const float*)d_in[4];
    const float* ln1_s  = (const float*)d_in[5];
    const float* ln1_b  = (const float*)d_in[6];
    const float* Wq     = (const float*)d_in[7];
    const float* bq     = (const float*)d_in[8];
    const float* Wk     = (const float*)d_in[9];
    const float* bk     = (const float*)d_in[10];
    const float* Wv     = (const float*)d_in[11];
    const float* bv     = (const float*)d_in[12];
    const float* Wr     = (const float*)d_in[13];
    const float* ub     = (const float*)d_in[14];
    const float* vbias  = (const float*)d_in[15];
    const float* Wo     = (const float*)d_in[16];
    const float* bo     = (const float*)d_in[17];
    const float* ln2_s  = (const float*)d_in[18];
    const float* ln2_b  = (const float*)d_in[19];
    const float* W1     = (const float*)d_in[20];
    const float* b1     = (const float*)d_in[21];
    const float* W2     = (const float*)d_in[22];
    const float* b2     = (const float*)d_in[23];
    float* out = (float*)d_out;

    float *px, *ph, *phn, *pt, *pvk, *pq, *pk, *pv_, *po, *pr, *ppe, *psc, *pP;
    float *pcu, *pcv;
    cudaGetSymbolAddress((void**)&px,  g_x);
    cudaGetSymbolAddress((void**)&ph,  g_h);
    cudaGetSymbolAddress((void**)&phn, g_hn);
    cudaGetSymbolAddress((void**)&pt,  g_t);
    cudaGetSymbolAddress((void**)&pvk, g_vk);
    cudaGetSymbolAddress((void**)&pq,  g_q);
    cudaGetSymbolAddress((void**)&pk,  g_k);
    cudaGetSymbolAddress((void**)&pv_, g_v);
    cudaGetSymbolAddress((void**)&po,  g_o);
    cudaGetSymbolAddress((void**)&pr,  g_r);
    cudaGetSymbolAddress((void**)&ppe, g_pe);
    cudaGetSymbolAddress((void**)&psc, g_sc);
    cudaGetSymbolAddress((void**)&pP,  g_P);
    cudaGetSymbolAddress((void**)&pcu, g_cu);
    cudaGetSymbolAddress((void**)&pcv, g_cv);

    cudaFuncSetAttribute(mma_gemm_cb<0>, cudaFuncAttributeMaxDynamicSharedMemorySize, CB_SMEM_BYTES);
    cudaFuncSetAttribute(mma_gemm_cb<1>, cudaFuncAttributeMaxDynamicSharedMemorySize, CB_SMEM_BYTES);
    cudaFuncSetAttribute(mma_gemm_cb<2>, cudaFuncAttributeMaxDynamicSharedMemorySize, CB_SMEM_BYTES);
    cudaFuncSetAttribute(mma_gemm_cb<3>, cudaFuncAttributeMaxDynamicSharedMemorySize, CB_SMEM_BYTES);
    cudaFuncSetAttribute(mma_gemm_ca<0,1>, cudaFuncAttributeMaxDynamicSharedMemorySize, CA_SMEM_BYTES);
    cudaFuncSetAttribute(mma_gemm_qk<0>, cudaFuncAttributeMaxDynamicSharedMemorySize, QK_SMEM_BYTES);
    cudaFuncSetAttribute(mma_gemm_qk<1>, cudaFuncAttributeMaxDynamicSharedMemorySize, QK_SMEM_BYTES);

    const long SE = (long)SS * EE, KE = (long)KK * EE, SK = (long)SS * KK;
    const long HSK = (long)HH * SK;

    // encoder: x = obs @ W_enc + b_enc
    mma_gemm_cb<1><<<dim3(4, 32, 1), 256, CB_SMEM_BYTES>>>(
        obs, 0, 0, OBS_, W_enc, 0, 0, EE, px, 0, 0, EE,
        b_enc, nullptr, 1, OBS_);
    pe_kernel<<<(KK * EE) / 256, 256>>>(ppe);

    for (int l = 0; l < LL; l++) {
        ln_concat_k<<<(BB * KK) / 8, 256>>>(mems, px, ln1_s, ln1_b, pvk, l);

        mma_gemm_cb<1><<<dim3(4, 64, 1), 256, CB_SMEM_BYTES>>>(
            pvk, 0, 0, EE, Wk + (long)l * LW, 0, 0, EE, pk, 0, 0, EE,
            bk + l * EE, nullptr, 1, EE);
        mma_gemm_cb<1><<<dim3(4, 64, 1), 256, CB_SMEM_BYTES>>>(
            pvk, 0, 0, EE, Wv + (long)l * LW, 0, 0, EE, pv_, 0, 0, EE,
            bv + l * EE, nullptr, 1, EE);
        mma_gemm_cb<1><<<dim3(4, 4, BB), 256, CB_SMEM_BYTES>>>(
            pvk + (long)MEM_ * EE, KE, 0, EE, Wq + (long)l * LW, 0, 0, EE,
            pq, SE, 0, EE, bq + l * EE, nullptr, 1, EE);
        mma_gemm_cb<0><<<dim3(4, 8, 1), 256, CB_SMEM_BYTES>>>(
            ppe, 0, 0, EE, Wr + (long)l * LW, 0, 0, EE, pr, 0, 0, EE,
            nullptr, nullptr, 1, EE);

        // column-bias vectors
        bias_uk<<<dim3(KK / 8, BB), 256>>>(pk, KE, ub + (long)l * EE,
                                           pcu, (long)HH * KK);
        bias_uk<<<dim3(KK / 8, 1), 256>>>(pr, 0, vbias + (long)l * EE,
                                          pcv, 0);

        // AC = 0.125*q@k^T + cu   (mask-dead tiles skipped)
        mma_gemm_qk<0><<<dim3(8, 4, BB * HH), 256, QK_SMEM_BYTES>>>(
            pq, SE, DH_, pk, KE, DH_, psc, HSK, SK,
            pcu, (long)HH * KK, KK, HH);
        // P = 0.125*q@r^T + cv    (unread-window tiles skipped)
        mma_gemm_qk<1><<<dim3(8, 4, BB * HH), 256, QK_SMEM_BYTES>>>(
            pq, SE, DH_, pr, 0, DH_, pP, HSK, SK,
            pcv, 0, KK, HH);

        softmax_k<<<(BB * HH * SS) / 8, 256>>>(psc, pP);

        // o = probs @ v  (K loop trimmed to the causal extent of the row block)
        mma_gemm_ca<0,1><<<dim3(1, 4, BB * HH), 256, CA_SMEM_BYTES>>>(
            psc, HSK, SK, KK, pv_, KE, DH_, EE, po, SE, DH_, EE,
            nullptr, nullptr, HH, KK);

        mma_gemm_cb<3><<<dim3(4, 32, 1), 256, CB_SMEM_BYTES>>>(
            po, 0, 0, EE, Wo + (long)l * LW, 0, 0, EE, ph, 0, 0, EE,
            bo + l * EE, px, 1, EE);
        ln_plain_k<<<(BB * SS) / 8, 256>>>(ph, ln2_s, ln2_b, phn, l);
        mma_gemm_cb<2><<<dim3(4, 32, 1), 256, CB_SMEM_BYTES>>>(
            phn, 0, 0, EE, W1 + (long)l * LW, 0, 0, EE, pt, 0, 0, EE,
            b1 + l * EE, nullptr, 1, EE);
        float* xo = (l == LL - 1) ? out : px;
        mma_gemm_cb<3><<<dim3(4, 32, 1), 256, CB_SMEM_BYTES>>>(
            pt, 0, 0, EE, W2 + (long)l * LW, 0, 0, EE, xo, 0, 0, EE,
            b2 + l * EE, ph, 1, EE);
    }
}

// round 13
// speedup vs baseline: 1.1664x; 1.0070x over previous
#include <cuda_runtime.h>
#include <cstdint>

// Shapes (fixed)
#define BB   8
#define SS   512
#define MEM_ 512
#define LL   4
#define EE   512
#define HH   8
#define DH_  64
#define OBS_ 128
#define KK   1024   // MEM + S
#define LW   (EE*EE)

// ---------------- scratch (static device globals) -----------------------------
__device__ float g_x [BB*SS*EE];
__device__ float g_h [BB*SS*EE];
__device__ float g_hn[BB*SS*EE];
__device__ float g_t [BB*SS*EE];
__device__ float g_vk[BB*KK*EE];
__device__ float g_q [BB*SS*EE];
__device__ float g_k [BB*KK*EE];
__device__ float g_v [BB*KK*EE];
__device__ float g_o [BB*SS*EE];
__device__ float g_r [KK*EE];
__device__ float g_pe[KK*EE];
__device__ float g_sc[(long)BB*HH*SS*KK];   // AC scores / probs (in-place)
__device__ float g_P [(long)BB*HH*SS*KK];   // rel-position term (unshifted)
__device__ float g_cu[BB*HH*KK];            // 0.125 * u  @ k^T  per (b,h,j)
__device__ float g_cv[HH*KK];               // 0.125 * vb @ r^T  per (h,p)

// ---------------- helpers ------------------------------------------------------
__device__ __forceinline__ uint32_t f2tf32(float x) {
    uint32_t o;
    asm("cvt.rna.tf32.f32 %0, %1;" : "=r"(o) : "f"(x));
    return o;
}
__device__ __forceinline__ uint32_t smem_u32(const void* p) {
    uint32_t a;
    asm("{ .reg .u64 t; cvta.to.shared.u64 t, %1; cvt.u32.u64 %0, t; }"
        : "=r"(a) : "l"(p));
    return a;
}
__device__ __forceinline__ void cp_async16(uint32_t dst, const void* src) {
    asm volatile("cp.async.cg.shared.global [%0], [%1], 16;"
                 :: "r"(dst), "l"(src) : "memory");
}
__device__ __forceinline__ void cp_commit() {
    asm volatile("cp.async.commit_group;" ::: "memory");
}
__device__ __forceinline__ void cp_wait1() {
    asm volatile("cp.async.wait_group 1;" ::: "memory");
}
__device__ __forceinline__ void cp_wait2() {
    asm volatile("cp.async.wait_group 2;" ::: "memory");
}
__device__ __forceinline__ void mma_tf32(float* d, const uint32_t* a, const uint32_t* b) {
    asm volatile(
        "mma.sync.aligned.m16n8k8.row.col.f32.tf32.tf32.f32 "
        "{%0,%1,%2,%3}, {%4,%5,%6,%7}, {%8,%9}, {%0,%1,%2,%3};"
        : "+f"(d[0]), "+f"(d[1]), "+f"(d[2]), "+f"(d[3])
        : "r"(a[0]), "r"(a[1]), "r"(a[2]), "r"(a[3]), "r"(b[0]), "r"(b[1]));
}
__device__ __forceinline__ float gelu_f(float x) {
    return 0.5f * x * (1.0f + tanhf(0.7978845608028654f * (x + 0.044715f * x * x * x)));
}

#define AS_STRIDE 36
#define BS_STRIDE 72
#define A_BUF (128 * AS_STRIDE)
#define B_BUF (32 * BS_STRIDE)

// ---------------- 128x128 tile cp.async tf32 GEMM, 3-stage pipeline ------------
#define BS2_ST 136
#define B2_BUF (32 * BS2_ST)
#define STAGE2_FLOATS (A_BUF + B2_BUF)
#define CB_STAGES 3
#define CB_SMEM_BYTES (CB_STAGES * STAGE2_FLOATS * 4)

template<int EPI>
__global__ __launch_bounds__(256)
void mma_gemm_cb(const float* __restrict__ A, long a_o, long a_i, int lda,
                 const float* __restrict__ B, long b_o, long b_i, int ldb,
                 float* __restrict__ C, long c_o, long c_i, int ldc,
                 const float* __restrict__ bias, const float* __restrict__ resid,
                 int Hd, int Kd) {
    extern __shared__ float smem[];
    const uint32_t sbase = smem_u32(smem);

    const int tid = threadIdx.x;
    const int z = blockIdx.z;
    const int m0 = blockIdx.y * 128;
    const int n0 = blockIdx.x * 128;

    const long aoff = ((long)(z / Hd)) * a_o + (long)(z % Hd) * a_i;
    const long boff = ((long)(z / Hd)) * b_o + (long)(z % Hd) * b_i;
    const long coff = ((long)(z / Hd)) * c_o + (long)(z % Hd) * c_i;
    const float* Ap = A + aoff + (long)m0 * lda;
    const float* Bp = B + boff + (long)n0;

    const int lane = tid & 31, w = tid >> 5;
    const int g = lane >> 2, t4 = lane & 3;
    const int wm = (w & 3) * 32;
    const int wn = (w >> 2) * 64;

    const int a_row = tid >> 3, a_c4 = (tid & 7) * 4;
    const int b_row = tid >> 5, b_c4 = (tid & 31) * 4;

    auto issue_stage = [&](int c, int s) {
        uint32_t sa = sbase + (uint32_t)(s * STAGE2_FLOATS) * 4u;
        uint32_t sb = sa + (uint32_t)A_BUF * 4u;
#pragma unroll
        for (int i = 0; i < 4; i++) {
            int row = a_row + i * 32;
            cp_async16(sa + (uint32_t)(row * AS_STRIDE + a_c4) * 4u,
                       Ap + (long)row * lda + c * 32 + a_c4);
        }
#pragma unroll
        for (int i = 0; i < 4; i++) {
            int kr = b_row + i * 8;
            cp_async16(sb + (uint32_t)(kr * BS2_ST + b_c4) * 4u,
                       Bp + (long)(c * 32 + kr) * ldb + b_c4);
        }
    };

    const int nch = Kd / 32;
    issue_stage(0, 0);
    cp_commit();
    if (1 < nch) issue_stage(1, 1);
    cp_commit();

    float acc[2][8][4] = {};

    for (int c = 0; c < nch; c++) {
        if (c + 2 < nch) issue_stage(c + 2, (c + 2) % CB_STAGES);
        cp_commit();
        cp_wait2();              // all but 2 newest groups done -> stage c ready
        __syncthreads();

        const float* cA = smem + (c % CB_STAGES) * STAGE2_FLOATS;
        const float* cB = cA + A_BUF;
#pragma unroll
        for (int ks = 0; ks < 4; ks++) {
            const int k = ks * 8;
            uint32_t af[2][4], bfr[8][2];
#pragma unroll
            for (int mt = 0; mt < 2; mt++) {
                const float* p = cA + (wm + mt * 16 + g) * AS_STRIDE + k + t4;
                af[mt][0] = f2tf32(p[0]);
                af[mt][1] = f2tf32(p[8 * AS_STRIDE]);
                af[mt][2] = f2tf32(p[4]);
                af[mt][3] = f2tf32(p[8 * AS_STRIDE + 4]);
            }
#pragma unroll
            for (int nt = 0; nt < 8; nt++) {
                const float* p = cB + (k + t4) * BS2_ST + wn + nt * 8 + g;
                bfr[nt][0] = f2tf32(p[0]);
                bfr[nt][1] = f2tf32(p[4 * BS2_ST]);
            }
#pragma unroll
            for (int mt = 0; mt < 2; mt++)
#pragma unroll
                for (int nt = 0; nt < 8; nt++)
                    mma_tf32(acc[mt][nt], af[mt], bfr[nt]);
        }
        __syncthreads();         // protect stage c buffer before iter c+1 rewrites it
    }

#pragma unroll
    for (int mt = 0; mt < 2; mt++) {
#pragma unroll
        for (int half = 0; half < 2; half++) {
            const int row = m0 + wm + mt * 16 + g + half * 8;
            float* Cr = C + coff + (long)row * ldc + n0;
            const float* Rr = (EPI == 3) ? (resid + coff + (long)row * ldc + n0) : nullptr;
#pragma unroll
            for (int nt = 0; nt < 8; nt++) {
                const int cn = wn + nt * 8 + t4 * 2;
                float2 o;
                o.x = acc[mt][nt][half * 2 + 0];
                o.y = acc[mt][nt][half * 2 + 1];
                if (EPI >= 1) {
                    float2 b2 = *(const float2*)(bias + n0 + cn);
                    o.x += b2.x; o.y += b2.y;
                }
                if (EPI == 2) { o.x = gelu_f(o.x); o.y = gelu_f(o.y); }
                if (EPI == 3) {
                    float2 r2 = *(const float2*)(Rr + cn);
                    o.x += r2.x; o.y += r2.y;
                }
                *(float2*)(Cr + cn) = o;
            }
        }
    }
}

// ---------------- score GEMM: C = 0.125 * A@B^T + colbias ----------------------
#define QK_A_BUF (128 * AS_STRIDE)
#define QK_STAGE (2 * QK_A_BUF)
#define QK_SMEM_BYTES (2 * QK_STAGE * 4)

template<int MODE>
__global__ __launch_bounds__(256)
void mma_gemm_qk(const float* __restrict__ A, long a_o, long a_i,
                 const float* __restrict__ B, long b_o, long b_i,
                 float* __restrict__ C, long c_o, long c_i,
                 const float* __restrict__ cb, long cb_o, long cb_i,
                 int Hd) {
    const int m0 = blockIdx.y * 128;
    const int n0 = blockIdx.x * 128;
    if (MODE == 0) { if (n0 >= MEM_ + m0 + 128) return; }
    else           { if (n0 + 127 < (SS - 1) - (m0 + 127)) return; }

    extern __shared__ float smem[];
    const uint32_t sbase = smem_u32(smem);

    const int tid = threadIdx.x;
    const int z = blockIdx.z;

    const float* Ap = A + ((long)(z / Hd)) * a_o + (long)(z % Hd) * a_i
                        + (long)m0 * EE;
    const float* Bp = B + ((long)(z / Hd)) * b_o + (long)(z % Hd) * b_i
                        + (long)n0 * EE;
    const long coff = ((long)(z / Hd)) * c_o + (long)(z % Hd) * c_i;
    const float* cbp = cb + ((long)(z / Hd)) * cb_o + (long)(z % Hd) * cb_i + n0;

    const int lane = tid & 31, w = tid >> 5;
    const int g = lane >> 2, t4 = lane & 3;
    const int wm = (w & 3) * 32;
    const int wn = (w >> 2) * 64;

    const int a_row = tid >> 3, a_c4 = (tid & 7) * 4;

    auto issue_stage = [&](int c, int s) {
        uint32_t sa = sbase + (uint32_t)(s * QK_STAGE) * 4u;
        uint32_t sb = sa + (uint32_t)QK_A_BUF * 4u;
#pragma unroll
        for (int i = 0; i < 4; i++) {
            int row = a_row + i * 32;
            cp_async16(sa + (uint32_t)(row * AS_STRIDE + a_c4) * 4u,
                       Ap + (long)row * EE + c * 32 + a_c4);
            cp_async16(sb + (uint32_t)(row * AS_STRIDE + a_c4) * 4u,
                       Bp + (long)row * EE + c * 32 + a_c4);
        }
    };

    issue_stage(0, 0);
    cp_commit();

    float acc[2][8][4] = {};

#pragma unroll
    for (int c = 0; c < 2; c++) {                 // Kd = 64 fixed
        if (c == 0) issue_stage(1, 1);
        cp_commit();
        cp_wait1();
        __syncthreads();

        const float* cA = smem + (c & 1) * QK_STAGE;
        const float* cB = cA + QK_A_BUF;
#pragma unroll
        for (int ks = 0; ks < 4; ks++) {
            const int k = ks * 8;
            uint32_t af[2][4], bfr[8][2];
#pragma unroll
            for (int mt = 0; mt < 2; mt++) {
                const float* p = cA + (wm + mt * 16 + g) * AS_STRIDE + k + t4;
                af[mt][0] = f2tf32(p[0]);
                af[mt][1] = f2tf32(p[8 * AS_STRIDE]);
                af[mt][2] = f2tf32(p[4]);
                af[mt][3] = f2tf32(p[8 * AS_STRIDE + 4]);
            }
#pragma unroll
            for (int nt = 0; nt < 8; nt++) {
                const float* p = cB + (wn + nt * 8 + g) * AS_STRIDE + k + t4;
                bfr[nt][0] = f2tf32(p[0]);
                bfr[nt][1] = f2tf32(p[4]);
            }
#pragma unroll
            for (int mt = 0; mt < 2; mt++)
#pragma unroll
                for (int nt = 0; nt < 8; nt++)
                    mma_tf32(acc[mt][nt], af[mt], bfr[nt]);
        }
        __syncthreads();
    }

#pragma unroll
    for (int mt = 0; mt < 2; mt++) {
#pragma unroll
        for (int half = 0; half < 2; half++) {
            const int row = m0 + wm + mt * 16 + g + half * 8;
            float* Cr = C + coff + (long)row * KK + n0;
#pragma unroll
            for (int nt = 0; nt < 8; nt++) {
                const int cn = wn + nt * 8 + t4 * 2;
                float2 b2 = *(const float2*)(cbp + cn);
                float2 o;
                o.x = acc[mt][nt][half * 2 + 0] * 0.125f + b2.x;
                o.y = acc[mt][nt][half * 2 + 1] * 0.125f + b2.y;
                *(float2*)(Cr + cn) = o;
            }
        }
    }
}

// ---------------- column-bias prep ---------------------------------------------
__global__ __launch_bounds__(256)
void bias_uk(const float* __restrict__ kmat, long bstride,
             const float* __restrict__ uvec,
             float* __restrict__ out, long obstride) {
    int b = blockIdx.y;
    int j = blockIdx.x * 8 + (threadIdx.x >> 5);
    int lane = threadIdx.x & 31;
    const float* krow = kmat + (long)b * bstride + (long)j * EE;
    float* orow = out + (long)b * obstride;
#pragma unroll
    for (int h = 0; h < HH; h++) {
        float s = krow[h * 64 + lane]      * uvec[h * 64 + lane]
                + krow[h * 64 + lane + 32] * uvec[h * 64 + lane + 32];
#pragma unroll
        for (int o = 16; o; o >>= 1) s += __shfl_xor_sync(0xffffffffu, s, o);
        if (lane == 0) orow[h * KK + j] = 0.125f * s;
    }
}

// ---------------- 128x64 cp.async GEMM (probs@V; mask-trimmed K loop) ----------
#define PIPE 2
#define STAGE_FLOATS (A_BUF + B_BUF)
#define CA_SMEM_BYTES (PIPE * STAGE_FLOATS * 4)

template<int EPI, int TRIM>
__global__ __launch_bounds__(256)
void mma_gemm_ca(const float* __restrict__ A, long a_o, long a_i, int lda,
                 const float* __restrict__ B, long b_o, long b_i, int ldb,
                 float* __restrict__ C, long c_o, long c_i, int ldc,
                 const float* __restrict__ bias, const float* __restrict__ resid,
                 int Hd, int Kd) {
    extern __shared__ float smem[];
    const uint32_t sbase = smem_u32(smem);

    const int tid = threadIdx.x;
    const int z = blockIdx.z;
    const int m0 = blockIdx.y * 128;
    const int n0 = blockIdx.x * 64;

    const long aoff = ((long)(z / Hd)) * a_o + (long)(z % Hd) * a_i;
    const long boff = ((long)(z / Hd)) * b_o + (long)(z % Hd) * b_i;
    const long coff = ((long)(z / Hd)) * c_o + (long)(z % Hd) * c_i;
    const float* Ap = A + aoff + (long)m0 * lda;
    const float* Bp = B + boff + (long)n0;

    const int lane = tid & 31, w = tid >> 5;
    const int g = lane >> 2, t4 = lane & 3;
    const int m_base = (w & 3) * 32;
    const int n_base = (w >> 2) * 32;

    const int a_row = tid >> 3, a_c4 = (tid & 7) * 4;
    const int b_kr = tid >> 4, b_c4 = (tid & 15) * 4;

    auto issue_stage = [&](int c, int s) {
        uint32_t sa = sbase + (uint32_t)(s * STAGE_FLOATS) * 4u;
        uint32_t sb = sa + (uint32_t)A_BUF * 4u;
#pragma unroll
        for (int i = 0; i < 4; i++) {
            int row = a_row + i * 32;
            cp_async16(sa + (uint32_t)(row * AS_STRIDE + a_c4) * 4u,
                       Ap + (long)row * lda + c * 32 + a_c4);
        }
#pragma unroll
        for (int i = 0; i < 2; i++) {
            int kr = b_kr + i * 16;
            cp_async16(sb + (uint32_t)(kr * BS_STRIDE + b_c4) * 4u,
                       Bp + (long)(c * 32 + kr) * ldb + b_c4);
        }
    };

    const int nch = TRIM ? ((MEM_ + m0 + 128) / 32) : (Kd / 32);
    issue_stage(0, 0);
    cp_commit();

    float acc[2][4][4] = {};

    for (int c = 0; c < nch; c++) {
        if (c + 1 < nch) issue_stage(c + 1, (c + 1) & 1);
        cp_commit();
        cp_wait1();
        __syncthreads();

        const float* cA = smem + (c & 1) * STAGE_FLOATS;
        const float* cB = cA + A_BUF;
#pragma unroll
        for (int ks = 0; ks < 4; ks++) {
            const int k = ks * 8;
            uint32_t af[2][4], bfr[4][2];
#pragma unroll
            for (int mt = 0; mt < 2; mt++) {
                const float* p = cA + (m_base + mt * 16 + g) * AS_STRIDE + k + t4;
                af[mt][0] = f2tf32(p[0]);
                af[mt][1] = f2tf32(p[8 * AS_STRIDE]);
                af[mt][2] = f2tf32(p[4]);
                af[mt][3] = f2tf32(p[8 * AS_STRIDE + 4]);
            }
#pragma unroll
            for (int nt = 0; nt < 4; nt++) {
                const float* p = cB + (k + t4) * BS_STRIDE + n_base + nt * 8 + g;
                bfr[nt][0] = f2tf32(p[0]);
                bfr[nt][1] = f2tf32(p[4 * BS_STRIDE]);
            }
#pragma unroll
            for (int mt = 0; mt < 2; mt++)
#pragma unroll
                for (int nt = 0; nt < 4; nt++)
                    mma_tf32(acc[mt][nt], af[mt], bfr[nt]);
        }
        __syncthreads();
    }

#pragma unroll
    for (int mt = 0; mt < 2; mt++) {
#pragma unroll
        for (int half = 0; half < 2; half++) {
            const int row = m0 + m_base + mt * 16 + g + half * 8;
            float* Cr = C + coff + (long)row * ldc + n0;
            const float* Rr = (EPI == 3) ? (resid + coff + (long)row * ldc + n0) : nullptr;
#pragma unroll
            for (int nt = 0; nt < 4; nt++) {
                const int cn = n_base + nt * 8 + t4 * 2;
                float2 o;
                o.x = acc[mt][nt][half * 2 + 0];
                o.y = acc[mt][nt][half * 2 + 1];
                if (EPI >= 1) {
                    float2 b2 = *(const float2*)(bias + n0 + cn);
                    o.x += b2.x; o.y += b2.y;
                }
                if (EPI == 2) { o.x = gelu_f(o.x); o.y = gelu_f(o.y); }
                if (EPI == 3) {
                    float2 r2 = *(const float2*)(Rr + cn);
                    o.x += r2.x; o.y += r2.y;
                }
                *(float2*)(Cr + cn) = o;
            }
        }
    }
}

// ---------------- positional embedding ----------------------------------------
__global__ void pe_kernel(float* __restrict__ pe) {
    int idx = blockIdx.x * 256 + threadIdx.x;
    int m = idx >> 9, c = idx & 511;
    double pos  = (double)(KK - m);
    int    t2   = c & 255;
    double invf = exp(-((double)(2 * t2) / 512.0) * log(10000.0));
    double a    = pos * invf;
    pe[idx] = (float)((c < 256) ? sin(a) : cos(a));
}

// ---------------- layer norm ---------------------------------------------------
__device__ __forceinline__ void ln_row(const float* __restrict__ src,
                                       float* __restrict__ dst,
                                       const float* __restrict__ g,
                                       const float* __restrict__ be, int lane) {
    float4 vals[4];
    float s = 0.f, ss = 0.f;
#pragma unroll
    for (int t = 0; t < 4; t++) {
        vals[t] = *(const float4*)(src + lane * 4 + t * 128);
        s  += vals[t].x + vals[t].y + vals[t].z + vals[t].w;
        ss += vals[t].x*vals[t].x + vals[t].y*vals[t].y
            + vals[t].z*vals[t].z + vals[t].w*vals[t].w;
    }
#pragma unroll
    for (int o = 16; o; o >>= 1) {
        s  += __shfl_xor_sync(0xffffffffu, s,  o);
        ss += __shfl_xor_sync(0xffffffffu, ss, o);
    }
    float mean = s * (1.f / 512.f);
    float var  = ss * (1.f / 512.f) - mean * mean;
    float rstd = rsqrtf(var + 1e-6f);
#pragma unroll
    for (int t = 0; t < 4; t++) {
        int e = lane * 4 + t * 128;
        float4 o4;
        o4.x = (vals[t].x - mean) * rstd * g[e+0] + be[e+0];
        o4.y = (vals[t].y - mean) * rstd * g[e+1] + be[e+1];
        o4.z = (vals[t].z - mean) * rstd * g[e+2] + be[e+2];
        o4.w = (vals[t].w - mean) * rstd * g[e+3] + be[e+3];
        *(float4*)(dst + e) = o4;
    }
}

__global__ void ln_concat_k(const float* __restrict__ mem, const float* __restrict__ x,
                            const float* __restrict__ gam, const float* __restrict__ bet,
                            float* __restrict__ out, int l) {
    int row  = blockIdx.x * 8 + (threadIdx.x >> 5);
    int lane = threadIdx.x & 31;
    int b = row >> 10, j = row & 1023;
    const float* src = (j < MEM_)
        ? (mem + ((long)(b * MEM_ + j) * LL + l) * EE)
        : (x   +  (long)(b * SS + (j - MEM_)) * EE);
    ln_row(src, out + (long)row * EE, gam + l * EE, bet + l * EE, lane);
}

__global__ void ln_plain_k(const float* __restrict__ in,
                           const float* __restrict__ gam, const float* __restrict__ bet,
                           float* __restrict__ out, int l) {
    int row  = blockIdx.x * 8 + (threadIdx.x >> 5);
    int lane = threadIdx.x & 31;
    ln_row(in + (long)row * EE, out + (long)row * EE, gam + l * EE, bet + l * EE, lane);
}

// ---------------- masked rel-shift softmax (warp per row, write-trimmed) -------
__global__ __launch_bounds__(256)
void softmax_k(float* __restrict__ sc, const float* __restrict__ P) {
    long row = (long)blockIdx.x * 8 + (threadIdx.x >> 5);
    int lane = threadIdx.x & 31;
    int i = (int)(row & (SS - 1));
    int jmax = MEM_ + i;
    // probs@V (TRIM) reads only j < MEM + (i|127) + 128... per-block: nfill chunks
    int nfill = (MEM_ + (i | 127) + 1) >> 5;   // 20,24,28,32
    float* srow = sc + row * KK;
    const float* prow = P + row * KK + (SS - 1 - i);
    float v[32];
    float mx = -1e30f;
#pragma unroll
    for (int t = 0; t < 32; t++) {
        int j = t * 32 + lane;
        float x = -1e30f;
        if (j <= jmax) x = srow[j] + prow[j];
        v[t] = x;
        mx = fmaxf(mx, x);
    }
#pragma unroll
    for (int o = 16; o; o >>= 1) mx = fmaxf(mx, __shfl_xor_sync(0xffffffffu, mx, o));
    float s = 0.f;
#pragma unroll
    for (int t = 0; t < 32; t++) {
        float e = (v[t] > -1e29f) ? __expf(v[t] - mx) : 0.f;
        v[t] = e; s += e;
    }
#pragma unroll
    for (int o = 16; o; o >>= 1) s += __shfl_xor_sync(0xffffffffu, s, o);
    float inv = 1.f / s;
#pragma unroll
    for (int t = 0; t < 32; t++)
        if (t < nfill) srow[t * 32 + lane] = v[t] * inv;
}

// ---------------- host orchestration ------------------------------------------
extern "C" void kernel_launch(void* const* d_in, const int* in_sizes, int n_in,
                              void* d_out, int out_size) {
    (void)in_sizes; (void)n_in; (void)out_size;
    const float* obs    = (const float*)d_in[0];
    const float* mems   = (const float*)d_in[1];
    const float* W_enc  = (const float*)d_in[3];
    const float* b_enc  = (const float*)d_in[4];
    const float* ln1_s  = (const float*)d_in[5];
    const float* ln1_b  = (const float*)d_in[6];
    const float* Wq     = (const float*)d_in[7];
    const float* bq     = (const float*)d_in[8];
    const float* Wk     = (const float*)d_in[9];
    const float* bk     = (const float*)d_in[10];
    const float* Wv     = (const float*)d_in[11];
    const float* bv     = (const float*)d_in[12];
    const float* Wr     = (const float*)d_in[13];
    const float* ub     = (const float*)d_in[14];
    const float* vbias  = (const float*)d_in[15];
    const float* Wo     = (const float*)d_in[16];
    const float* bo     = (const float*)d_in[17];
    const float* ln2_s  = (const float*)d_in[18];
    const float* ln2_b  = (const float*)d_in[19];
    const float* W1     = (const float*)d_in[20];
    const float* b1     = (const float*)d_in[21];
    const float* W2     = (const float*)d_in[22];
    const float* b2     = (const float*)d_in[23];
    float* out = (float*)d_out;

    float *px, *ph, *phn, *pt, *pvk, *pq, *pk, *pv_, *po, *pr, *ppe, *psc, *pP;
    float *pcu, *pcv;
    cudaGetSymbolAddress((void**)&px,  g_x);
    cudaGetSymbolAddress((void**)&ph,  g_h);
    cudaGetSymbolAddress((void**)&phn, g_hn);
    cudaGetSymbolAddress((void**)&pt,  g_t);
    cudaGetSymbolAddress((void**)&pvk, g_vk);
    cudaGetSymbolAddress((void**)&pq,  g_q);
    cudaGetSymbolAddress((void**)&pk,  g_k);
    cudaGetSymbolAddress((void**)&pv_, g_v);
    cudaGetSymbolAddress((void**)&po,  g_o);
    cudaGetSymbolAddress((void**)&pr,  g_r);
    cudaGetSymbolAddress((void**)&ppe, g_pe);
    cudaGetSymbolAddress((void**)&psc, g_sc);
    cudaGetSymbolAddress((void**)&pP,  g_P);
    cudaGetSymbolAddress((void**)&pcu, g_cu);
    cudaGetSymbolAddress((void**)&pcv, g_cv);

    cudaFuncSetAttribute(mma_gemm_cb<0>, cudaFuncAttributeMaxDynamicSharedMemorySize, CB_SMEM_BYTES);
    cudaFuncSetAttribute(mma_gemm_cb<1>, cudaFuncAttributeMaxDynamicSharedMemorySize, CB_SMEM_BYTES);
    cudaFuncSetAttribute(mma_gemm_cb<2>, cudaFuncAttributeMaxDynamicSharedMemorySize, CB_SMEM_BYTES);
    cudaFuncSetAttribute(mma_gemm_cb<3>, cudaFuncAttributeMaxDynamicSharedMemorySize, CB_SMEM_BYTES);
    cudaFuncSetAttribute(mma_gemm_ca<0,1>, cudaFuncAttributeMaxDynamicSharedMemorySize, CA_SMEM_BYTES);
    cudaFuncSetAttribute(mma_gemm_qk<0>, cudaFuncAttributeMaxDynamicSharedMemorySize, QK_SMEM_BYTES);
    cudaFuncSetAttribute(mma_gemm_qk<1>, cudaFuncAttributeMaxDynamicSharedMemorySize, QK_SMEM_BYTES);

    const long SE = (long)SS * EE, KE = (long)KK * EE, SK = (long)SS * KK;
    const long HSK = (long)HH * SK;

    // encoder: x = obs @ W_enc + b_enc
    mma_gemm_cb<1><<<dim3(4, 32, 1), 256, CB_SMEM_BYTES>>>(
        obs, 0, 0, OBS_, W_enc, 0, 0, EE, px, 0, 0, EE,
        b_enc, nullptr, 1, OBS_);
    pe_kernel<<<(KK * EE) / 256, 256>>>(ppe);

    for (int l = 0; l < LL; l++) {
        ln_concat_k<<<(BB * KK) / 8, 256>>>(mems, px, ln1_s, ln1_b, pvk, l);

        mma_gemm_cb<1><<<dim3(4, 64, 1), 256, CB_SMEM_BYTES>>>(
            pvk, 0, 0, EE, Wk + (long)l * LW, 0, 0, EE, pk, 0, 0, EE,
            bk + l * EE, nullptr, 1, EE);
        mma_gemm_cb<1><<<dim3(4, 64, 1), 256, CB_SMEM_BYTES>>>(
            pvk, 0, 0, EE, Wv + (long)l * LW, 0, 0, EE, pv_, 0, 0, EE,
            bv + l * EE, nullptr, 1, EE);
        mma_gemm_cb<1><<<dim3(4, 4, BB), 256, CB_SMEM_BYTES>>>(
            pvk + (long)MEM_ * EE, KE, 0, EE, Wq + (long)l * LW, 0, 0, EE,
            pq, SE, 0, EE, bq + l * EE, nullptr, 1, EE);
        mma_gemm_cb<0><<<dim3(4, 8, 1), 256, CB_SMEM_BYTES>>>(
            ppe, 0, 0, EE, Wr + (long)l * LW, 0, 0, EE, pr, 0, 0, EE,
            nullptr, nullptr, 1, EE);

        // column-bias vectors
        bias_uk<<<dim3(KK / 8, BB), 256>>>(pk, KE, ub + (long)l * EE,
                                           pcu, (long)HH * KK);
        bias_uk<<<dim3(KK / 8, 1), 256>>>(pr, 0, vbias + (long)l * EE,
                                          pcv, 0);

        // AC = 0.125*q@k^T + cu   (mask-dead tiles skipped)
        mma_gemm_qk<0><<<dim3(8, 4, BB * HH), 256, QK_SMEM_BYTES>>>(
            pq, SE, DH_, pk, KE, DH_, psc, HSK, SK,
            pcu, (long)HH * KK, KK, HH);
        // P = 0.125*q@r^T + cv    (unread-window tiles skipped)
        mma_gemm_qk<1><<<dim3(8, 4, BB * HH), 256, QK_SMEM_BYTES>>>(
            pq, SE, DH_, pr, 0, DH_, pP, HSK, SK,
            pcv, 0, KK, HH);

        softmax_k<<<(BB * HH * SS) / 8, 256>>>(psc, pP);

        // o = probs @ v  (K loop trimmed to causal extent)
        mma_gemm_ca<0,1><<<dim3(1, 4, BB * HH), 256, CA_SMEM_BYTES>>>(
            psc, HSK, SK, KK, pv_, KE, DH_, EE, po, SE, DH_, EE,
            nullptr, nullptr, HH, KK);

        mma_gemm_cb<3><<<dim3(4, 32, 1), 256, CB_SMEM_BYTES>>>(
            po, 0, 0, EE, Wo + (long)l * LW, 0, 0, EE, ph, 0, 0, EE,
            bo + l * EE, px, 1, EE);
        ln_plain_k<<<(BB * SS) / 8, 256>>>(ph, ln2_s, ln2_b, phn, l);
        mma_gemm_cb<2><<<dim3(4, 32, 1), 256, CB_SMEM_BYTES>>>(
            phn, 0, 0, EE, W1 + (long)l * LW, 0, 0, EE, pt, 0, 0, EE,
            b1 + l * EE, nullptr, 1, EE);
        float* xo = (l == LL - 1) ? out : px;
        mma_gemm_cb<3><<<dim3(4, 32, 1), 256, CB_SMEM_BYTES>>>(
            pt, 0, 0, EE, W2 + (long)l * LW, 0, 0, EE, xo, 0, 0, EE,
            b2 + l * EE, ph, 1, EE);
    }
}

// round 14
// speedup vs baseline: 1.7404x; 1.4922x over previous
#include <cuda_runtime.h>
#include <cuda_fp16.h>
#include <cstdint>

// Shapes (fixed)
#define BB   8
#define SS   512
#define MEM_ 512
#define LL   4
#define EE   512
#define HH   8
#define DH_  64
#define OBS_ 128
#define KK   1024   // MEM + S
#define LW   (EE*EE)

// ---------------- scratch (static device globals) -----------------------------
__device__ float  g_x [BB*SS*EE];             // residual stream (fp32)
__device__ float  g_h [BB*SS*EE];             // post-attn residual (fp32)
__device__ float  g_cu[BB*HH*KK];
__device__ float  g_cv[HH*KK];

__device__ __half g_obsh[BB*SS*OBS_];
__device__ __half g_vkh[BB*KK*EE];
__device__ __half g_qh [BB*SS*EE];
__device__ __half g_kh [BB*KK*EE];
__device__ __half g_vth[(long)BB*EE*KK];      // v transposed: [b][dh(E)][keys]
__device__ __half g_oh [BB*SS*EE];
__device__ __half g_rh [KK*EE];
__device__ __half g_peh[KK*EE];
__device__ __half g_hnh[BB*SS*EE];
__device__ __half g_th [BB*SS*EE];
__device__ __half g_sch[(long)BB*HH*SS*KK];   // scores -> probs (in-place)
__device__ __half g_Ph [(long)BB*HH*SS*KK];

// transposed half weights: [n][k]
__device__ __half g_wet[512*128];             // W_enc^T
__device__ __half g_wkt[LL*LW];
__device__ __half g_wvt[LL*LW];
__device__ __half g_wqt[LL*LW];
__device__ __half g_wrt[LL*LW];
__device__ __half g_wot[LL*LW];
__device__ __half g_w1t[LL*LW];
__device__ __half g_w2t[LL*LW];

// ---------------- helpers ------------------------------------------------------
__device__ __forceinline__ uint32_t smem_u32(const void* p) {
    uint32_t a;
    asm("{ .reg .u64 t; cvta.to.shared.u64 t, %1; cvt.u32.u64 %0, t; }"
        : "=r"(a) : "l"(p));
    return a;
}
__device__ __forceinline__ void cp_async16(uint32_t dst, const void* src) {
    asm volatile("cp.async.cg.shared.global [%0], [%1], 16;"
                 :: "r"(dst), "l"(src) : "memory");
}
__device__ __forceinline__ void cp_commit() {
    asm volatile("cp.async.commit_group;" ::: "memory");
}
__device__ __forceinline__ void cp_wait0() {
    asm volatile("cp.async.wait_group 0;" ::: "memory");
}
__device__ __forceinline__ void cp_wait1() {
    asm volatile("cp.async.wait_group 1;" ::: "memory");
}
__device__ __forceinline__ void mma_f16(float* d, const uint32_t* a, const uint32_t* b) {
    asm volatile(
        "mma.sync.aligned.m16n8k16.row.col.f32.f16.f16.f32 "
        "{%0,%1,%2,%3}, {%4,%5,%6,%7}, {%8,%9}, {%0,%1,%2,%3};"
        : "+f"(d[0]), "+f"(d[1]), "+f"(d[2]), "+f"(d[3])
        : "r"(a[0]), "r"(a[1]), "r"(a[2]), "r"(a[3]), "r"(b[0]), "r"(b[1]));
}
__device__ __forceinline__ float gelu_f(float x) {
    return 0.5f * x * (1.0f + tanhf(0.7978845608028654f * (x + 0.044715f * x * x * x)));
}

#define KC      64      // contraction halves per stage
#define HROW_B  144     // smem bytes per tile row (72 halves, conflict-free)

// ---------------- generic fp16 GEMM ---------------------------------------------
// C[z] = A[z] @ B[z]^T ; A [m][kd] half row-major, B [n][kd] half row-major.
// NTILE in {64,128}. OUTH: half output. VTR: transposed half output (V proj).
// TRIM: causal K-loop trim (probs@V). EPI: 0 none|1 bias|2 bias+gelu|3 bias+resid
template<int NTILE, int EPI, int OUTH, int VTR, int TRIM>
__global__ __launch_bounds__(256)
void hgemm(const __half* __restrict__ A, long a_o, long a_i, int lda,
           const __half* __restrict__ B, long b_o, long b_i, int ldb,
           void* __restrict__ Cv, long c_o, long c_i, int ldc,
           const float* __restrict__ bias, const float* __restrict__ resid,
           int Hd, int Kd) {
    extern __shared__ __align__(16) char smemc[];
    const uint32_t sbase = smem_u32(smemc);
    constexpr int ABUF_B  = 128 * HROW_B;
    constexpr int BBUF_B  = NTILE * HROW_B;
    constexpr int STAGE_B = ABUF_B + BBUF_B;
    constexpr int NT      = NTILE / 16;          // nt count per warp (8 or 4)

    const int tid = threadIdx.x;
    const int z = blockIdx.z;
    const int m0 = blockIdx.y * 128;
    const int n0 = blockIdx.x * NTILE;

    const long aoff = ((long)(z / Hd)) * a_o + (long)(z % Hd) * a_i;
    const long boff = ((long)(z / Hd)) * b_o + (long)(z % Hd) * b_i;
    const long coff = ((long)(z / Hd)) * c_o + (long)(z % Hd) * c_i;
    const __half* Ap = A + aoff + (long)m0 * lda;
    const __half* Bp = B + boff + (long)n0 * ldb;

    const int lane = tid & 31, w = tid >> 5;
    const int g = lane >> 2, t4 = lane & 3;
    const int wm = (w & 3) * 32;
    const int wn = (w >> 2) * (NTILE / 2);

    auto issue_stage = [&](int c, int s) {
        uint32_t sa = sbase + (uint32_t)(s * STAGE_B);
        uint32_t sb = sa + (uint32_t)ABUF_B;
#pragma unroll
        for (int i = 0; i < 4; i++) {
            int idx = tid + i * 256;
            int row = idx >> 3, seg = idx & 7;
            cp_async16(sa + (uint32_t)(row * HROW_B + seg * 16),
                       Ap + (long)row * lda + c * KC + seg * 8);
        }
#pragma unroll
        for (int i = 0; i < NTILE / 32; i++) {
            int idx = tid + i * 256;
            int row = idx >> 3, seg = idx & 7;
            cp_async16(sb + (uint32_t)(row * HROW_B + seg * 16),
                       Bp + (long)row * ldb + c * KC + seg * 8);
        }
    };

    const int nch = TRIM ? ((MEM_ + m0 + 128) / KC) : (Kd / KC);
    issue_stage(0, 0);
    cp_commit();

    float acc[2][NT][4] = {};

    for (int c = 0; c < nch; c++) {
        if (c + 1 < nch) issue_stage(c + 1, (c + 1) & 1);
        cp_commit();
        cp_wait1();
        __syncthreads();

        const char* cA = smemc + (c & 1) * STAGE_B;
        const char* cB = cA + ABUF_B;
#pragma unroll
        for (int ks = 0; ks < 4; ks++) {
            const int k0b = ks * 32;                 // 16 halves per step
            uint32_t af[2][4], bf[NT][2];
#pragma unroll
            for (int mt = 0; mt < 2; mt++) {
                const char* p = cA + (wm + mt * 16 + g) * HROW_B + t4 * 4 + k0b;
                af[mt][0] = *(const uint32_t*)(p);
                af[mt][1] = *(const uint32_t*)(p + 8 * HROW_B);
                af[mt][2] = *(const uint32_t*)(p + 16);
                af[mt][3] = *(const uint32_t*)(p + 8 * HROW_B + 16);
            }
#pragma unroll
            for (int nt = 0; nt < NT; nt++) {
                const char* p = cB + (wn + nt * 8 + g) * HROW_B + t4 * 4 + k0b;
                bf[nt][0] = *(const uint32_t*)(p);
                bf[nt][1] = *(const uint32_t*)(p + 16);
            }
#pragma unroll
            for (int mt = 0; mt < 2; mt++)
#pragma unroll
                for (int nt = 0; nt < NT; nt++)
                    mma_f16(acc[mt][nt], af[mt], bf[nt]);
        }
        __syncthreads();
    }

    // ---- epilogue ----
#pragma unroll
    for (int mt = 0; mt < 2; mt++) {
#pragma unroll
        for (int hf = 0; hf < 2; hf++) {
            const int row = m0 + wm + mt * 16 + g + hf * 8;
#pragma unroll
            for (int nt = 0; nt < NT; nt++) {
                const int cn = wn + nt * 8 + t4 * 2;
                float ox = acc[mt][nt][hf * 2 + 0];
                float oy = acc[mt][nt][hf * 2 + 1];
                if (EPI >= 1) {
                    float2 b2 = *(const float2*)(bias + n0 + cn);
                    ox += b2.x; oy += b2.y;
                }
                if (EPI == 2) { ox = gelu_f(ox); oy = gelu_f(oy); }
                if (EPI == 3) {
                    float2 r2 = *(const float2*)(resid + coff + (long)row * ldc + n0 + cn);
                    ox += r2.x; oy += r2.y;
                }
                if (VTR) {
                    // transposed half store: out[(b*E + n0+cn)][key]
                    __half* Ct = (__half*)Cv;
                    int b = row >> 10, key = row & (KK - 1);
                    long i0 = ((long)(b * EE + n0 + cn)) * KK + key;
                    Ct[i0]      = __float2half_rn(ox);
                    Ct[i0 + KK] = __float2half_rn(oy);
                } else if (OUTH) {
                    __half* Ch = (__half*)Cv + coff + (long)row * ldc + n0;
                    *(__half2*)(Ch + cn) = __floats2half2_rn(ox, oy);
                } else {
                    float* Cf = (float*)Cv + coff + (long)row * ldc + n0;
                    *(float2*)(Cf + cn) = make_float2(ox, oy);
                }
            }
        }
    }
}

// ---------------- score GEMM fp16: C = 0.125*A@B^T + colbias (half out) --------
// Kd = 64 (single stage). MODE 0: AC mask skip; MODE 1: P window skip.
#define QK_STAGE_B (2 * 128 * HROW_B)

template<int MODE>
__global__ __launch_bounds__(256)
void hgemm_qk(const __half* __restrict__ A, long a_o, long a_i,
              const __half* __restrict__ B, long b_o, long b_i,
              __half* __restrict__ C, long c_o, long c_i,
              const float* __restrict__ cb, long cb_o, long cb_i,
              int Hd) {
    const int m0 = blockIdx.y * 128;
    const int n0 = blockIdx.x * 128;
    if (MODE == 0) { if (n0 >= MEM_ + m0 + 128) return; }
    else           { if (n0 + 127 < (SS - 1) - (m0 + 127)) return; }

    extern __shared__ __align__(16) char smemc[];
    const uint32_t sbase = smem_u32(smemc);
    constexpr int ABUF_B = 128 * HROW_B;

    const int tid = threadIdx.x;
    const int z = blockIdx.z;

    const __half* Ap = A + ((long)(z / Hd)) * a_o + (long)(z % Hd) * a_i
                         + (long)m0 * EE;
    const __half* Bp = B + ((long)(z / Hd)) * b_o + (long)(z % Hd) * b_i
                         + (long)n0 * EE;
    const long coff = ((long)(z / Hd)) * c_o + (long)(z % Hd) * c_i;
    const float* cbp = cb + ((long)(z / Hd)) * cb_o + (long)(z % Hd) * cb_i + n0;

    const int lane = tid & 31, w = tid >> 5;
    const int g = lane >> 2, t4 = lane & 3;
    const int wm = (w & 3) * 32;
    const int wn = (w >> 2) * 64;

#pragma unroll
    for (int i = 0; i < 4; i++) {
        int idx = tid + i * 256;
        int row = idx >> 3, seg = idx & 7;
        cp_async16(sbase + (uint32_t)(row * HROW_B + seg * 16),
                   Ap + (long)row * EE + seg * 8);
        cp_async16(sbase + (uint32_t)(ABUF_B + row * HROW_B + seg * 16),
                   Bp + (long)row * EE + seg * 8);
    }
    cp_commit();
    cp_wait0();
    __syncthreads();

    float acc[2][8][4] = {};
    const char* cA = smemc;
    const char* cB = smemc + ABUF_B;
#pragma unroll
    for (int ks = 0; ks < 4; ks++) {
        const int k0b = ks * 32;
        uint32_t af[2][4], bf[8][2];
#pragma unroll
        for (int mt = 0; mt < 2; mt++) {
            const char* p = cA + (wm + mt * 16 + g) * HROW_B + t4 * 4 + k0b;
            af[mt][0] = *(const uint32_t*)(p);
            af[mt][1] = *(const uint32_t*)(p + 8 * HROW_B);
            af[mt][2] = *(const uint32_t*)(p + 16);
            af[mt][3] = *(const uint32_t*)(p + 8 * HROW_B + 16);
        }
#pragma unroll
        for (int nt = 0; nt < 8; nt++) {
            const char* p = cB + (wn + nt * 8 + g) * HROW_B + t4 * 4 + k0b;
            bf[nt][0] = *(const uint32_t*)(p);
            bf[nt][1] = *(const uint32_t*)(p + 16);
        }
#pragma unroll
        for (int mt = 0; mt < 2; mt++)
#pragma unroll
            for (int nt = 0; nt < 8; nt++)
                mma_f16(acc[mt][nt], af[mt], bf[nt]);
    }

#pragma unroll
    for (int mt = 0; mt < 2; mt++) {
#pragma unroll
        for (int hf = 0; hf < 2; hf++) {
            const int row = m0 + wm + mt * 16 + g + hf * 8;
            __half* Cr = C + coff + (long)row * KK + n0;
#pragma unroll
            for (int nt = 0; nt < 8; nt++) {
                const int cn = wn + nt * 8 + t4 * 2;
                float2 b2 = *(const float2*)(cbp + cn);
                *(__half2*)(Cr + cn) = __floats2half2_rn(
                    acc[mt][nt][hf * 2 + 0] * 0.125f + b2.x,
                    acc[mt][nt][hf * 2 + 1] * 0.125f + b2.y);
            }
        }
    }
}

// ---------------- weight transpose + convert: Wt[n][k] = half(W[k][n]) ---------
__global__ __launch_bounds__(256)
void w_tr(const float* __restrict__ W, __half* __restrict__ Wt,
          int K, int N, long wstride, long tstride) {
    __shared__ float t[32][33];
    const float* Wl = W + (long)blockIdx.z * wstride;
    __half* Wtl = Wt + (long)blockIdx.z * tstride;
    int k0 = blockIdx.y * 32, n0 = blockIdx.x * 32;
    int tid = threadIdx.x;
#pragma unroll
    for (int i = 0; i < 4; i++) {
        int idx = tid + i * 256;
        int r = idx >> 5, c = idx & 31;
        t[r][c] = Wl[(long)(k0 + r) * N + n0 + c];
    }
    __syncthreads();
#pragma unroll
    for (int i = 0; i < 4; i++) {
        int idx = tid + i * 256;
        int r = idx >> 5, c = idx & 31;
        Wtl[(long)(n0 + r) * K + k0 + c] = __float2half_rn(t[c][r]);
    }
}

// ---------------- fp32 -> half elementwise -------------------------------------
__global__ void conv_half(const float* __restrict__ in, __half* __restrict__ outp) {
    int idx = blockIdx.x * 256 + threadIdx.x;
    outp[idx] = __float2half_rn(in[idx]);
}

// ---------------- positional embedding (half) ----------------------------------
__global__ void pe_kernel(__half* __restrict__ pe) {
    int idx = blockIdx.x * 256 + threadIdx.x;
    int m = idx >> 9, c = idx & 511;
    double pos  = (double)(KK - m);
    int    t2   = c & 255;
    double invf = exp(-((double)(2 * t2) / 512.0) * log(10000.0));
    double a    = pos * invf;
    pe[idx] = __float2half_rn((float)((c < 256) ? sin(a) : cos(a)));
}

// ---------------- layer norm (fp32 in, half out) -------------------------------
__device__ __forceinline__ void ln_row_h(const float* __restrict__ src,
                                         __half* __restrict__ dst,
                                         const float* __restrict__ g,
                                         const float* __restrict__ be, int lane) {
    float4 vals[4];
    float s = 0.f, ss = 0.f;
#pragma unroll
    for (int t = 0; t < 4; t++) {
        vals[t] = *(const float4*)(src + lane * 4 + t * 128);
        s  += vals[t].x + vals[t].y + vals[t].z + vals[t].w;
        ss += vals[t].x*vals[t].x + vals[t].y*vals[t].y
            + vals[t].z*vals[t].z + vals[t].w*vals[t].w;
    }
#pragma unroll
    for (int o = 16; o; o >>= 1) {
        s  += __shfl_xor_sync(0xffffffffu, s,  o);
        ss += __shfl_xor_sync(0xffffffffu, ss, o);
    }
    float mean = s * (1.f / 512.f);
    float var  = ss * (1.f / 512.f) - mean * mean;
    float rstd = rsqrtf(var + 1e-6f);
#pragma unroll
    for (int t = 0; t < 4; t++) {
        int e = lane * 4 + t * 128;
        float ox = (vals[t].x - mean) * rstd * g[e+0] + be[e+0];
        float oy = (vals[t].y - mean) * rstd * g[e+1] + be[e+1];
        float oz = (vals[t].z - mean) * rstd * g[e+2] + be[e+2];
        float ow = (vals[t].w - mean) * rstd * g[e+3] + be[e+3];
        *(__half2*)(dst + e)     = __floats2half2_rn(ox, oy);
        *(__half2*)(dst + e + 2) = __floats2half2_rn(oz, ow);
    }
}

__global__ void ln_concat_k(const float* __restrict__ mem, const float* __restrict__ x,
                            const float* __restrict__ gam, const float* __restrict__ bet,
                            __half* __restrict__ out, int l) {
    int row  = blockIdx.x * 8 + (threadIdx.x >> 5);
    int lane = threadIdx.x & 31;
    int b = row >> 10, j = row & 1023;
    const float* src = (j < MEM_)
        ? (mem + ((long)(b * MEM_ + j) * LL + l) * EE)
        : (x   +  (long)(b * SS + (j - MEM_)) * EE);
    ln_row_h(src, out + (long)row * EE, gam + l * EE, bet + l * EE, lane);
}

__global__ void ln_plain_k(const float* __restrict__ in,
                           const float* __restrict__ gam, const float* __restrict__ bet,
                           __half* __restrict__ out, int l) {
    int row  = blockIdx.x * 8 + (threadIdx.x >> 5);
    int lane = threadIdx.x & 31;
    ln_row_h(in + (long)row * EE, out + (long)row * EE, gam + l * EE, bet + l * EE, lane);
}

// ---------------- column-bias prep (half k) ------------------------------------
__global__ __launch_bounds__(256)
void bias_uk(const __half* __restrict__ kmat, long bstride,
             const float* __restrict__ uvec,
             float* __restrict__ out, long obstride) {
    int b = blockIdx.y;
    int j = blockIdx.x * 8 + (threadIdx.x >> 5);
    int lane = threadIdx.x & 31;
    const __half* krow = kmat + (long)b * bstride + (long)j * EE;
    float* orow = out + (long)b * obstride;
#pragma unroll
    for (int h = 0; h < HH; h++) {
        float s = __half2float(krow[h * 64 + lane])      * uvec[h * 64 + lane]
                + __half2float(krow[h * 64 + lane + 32]) * uvec[h * 64 + lane + 32];
#pragma unroll
        for (int o = 16; o; o >>= 1) s += __shfl_xor_sync(0xffffffffu, s, o);
        if (lane == 0) orow[h * KK + j] = 0.125f * s;
    }
}

// ---------------- masked rel-shift softmax (half in/out, write-trimmed) --------
__global__ __launch_bounds__(256)
void softmax_k(__half* __restrict__ sc, const __half* __restrict__ P) {
    long row = (long)blockIdx.x * 8 + (threadIdx.x >> 5);
    int lane = threadIdx.x & 31;
    int i = (int)(row & (SS - 1));
    int jmax = MEM_ + i;
    int nfill = (MEM_ + (i | 127) + 1) >> 5;   // 20,24,28,32 (t-steps of 32)
    __half* srow = sc + row * KK;
    const __half* prow = P + row * KK + (SS - 1 - i);
    float v[32];
    float mx = -1e30f;
#pragma unroll
    for (int t = 0; t < 32; t++) {
        int j = t * 32 + lane;
        float x = -1e30f;
        if (j <= jmax) x = __half2float(srow[j]) + __half2float(prow[j]);
        v[t] = x;
        mx = fmaxf(mx, x);
    }
#pragma unroll
    for (int o = 16; o; o >>= 1) mx = fmaxf(mx, __shfl_xor_sync(0xffffffffu, mx, o));
    float s = 0.f;
#pragma unroll
    for (int t = 0; t < 32; t++) {
        float e = (v[t] > -1e29f) ? __expf(v[t] - mx) : 0.f;
        v[t] = e; s += e;
    }
#pragma unroll
    for (int o = 16; o; o >>= 1) s += __shfl_xor_sync(0xffffffffu, s, o);
    float inv = 1.f / s;
#pragma unroll
    for (int t = 0; t < 32; t++)
        if (t < nfill) srow[t * 32 + lane] = __float2half_rn(v[t] * inv);
}

// ---------------- host orchestration ------------------------------------------
#define SM128 (2 * (128 + 128) * HROW_B)      // 73728
#define SM64  (2 * (128 + 64)  * HROW_B)      // 55296
#define SMQK  (2 * 128 * HROW_B)              // 36864

extern "C" void kernel_launch(void* const* d_in, const int* in_sizes, int n_in,
                              void* d_out, int out_size) {
    (void)in_sizes; (void)n_in; (void)out_size;
    const float* obs    = (const float*)d_in[0];
    const float* mems   = (const float*)d_in[1];
    const float* W_enc  = (const float*)d_in[3];
    const float* b_enc  = (const float*)d_in[4];
    const float* ln1_s  = (const float*)d_in[5];
    const float* ln1_b  = (const float*)d_in[6];
    const float* Wq     = (const float*)d_in[7];
    const float* bq     = (const float*)d_in[8];
    const float* Wk     = (const float*)d_in[9];
    const float* bk     = (const float*)d_in[10];
    const float* Wv     = (const float*)d_in[11];
    const float* bv     = (const float*)d_in[12];
    const float* Wr     = (const float*)d_in[13];
    const float* ub     = (const float*)d_in[14];
    const float* vbias  = (const float*)d_in[15];
    const float* Wo     = (const float*)d_in[16];
    const float* bo     = (const float*)d_in[17];
    const float* ln2_s  = (const float*)d_in[18];
    const float* ln2_b  = (const float*)d_in[19];
    const float* W1     = (const float*)d_in[20];
    const float* b1     = (const float*)d_in[21];
    const float* W2     = (const float*)d_in[22];
    const float* b2     = (const float*)d_in[23];
    float* out = (float*)d_out;

    float *px, *ph, *pcu, *pcv;
    __half *pobsh, *pvkh, *pqh, *pkh, *pvth, *poh, *prh, *ppeh, *phnh, *pth, *psch, *pPh;
    __half *pwet, *pwkt, *pwvt, *pwqt, *pwrt, *pwot, *pw1t, *pw2t;
    cudaGetSymbolAddress((void**)&px,   g_x);
    cudaGetSymbolAddress((void**)&ph,   g_h);
    cudaGetSymbolAddress((void**)&pcu,  g_cu);
    cudaGetSymbolAddress((void**)&pcv,  g_cv);
    cudaGetSymbolAddress((void**)&pobsh,g_obsh);
    cudaGetSymbolAddress((void**)&pvkh, g_vkh);
    cudaGetSymbolAddress((void**)&pqh,  g_qh);
    cudaGetSymbolAddress((void**)&pkh,  g_kh);
    cudaGetSymbolAddress((void**)&pvth, g_vth);
    cudaGetSymbolAddress((void**)&poh,  g_oh);
    cudaGetSymbolAddress((void**)&prh,  g_rh);
    cudaGetSymbolAddress((void**)&ppeh, g_peh);
    cudaGetSymbolAddress((void**)&phnh, g_hnh);
    cudaGetSymbolAddress((void**)&pth,  g_th);
    cudaGetSymbolAddress((void**)&psch, g_sch);
    cudaGetSymbolAddress((void**)&pPh,  g_Ph);
    cudaGetSymbolAddress((void**)&pwet, g_wet);
    cudaGetSymbolAddress((void**)&pwkt, g_wkt);
    cudaGetSymbolAddress((void**)&pwvt, g_wvt);
    cudaGetSymbolAddress((void**)&pwqt, g_wqt);
    cudaGetSymbolAddress((void**)&pwrt, g_wrt);
    cudaGetSymbolAddress((void**)&pwot, g_wot);
    cudaGetSymbolAddress((void**)&pw1t, g_w1t);
    cudaGetSymbolAddress((void**)&pw2t, g_w2t);

    cudaFuncSetAttribute(hgemm<128,1,0,0,0>, cudaFuncAttributeMaxDynamicSharedMemorySize, SM128);
    cudaFuncSetAttribute(hgemm<128,1,1,0,0>, cudaFuncAttributeMaxDynamicSharedMemorySize, SM128);
    cudaFuncSetAttribute(hgemm<128,1,1,1,0>, cudaFuncAttributeMaxDynamicSharedMemorySize, SM128);
    cudaFuncSetAttribute(hgemm<128,0,1,0,0>, cudaFuncAttributeMaxDynamicSharedMemorySize, SM128);
    cudaFuncSetAttribute(hgemm<128,3,0,0,0>, cudaFuncAttributeMaxDynamicSharedMemorySize, SM128);
    cudaFuncSetAttribute(hgemm<128,2,1,0,0>, cudaFuncAttributeMaxDynamicSharedMemorySize, SM128);
    cudaFuncSetAttribute(hgemm<64,0,1,0,1>,  cudaFuncAttributeMaxDynamicSharedMemorySize, SM64);
    cudaFuncSetAttribute(hgemm_qk<0>, cudaFuncAttributeMaxDynamicSharedMemorySize, SMQK);
    cudaFuncSetAttribute(hgemm_qk<1>, cudaFuncAttributeMaxDynamicSharedMemorySize, SMQK);

    const long SE = (long)SS * EE, KE = (long)KK * EE, SK = (long)SS * KK;
    const long HSK = (long)HH * SK;
    const long EK = (long)EE * KK;

    // ---- one-time conversions ----
    conv_half<<<(BB * SS * OBS_) / 256, 256>>>(obs, pobsh);
    w_tr<<<dim3(16, 4, 1),  256>>>(W_enc, pwet, OBS_, EE, 0, 0);
    w_tr<<<dim3(16, 16, LL), 256>>>(Wk, pwkt, EE, EE, (long)LW, (long)LW);
    w_tr<<<dim3(16, 16, LL), 256>>>(Wv, pwvt, EE, EE, (long)LW, (long)LW);
    w_tr<<<dim3(16, 16, LL), 256>>>(Wq, pwqt, EE, EE, (long)LW, (long)LW);
    w_tr<<<dim3(16, 16, LL), 256>>>(Wr, pwrt, EE, EE, (long)LW, (long)LW);
    w_tr<<<dim3(16, 16, LL), 256>>>(Wo, pwot, EE, EE, (long)LW, (long)LW);
    w_tr<<<dim3(16, 16, LL), 256>>>(W1, pw1t, EE, EE, (long)LW, (long)LW);
    w_tr<<<dim3(16, 16, LL), 256>>>(W2, pw2t, EE, EE, (long)LW, (long)LW);
    pe_kernel<<<(KK * EE) / 256, 256>>>(ppeh);

    // encoder: x = obs @ W_enc + b_enc  (fp32 out)
    hgemm<128,1,0,0,0><<<dim3(4, 32, 1), 256, SM128>>>(
        pobsh, 0, 0, OBS_, pwet, 0, 0, OBS_, px, 0, 0, EE,
        b_enc, nullptr, 1, OBS_);

    for (int l = 0; l < LL; l++) {
        ln_concat_k<<<(BB * KK) / 8, 256>>>(mems, px, ln1_s, ln1_b, pvkh, l);

        // K projection (half out, normal layout)
        hgemm<128,1,1,0,0><<<dim3(4, 64, 1), 256, SM128>>>(
            pvkh, 0, 0, EE, pwkt + (long)l * LW, 0, 0, EE, pkh, 0, 0, EE,
            bk + l * EE, nullptr, 1, EE);
        // V projection (half out, TRANSPOSED [b][E][keys])
        hgemm<128,1,1,1,0><<<dim3(4, 64, 1), 256, SM128>>>(
            pvkh, 0, 0, EE, pwvt + (long)l * LW, 0, 0, EE, pvth, 0, 0, 0,
            bv + l * EE, nullptr, 1, EE);
        // Q projection (x-rows of vk)
        hgemm<128,1,1,0,0><<<dim3(4, 4, BB), 256, SM128>>>(
            pvkh + (long)MEM_ * EE, KE, 0, EE, pwqt + (long)l * LW, 0, 0, EE,
            pqh, SE, 0, EE, bq + l * EE, nullptr, 1, EE);
        // R projection
        hgemm<128,0,1,0,0><<<dim3(4, 8, 1), 256, SM128>>>(
            ppeh, 0, 0, EE, pwrt + (long)l * LW, 0, 0, EE, prh, 0, 0, EE,
            nullptr, nullptr, 1, EE);

        // column-bias vectors
        bias_uk<<<dim3(KK / 8, BB), 256>>>(pkh, KE, ub + (long)l * EE,
                                           pcu, (long)HH * KK);
        bias_uk<<<dim3(KK / 8, 1), 256>>>(prh, 0, vbias + (long)l * EE,
                                          pcv, 0);

        // AC = 0.125*q@k^T + cu   (mask-dead tiles skipped)
        hgemm_qk<0><<<dim3(8, 4, BB * HH), 256, SMQK>>>(
            pqh, SE, DH_, pkh, KE, DH_, psch, HSK, SK,
            pcu, (long)HH * KK, KK, HH);
        // P = 0.125*q@r^T + cv    (unread-window tiles skipped)
        hgemm_qk<1><<<dim3(8, 4, BB * HH), 256, SMQK>>>(
            pqh, SE, DH_, prh, 0, DH_, pPh, HSK, SK,
            pcv, 0, KK, HH);

        softmax_k<<<(BB * HH * SS) / 8, 256>>>(psch, pPh);

        // o = probs @ v  (B = vT native [dh][keys], causal K trim)
        hgemm<64,0,1,0,1><<<dim3(1, 4, BB * HH), 256, SM64>>>(
            psch, HSK, SK, KK, pvth, EK, (long)64 * KK, KK,
            poh, SE, 64, EE, nullptr, nullptr, HH, KK);

        // Wo + residual (fp32 out)
        hgemm<128,3,0,0,0><<<dim3(4, 32, 1), 256, SM128>>>(
            poh, 0, 0, EE, pwot + (long)l * LW, 0, 0, EE, ph, 0, 0, EE,
            bo + l * EE, px, 1, EE);
        ln_plain_k<<<(BB * SS) / 8, 256>>>(ph, ln2_s, ln2_b, phnh, l);
        // FF1 (gelu, half out)
        hgemm<128,2,1,0,0><<<dim3(4, 32, 1), 256, SM128>>>(
            phnh, 0, 0, EE, pw1t + (long)l * LW, 0, 0, EE, pth, 0, 0, EE,
            b1 + l * EE, nullptr, 1, EE);
        // FF2 + residual (fp32 out)
        float* xo = (l == LL - 1) ? out : px;
        hgemm<128,3,0,0,0><<<dim3(4, 32, 1), 256, SM128>>>(
            pth, 0, 0, EE, pw2t + (long)l * LW, 0, 0, EE, xo, 0, 0, EE,
            b2 + l * EE, ph, 1, EE);
    }
}

// round 15
// speedup vs baseline: 1.8187x; 1.0450x over previous
#include <cuda_runtime.h>
#include <cuda_fp16.h>
#include <cstdint>

// Shapes (fixed)
#define BB   8
#define SS   512
#define MEM_ 512
#define LL   4
#define EE   512
#define HH   8
#define DH_  64
#define OBS_ 128
#define KK   1024   // MEM + S
#define LW   (EE*EE)

// ---------------- scratch (static device globals) -----------------------------
__device__ float  g_x [BB*SS*EE];             // residual stream (fp32)
__device__ float  g_h [BB*SS*EE];             // post-attn residual (fp32)
__device__ float  g_cu[BB*HH*KK];
__device__ float  g_cv[HH*KK];

__device__ __half g_obsh[BB*SS*OBS_];
__device__ __half g_vkh[BB*KK*EE];
__device__ __half g_qh [BB*SS*EE];
__device__ __half g_kh [BB*KK*EE];
__device__ __half g_vth[(long)BB*EE*KK];      // v transposed: [b][dh(E)][keys]
__device__ __half g_oh [BB*SS*EE];
__device__ __half g_rh [KK*EE];
__device__ __half g_peh[KK*EE];
__device__ __half g_hnh[BB*SS*EE];
__device__ __half g_th [BB*SS*EE];
__device__ __half g_sch[(long)BB*HH*SS*KK];   // scores -> probs (in-place)
__device__ __half g_Ph [(long)BB*HH*SS*KK];

// transposed half weights: [n][k]
__device__ __half g_wet[512*128];             // W_enc^T
__device__ __half g_wkt[LL*LW];
__device__ __half g_wvt[LL*LW];
__device__ __half g_wqt[LL*LW];
__device__ __half g_wrt[LL*LW];
__device__ __half g_wot[LL*LW];
__device__ __half g_w1t[LL*LW];
__device__ __half g_w2t[LL*LW];

// ---------------- helpers ------------------------------------------------------
__device__ __forceinline__ uint32_t smem_u32(const void* p) {
    uint32_t a;
    asm("{ .reg .u64 t; cvta.to.shared.u64 t, %1; cvt.u32.u64 %0, t; }"
        : "=r"(a) : "l"(p));
    return a;
}
__device__ __forceinline__ void cp_async16(uint32_t dst, const void* src) {
    asm volatile("cp.async.cg.shared.global [%0], [%1], 16;"
                 :: "r"(dst), "l"(src) : "memory");
}
__device__ __forceinline__ void cp_commit() {
    asm volatile("cp.async.commit_group;" ::: "memory");
}
__device__ __forceinline__ void cp_wait0() {
    asm volatile("cp.async.wait_group 0;" ::: "memory");
}
__device__ __forceinline__ void cp_wait1() {
    asm volatile("cp.async.wait_group 1;" ::: "memory");
}
__device__ __forceinline__ void mma_f16(float* d, const uint32_t* a, const uint32_t* b) {
    asm volatile(
        "mma.sync.aligned.m16n8k16.row.col.f32.f16.f16.f32 "
        "{%0,%1,%2,%3}, {%4,%5,%6,%7}, {%8,%9}, {%0,%1,%2,%3};"
        : "+f"(d[0]), "+f"(d[1]), "+f"(d[2]), "+f"(d[3])
        : "r"(a[0]), "r"(a[1]), "r"(a[2]), "r"(a[3]), "r"(b[0]), "r"(b[1]));
}
#define LDM_X4(d0, d1, d2, d3, addr) \
    asm volatile("ldmatrix.sync.aligned.m8n8.x4.shared.b16 {%0,%1,%2,%3}, [%4];" \
                 : "=r"(d0), "=r"(d1), "=r"(d2), "=r"(d3) : "r"(addr))

__device__ __forceinline__ float gelu_f(float x) {
    return 0.5f * x * (1.0f + tanhf(0.7978845608028654f * (x + 0.044715f * x * x * x)));
}

#define KC      64      // contraction halves per stage
#define HROW_B  144     // smem bytes per tile row (72 halves, conflict-free)

// ---------------- generic fp16 GEMM (ldmatrix fragment loads) -------------------
// C[z] = A[z] @ B[z]^T ; A [m][kd] half row-major, B [n][kd] half row-major.
template<int NTILE, int EPI, int OUTH, int VTR, int TRIM>
__global__ __launch_bounds__(256)
void hgemm(const __half* __restrict__ A, long a_o, long a_i, int lda,
           const __half* __restrict__ B, long b_o, long b_i, int ldb,
           void* __restrict__ Cv, long c_o, long c_i, int ldc,
           const float* __restrict__ bias, const float* __restrict__ resid,
           int Hd, int Kd) {
    extern __shared__ __align__(16) char smemc[];
    const uint32_t sbase = smem_u32(smemc);
    constexpr int ABUF_B  = 128 * HROW_B;
    constexpr int BBUF_B  = NTILE * HROW_B;
    constexpr int STAGE_B = ABUF_B + BBUF_B;
    constexpr int NT      = NTILE / 16;

    const int tid = threadIdx.x;
    const int z = blockIdx.z;
    const int m0 = blockIdx.y * 128;
    const int n0 = blockIdx.x * NTILE;

    const long aoff = ((long)(z / Hd)) * a_o + (long)(z % Hd) * a_i;
    const long boff = ((long)(z / Hd)) * b_o + (long)(z % Hd) * b_i;
    const long coff = ((long)(z / Hd)) * c_o + (long)(z % Hd) * c_i;
    const __half* Ap = A + aoff + (long)m0 * lda;
    const __half* Bp = B + boff + (long)n0 * ldb;

    const int lane = tid & 31, w = tid >> 5;
    const int g = lane >> 2, t4 = lane & 3;
    const int wm = (w & 3) * 32;
    const int wn = (w >> 2) * (NTILE / 2);

    // ldmatrix per-lane address components
    const int seg = lane >> 3, rr = lane & 7;
    const uint32_t a_lm = (uint32_t)((wm + (seg & 1) * 8 + rr) * HROW_B + (seg >> 1) * 16);
    const uint32_t b_lm = (uint32_t)(ABUF_B + (wn + (seg >> 1) * 8 + rr) * HROW_B
                                     + (seg & 1) * 16);

    auto issue_stage = [&](int c, int s) {
        uint32_t sa = sbase + (uint32_t)(s * STAGE_B);
        uint32_t sb = sa + (uint32_t)ABUF_B;
#pragma unroll
        for (int i = 0; i < 4; i++) {
            int idx = tid + i * 256;
            int row = idx >> 3, sg = idx & 7;
            cp_async16(sa + (uint32_t)(row * HROW_B + sg * 16),
                       Ap + (long)row * lda + c * KC + sg * 8);
        }
#pragma unroll
        for (int i = 0; i < NTILE / 32; i++) {
            int idx = tid + i * 256;
            int row = idx >> 3, sg = idx & 7;
            cp_async16(sb + (uint32_t)(row * HROW_B + sg * 16),
                       Bp + (long)row * ldb + c * KC + sg * 8);
        }
    };

    const int nch = TRIM ? ((MEM_ + m0 + 128) / KC) : (Kd / KC);
    issue_stage(0, 0);
    cp_commit();

    float acc[2][NT][4] = {};

    for (int c = 0; c < nch; c++) {
        if (c + 1 < nch) issue_stage(c + 1, (c + 1) & 1);
        cp_commit();
        cp_wait1();
        __syncthreads();

        const uint32_t stg = sbase + (uint32_t)((c & 1) * STAGE_B);
#pragma unroll
        for (int ks = 0; ks < 4; ks++) {
            const uint32_t k0b = ks * 32;
            uint32_t af[2][4], bf[NT][2];
#pragma unroll
            for (int mt = 0; mt < 2; mt++)
                LDM_X4(af[mt][0], af[mt][1], af[mt][2], af[mt][3],
                       stg + a_lm + mt * 16 * HROW_B + k0b);
#pragma unroll
            for (int np = 0; np < NT / 2; np++)
                LDM_X4(bf[2*np][0], bf[2*np][1], bf[2*np+1][0], bf[2*np+1][1],
                       stg + b_lm + np * 16 * HROW_B + k0b);
#pragma unroll
            for (int mt = 0; mt < 2; mt++)
#pragma unroll
                for (int nt = 0; nt < NT; nt++)
                    mma_f16(acc[mt][nt], af[mt], bf[nt]);
        }
        __syncthreads();
    }

    // ---- epilogue ----
#pragma unroll
    for (int mt = 0; mt < 2; mt++) {
#pragma unroll
        for (int hf = 0; hf < 2; hf++) {
            const int row = m0 + wm + mt * 16 + g + hf * 8;
#pragma unroll
            for (int nt = 0; nt < NT; nt++) {
                const int cn = wn + nt * 8 + t4 * 2;
                float ox = acc[mt][nt][hf * 2 + 0];
                float oy = acc[mt][nt][hf * 2 + 1];
                if (EPI >= 1) {
                    float2 b2 = *(const float2*)(bias + n0 + cn);
                    ox += b2.x; oy += b2.y;
                }
                if (EPI == 2) { ox = gelu_f(ox); oy = gelu_f(oy); }
                if (EPI == 3) {
                    float2 r2 = *(const float2*)(resid + coff + (long)row * ldc + n0 + cn);
                    ox += r2.x; oy += r2.y;
                }
                if (VTR) {
                    __half* Ct = (__half*)Cv;
                    int b = row >> 10, key = row & (KK - 1);
                    long i0 = ((long)(b * EE + n0 + cn)) * KK + key;
                    Ct[i0]      = __float2half_rn(ox);
                    Ct[i0 + KK] = __float2half_rn(oy);
                } else if (OUTH) {
                    __half* Ch = (__half*)Cv + coff + (long)row * ldc + n0;
                    *(__half2*)(Ch + cn) = __floats2half2_rn(ox, oy);
                } else {
                    float* Cf = (float*)Cv + coff + (long)row * ldc + n0;
                    *(float2*)(Cf + cn) = make_float2(ox, oy);
                }
            }
        }
    }
}

// ---------------- score GEMM fp16 (ldmatrix): C = 0.125*A@B^T + colbias --------
template<int MODE>
__global__ __launch_bounds__(256)
void hgemm_qk(const __half* __restrict__ A, long a_o, long a_i,
              const __half* __restrict__ B, long b_o, long b_i,
              __half* __restrict__ C, long c_o, long c_i,
              const float* __restrict__ cb, long cb_o, long cb_i,
              int Hd) {
    const int m0 = blockIdx.y * 128;
    const int n0 = blockIdx.x * 128;
    if (MODE == 0) { if (n0 >= MEM_ + m0 + 128) return; }
    else           { if (n0 + 127 < (SS - 1) - (m0 + 127)) return; }

    extern __shared__ __align__(16) char smemc[];
    const uint32_t sbase = smem_u32(smemc);
    constexpr int ABUF_B = 128 * HROW_B;

    const int tid = threadIdx.x;
    const int z = blockIdx.z;

    const __half* Ap = A + ((long)(z / Hd)) * a_o + (long)(z % Hd) * a_i
                         + (long)m0 * EE;
    const __half* Bp = B + ((long)(z / Hd)) * b_o + (long)(z % Hd) * b_i
                         + (long)n0 * EE;
    const long coff = ((long)(z / Hd)) * c_o + (long)(z % Hd) * c_i;
    const float* cbp = cb + ((long)(z / Hd)) * cb_o + (long)(z % Hd) * cb_i + n0;

    const int lane = tid & 31, w = tid >> 5;
    const int g = lane >> 2, t4 = lane & 3;
    const int wm = (w & 3) * 32;
    const int wn = (w >> 2) * 64;

    const int seg = lane >> 3, rr = lane & 7;
    const uint32_t a_lm = (uint32_t)((wm + (seg & 1) * 8 + rr) * HROW_B + (seg >> 1) * 16);
    const uint32_t b_lm = (uint32_t)(ABUF_B + (wn + (seg >> 1) * 8 + rr) * HROW_B
                                     + (seg & 1) * 16);

#pragma unroll
    for (int i = 0; i < 4; i++) {
        int idx = tid + i * 256;
        int row = idx >> 3, sg = idx & 7;
        cp_async16(sbase + (uint32_t)(row * HROW_B + sg * 16),
                   Ap + (long)row * EE + sg * 8);
        cp_async16(sbase + (uint32_t)(ABUF_B + row * HROW_B + sg * 16),
                   Bp + (long)row * EE + sg * 8);
    }
    cp_commit();
    cp_wait0();
    __syncthreads();

    float acc[2][8][4] = {};
#pragma unroll
    for (int ks = 0; ks < 4; ks++) {
        const uint32_t k0b = ks * 32;
        uint32_t af[2][4], bf[8][2];
#pragma unroll
        for (int mt = 0; mt < 2; mt++)
            LDM_X4(af[mt][0], af[mt][1], af[mt][2], af[mt][3],
                   sbase + a_lm + mt * 16 * HROW_B + k0b);
#pragma unroll
        for (int np = 0; np < 4; np++)
            LDM_X4(bf[2*np][0], bf[2*np][1], bf[2*np+1][0], bf[2*np+1][1],
                   sbase + b_lm + np * 16 * HROW_B + k0b);
#pragma unroll
        for (int mt = 0; mt < 2; mt++)
#pragma unroll
            for (int nt = 0; nt < 8; nt++)
                mma_f16(acc[mt][nt], af[mt], bf[nt]);
    }

#pragma unroll
    for (int mt = 0; mt < 2; mt++) {
#pragma unroll
        for (int hf = 0; hf < 2; hf++) {
            const int row = m0 + wm + mt * 16 + g + hf * 8;
            __half* Cr = C + coff + (long)row * KK + n0;
#pragma unroll
            for (int nt = 0; nt < 8; nt++) {
                const int cn = wn + nt * 8 + t4 * 2;
                float2 b2 = *(const float2*)(cbp + cn);
                *(__half2*)(Cr + cn) = __floats2half2_rn(
                    acc[mt][nt][hf * 2 + 0] * 0.125f + b2.x,
                    acc[mt][nt][hf * 2 + 1] * 0.125f + b2.y);
            }
        }
    }
}

// ---------------- weight transpose + convert: Wt[n][k] = half(W[k][n]) ---------
__global__ __launch_bounds__(256)
void w_tr(const float* __restrict__ W, __half* __restrict__ Wt,
          int K, int N, long wstride, long tstride) {
    __shared__ float t[32][33];
    const float* Wl = W + (long)blockIdx.z * wstride;
    __half* Wtl = Wt + (long)blockIdx.z * tstride;
    int k0 = blockIdx.y * 32, n0 = blockIdx.x * 32;
    int tid = threadIdx.x;
#pragma unroll
    for (int i = 0; i < 4; i++) {
        int idx = tid + i * 256;
        int r = idx >> 5, c = idx & 31;
        t[r][c] = Wl[(long)(k0 + r) * N + n0 + c];
    }
    __syncthreads();
#pragma unroll
    for (int i = 0; i < 4; i++) {
        int idx = tid + i * 256;
        int r = idx >> 5, c = idx & 31;
        Wtl[(long)(n0 + r) * K + k0 + c] = __float2half_rn(t[c][r]);
    }
}

// ---------------- fp32 -> half elementwise -------------------------------------
__global__ void conv_half(const float* __restrict__ in, __half* __restrict__ outp) {
    int idx = blockIdx.x * 256 + threadIdx.x;
    outp[idx] = __float2half_rn(in[idx]);
}

// ---------------- positional embedding (half) ----------------------------------
__global__ void pe_kernel(__half* __restrict__ pe) {
    int idx = blockIdx.x * 256 + threadIdx.x;
    int m = idx >> 9, c = idx & 511;
    double pos  = (double)(KK - m);
    int    t2   = c & 255;
    double invf = exp(-((double)(2 * t2) / 512.0) * log(10000.0));
    double a    = pos * invf;
    pe[idx] = __float2half_rn((float)((c < 256) ? sin(a) : cos(a)));
}

// ---------------- layer norm (fp32 in, half out) -------------------------------
__device__ __forceinline__ void ln_row_h(const float* __restrict__ src,
                                         __half* __restrict__ dst,
                                         const float* __restrict__ g,
                                         const float* __restrict__ be, int lane) {
    float4 vals[4];
    float s = 0.f, ss = 0.f;
#pragma unroll
    for (int t = 0; t < 4; t++) {
        vals[t] = *(const float4*)(src + lane * 4 + t * 128);
        s  += vals[t].x + vals[t].y + vals[t].z + vals[t].w;
        ss += vals[t].x*vals[t].x + vals[t].y*vals[t].y
            + vals[t].z*vals[t].z + vals[t].w*vals[t].w;
    }
#pragma unroll
    for (int o = 16; o; o >>= 1) {
        s  += __shfl_xor_sync(0xffffffffu, s,  o);
        ss += __shfl_xor_sync(0xffffffffu, ss, o);
    }
    float mean = s * (1.f / 512.f);
    float var  = ss * (1.f / 512.f) - mean * mean;
    float rstd = rsqrtf(var + 1e-6f);
#pragma unroll
    for (int t = 0; t < 4; t++) {
        int e = lane * 4 + t * 128;
        float ox = (vals[t].x - mean) * rstd * g[e+0] + be[e+0];
        float oy = (vals[t].y - mean) * rstd * g[e+1] + be[e+1];
        float oz = (vals[t].z - mean) * rstd * g[e+2] + be[e+2];
        float ow = (vals[t].w - mean) * rstd * g[e+3] + be[e+3];
        *(__half2*)(dst + e)     = __floats2half2_rn(ox, oy);
        *(__half2*)(dst + e + 2) = __floats2half2_rn(oz, ow);
    }
}

__global__ void ln_concat_k(const float* __restrict__ mem, const float* __restrict__ x,
                            const float* __restrict__ gam, const float* __restrict__ bet,
                            __half* __restrict__ out, int l) {
    int row  = blockIdx.x * 8 + (threadIdx.x >> 5);
    int lane = threadIdx.x & 31;
    int b = row >> 10, j = row & 1023;
    const float* src = (j < MEM_)
        ? (mem + ((long)(b * MEM_ + j) * LL + l) * EE)
        : (x   +  (long)(b * SS + (j - MEM_)) * EE);
    ln_row_h(src, out + (long)row * EE, gam + l * EE, bet + l * EE, lane);
}

__global__ void ln_plain_k(const float* __restrict__ in,
                           const float* __restrict__ gam, const float* __restrict__ bet,
                           __half* __restrict__ out, int l) {
    int row  = blockIdx.x * 8 + (threadIdx.x >> 5);
    int lane = threadIdx.x & 31;
    ln_row_h(in + (long)row * EE, out + (long)row * EE, gam + l * EE, bet + l * EE, lane);
}

// ---------------- column-bias prep (half k) ------------------------------------
__global__ __launch_bounds__(256)
void bias_uk(const __half* __restrict__ kmat, long bstride,
             const float* __restrict__ uvec,
             float* __restrict__ out, long obstride) {
    int b = blockIdx.y;
    int j = blockIdx.x * 8 + (threadIdx.x >> 5);
    int lane = threadIdx.x & 31;
    const __half* krow = kmat + (long)b * bstride + (long)j * EE;
    float* orow = out + (long)b * obstride;
#pragma unroll
    for (int h = 0; h < HH; h++) {
        float s = __half2float(krow[h * 64 + lane])      * uvec[h * 64 + lane]
                + __half2float(krow[h * 64 + lane + 32]) * uvec[h * 64 + lane + 32];
#pragma unroll
        for (int o = 16; o; o >>= 1) s += __shfl_xor_sync(0xffffffffu, s, o);
        if (lane == 0) orow[h * KK + j] = 0.125f * s;
    }
}

// ---------------- masked rel-shift softmax (half in/out, write-trimmed) --------
__global__ __launch_bounds__(256)
void softmax_k(__half* __restrict__ sc, const __half* __restrict__ P) {
    long row = (long)blockIdx.x * 8 + (threadIdx.x >> 5);
    int lane = threadIdx.x & 31;
    int i = (int)(row & (SS - 1));
    int jmax = MEM_ + i;
    int nfill = (MEM_ + (i | 127) + 1) >> 5;
    __half* srow = sc + row * KK;
    const __half* prow = P + row * KK + (SS - 1 - i);
    float v[32];
    float mx = -1e30f;
#pragma unroll
    for (int t = 0; t < 32; t++) {
        int j = t * 32 + lane;
        float x = -1e30f;
        if (j <= jmax) x = __half2float(srow[j]) + __half2float(prow[j]);
        v[t] = x;
        mx = fmaxf(mx, x);
    }
#pragma unroll
    for (int o = 16; o; o >>= 1) mx = fmaxf(mx, __shfl_xor_sync(0xffffffffu, mx, o));
    float s = 0.f;
#pragma unroll
    for (int t = 0; t < 32; t++) {
        float e = (v[t] > -1e29f) ? __expf(v[t] - mx) : 0.f;
        v[t] = e; s += e;
    }
#pragma unroll
    for (int o = 16; o; o >>= 1) s += __shfl_xor_sync(0xffffffffu, s, o);
    float inv = 1.f / s;
#pragma unroll
    for (int t = 0; t < 32; t++)
        if (t < nfill) srow[t * 32 + lane] = __float2half_rn(v[t] * inv);
}

// ---------------- host orchestration ------------------------------------------
#define SM128 (2 * (128 + 128) * HROW_B)      // 73728
#define SM64  (2 * (128 + 64)  * HROW_B)      // 55296
#define SMQK  (2 * 128 * HROW_B)              // 36864

extern "C" void kernel_launch(void* const* d_in, const int* in_sizes, int n_in,
                              void* d_out, int out_size) {
    (void)in_sizes; (void)n_in; (void)out_size;
    const float* obs    = (const float*)d_in[0];
    const float* mems   = (const float*)d_in[1];
    const float* W_enc  = (const float*)d_in[3];
    const float* b_enc  = (const float*)d_in[4];
    const float* ln1_s  = (const float*)d_in[5];
    const float* ln1_b  = (const float*)d_in[6];
    const float* Wq     = (const float*)d_in[7];
    const float* bq     = (const float*)d_in[8];
    const float* Wk     = (const float*)d_in[9];
    const float* bk     = (const float*)d_in[10];
    const float* Wv     = (const float*)d_in[11];
    const float* bv     = (const float*)d_in[12];
    const float* Wr     = (const float*)d_in[13];
    const float* ub     = (const float*)d_in[14];
    const float* vbias  = (const float*)d_in[15];
    const float* Wo     = (const float*)d_in[16];
    const float* bo     = (const float*)d_in[17];
    const float* ln2_s  = (const float*)d_in[18];
    const float* ln2_b  = (const float*)d_in[19];
    const float* W1     = (const float*)d_in[20];
    const float* b1     = (const float*)d_in[21];
    const float* W2     = (const float*)d_in[22];
    const float* b2     = (const float*)d_in[23];
    float* out = (float*)d_out;

    float *px, *ph, *pcu, *pcv;
    __half *pobsh, *pvkh, *pqh, *pkh, *pvth, *poh, *prh, *ppeh, *phnh, *pth, *psch, *pPh;
    __half *pwet, *pwkt, *pwvt, *pwqt, *pwrt, *pwot, *pw1t, *pw2t;
    cudaGetSymbolAddress((void**)&px,   g_x);
    cudaGetSymbolAddress((void**)&ph,   g_h);
    cudaGetSymbolAddress((void**)&pcu,  g_cu);
    cudaGetSymbolAddress((void**)&pcv,  g_cv);
    cudaGetSymbolAddress((void**)&pobsh,g_obsh);
    cudaGetSymbolAddress((void**)&pvkh, g_vkh);
    cudaGetSymbolAddress((void**)&pqh,  g_qh);
    cudaGetSymbolAddress((void**)&pkh,  g_kh);
    cudaGetSymbolAddress((void**)&pvth, g_vth);
    cudaGetSymbolAddress((void**)&poh,  g_oh);
    cudaGetSymbolAddress((void**)&prh,  g_rh);
    cudaGetSymbolAddress((void**)&ppeh, g_peh);
    cudaGetSymbolAddress((void**)&phnh, g_hnh);
    cudaGetSymbolAddress((void**)&pth,  g_th);
    cudaGetSymbolAddress((void**)&psch, g_sch);
    cudaGetSymbolAddress((void**)&pPh,  g_Ph);
    cudaGetSymbolAddress((void**)&pwet, g_wet);
    cudaGetSymbolAddress((void**)&pwkt, g_wkt);
    cudaGetSymbolAddress((void**)&pwvt, g_wvt);
    cudaGetSymbolAddress((void**)&pwqt, g_wqt);
    cudaGetSymbolAddress((void**)&pwrt, g_wrt);
    cudaGetSymbolAddress((void**)&pwot, g_wot);
    cudaGetSymbolAddress((void**)&pw1t, g_w1t);
    cudaGetSymbolAddress((void**)&pw2t, g_w2t);

    cudaFuncSetAttribute(hgemm<128,1,0,0,0>, cudaFuncAttributeMaxDynamicSharedMemorySize, SM128);
    cudaFuncSetAttribute(hgemm<128,1,1,0,0>, cudaFuncAttributeMaxDynamicSharedMemorySize, SM128);
    cudaFuncSetAttribute(hgemm<128,1,1,1,0>, cudaFuncAttributeMaxDynamicSharedMemorySize, SM128);
    cudaFuncSetAttribute(hgemm<128,0,1,0,0>, cudaFuncAttributeMaxDynamicSharedMemorySize, SM128);
    cudaFuncSetAttribute(hgemm<128,3,0,0,0>, cudaFuncAttributeMaxDynamicSharedMemorySize, SM128);
    cudaFuncSetAttribute(hgemm<128,2,1,0,0>, cudaFuncAttributeMaxDynamicSharedMemorySize, SM128);
    cudaFuncSetAttribute(hgemm<64,0,1,0,1>,  cudaFuncAttributeMaxDynamicSharedMemorySize, SM64);
    cudaFuncSetAttribute(hgemm_qk<0>, cudaFuncAttributeMaxDynamicSharedMemorySize, SMQK);
    cudaFuncSetAttribute(hgemm_qk<1>, cudaFuncAttributeMaxDynamicSharedMemorySize, SMQK);

    const long SE = (long)SS * EE, KE = (long)KK * EE, SK = (long)SS * KK;
    const long HSK = (long)HH * SK;
    const long EK = (long)EE * KK;

    // ---- one-time conversions ----
    conv_half<<<(BB * SS * OBS_) / 256, 256>>>(obs, pobsh);
    w_tr<<<dim3(16, 4, 1),  256>>>(W_enc, pwet, OBS_, EE, 0, 0);
    w_tr<<<dim3(16, 16, LL), 256>>>(Wk, pwkt, EE, EE, (long)LW, (long)LW);
    w_tr<<<dim3(16, 16, LL), 256>>>(Wv, pwvt, EE, EE, (long)LW, (long)LW);
    w_tr<<<dim3(16, 16, LL), 256>>>(Wq, pwqt, EE, EE, (long)LW, (long)LW);
    w_tr<<<dim3(16, 16, LL), 256>>>(Wr, pwrt, EE, EE, (long)LW, (long)LW);
    w_tr<<<dim3(16, 16, LL), 256>>>(Wo, pwot, EE, EE, (long)LW, (long)LW);
    w_tr<<<dim3(16, 16, LL), 256>>>(W1, pw1t, EE, EE, (long)LW, (long)LW);
    w_tr<<<dim3(16, 16, LL), 256>>>(W2, pw2t, EE, EE, (long)LW, (long)LW);
    pe_kernel<<<(KK * EE) / 256, 256>>>(ppeh);

    // encoder: x = obs @ W_enc + b_enc  (fp32 out)
    hgemm<128,1,0,0,0><<<dim3(4, 32, 1), 256, SM128>>>(
        pobsh, 0, 0, OBS_, pwet, 0, 0, OBS_, px, 0, 0, EE,
        b_enc, nullptr, 1, OBS_);

    for (int l = 0; l < LL; l++) {
        ln_concat_k<<<(BB * KK) / 8, 256>>>(mems, px, ln1_s, ln1_b, pvkh, l);

        hgemm<128,1,1,0,0><<<dim3(4, 64, 1), 256, SM128>>>(
            pvkh, 0, 0, EE, pwkt + (long)l * LW, 0, 0, EE, pkh, 0, 0, EE,
            bk + l * EE, nullptr, 1, EE);
        hgemm<128,1,1,1,0><<<dim3(4, 64, 1), 256, SM128>>>(
            pvkh, 0, 0, EE, pwvt + (long)l * LW, 0, 0, EE, pvth, 0, 0, 0,
            bv + l * EE, nullptr, 1, EE);
        hgemm<128,1,1,0,0><<<dim3(4, 4, BB), 256, SM128>>>(
            pvkh + (long)MEM_ * EE, KE, 0, EE, pwqt + (long)l * LW, 0, 0, EE,
            pqh, SE, 0, EE, bq + l * EE, nullptr, 1, EE);
        hgemm<128,0,1,0,0><<<dim3(4, 8, 1), 256, SM128>>>(
            ppeh, 0, 0, EE, pwrt + (long)l * LW, 0, 0, EE, prh, 0, 0, EE,
            nullptr, nullptr, 1, EE);

        bias_uk<<<dim3(KK / 8, BB), 256>>>(pkh, KE, ub + (long)l * EE,
                                           pcu, (long)HH * KK);
        bias_uk<<<dim3(KK / 8, 1), 256>>>(prh, 0, vbias + (long)l * EE,
                                          pcv, 0);

        hgemm_qk<0><<<dim3(8, 4, BB * HH), 256, SMQK>>>(
            pqh, SE, DH_, pkh, KE, DH_, psch, HSK, SK,
            pcu, (long)HH * KK, KK, HH);
        hgemm_qk<1><<<dim3(8, 4, BB * HH), 256, SMQK>>>(
            pqh, SE, DH_, prh, 0, DH_, pPh, HSK, SK,
            pcv, 0, KK, HH);

        softmax_k<<<(BB * HH * SS) / 8, 256>>>(psch, pPh);

        hgemm<64,0,1,0,1><<<dim3(1, 4, BB * HH), 256, SM64>>>(
            psch, HSK, SK, KK, pvth, EK, (long)64 * KK, KK,
            poh, SE, 64, EE, nullptr, nullptr, HH, KK);

        hgemm<128,3,0,0,0><<<dim3(4, 32, 1), 256, SM128>>>(
            poh, 0, 0, EE, pwot + (long)l * LW, 0, 0, EE, ph, 0, 0, EE,
            bo + l * EE, px, 1, EE);
        ln_plain_k<<<(BB * SS) / 8, 256>>>(ph, ln2_s, ln2_b, phnh, l);
        hgemm<128,2,1,0,0><<<dim3(4, 32, 1), 256, SM128>>>(
            phnh, 0, 0, EE, pw1t + (long)l * LW, 0, 0, EE, pth, 0, 0, EE,
            b1 + l * EE, nullptr, 1, EE);
        float* xo = (l == LL - 1) ? out : px;
        hgemm<128,3,0,0,0><<<dim3(4, 32, 1), 256, SM128>>>(
            pth, 0, 0, EE, pw2t + (long)l * LW, 0, 0, EE, xo, 0, 0, EE,
            b2 + l * EE, ph, 1, EE);
    }
}

// round 16
// speedup vs baseline: 1.8658x; 1.0259x over previous
#include <cuda_runtime.h>
#include <cuda_fp16.h>
#include <cstdint>

// Shapes (fixed)
#define BB   8
#define SS   512
#define MEM_ 512
#define LL   4
#define EE   512
#define HH   8
#define DH_  64
#define OBS_ 128
#define KK   1024
#define LW   (EE*EE)

// ---------------- scratch ------------------------------------------------------
__device__ float  g_x [BB*SS*EE];
__device__ float  g_h [BB*SS*EE];
__device__ float  g_cu[BB*HH*KK];
__device__ float  g_cv[HH*KK];

__device__ __half g_obsh[BB*SS*OBS_];
__device__ __half g_vkh[BB*KK*EE];
__device__ __half g_qh [BB*SS*EE];
__device__ __half g_kh [BB*KK*EE];
__device__ __half g_vth[(long)BB*EE*KK];
__device__ __half g_oh [BB*SS*EE];
__device__ __half g_rh [KK*EE];
__device__ __half g_peh[KK*EE];
__device__ __half g_hnh[BB*SS*EE];
__device__ __half g_th [BB*SS*EE];
__device__ __half g_sch[(long)BB*HH*SS*KK];
__device__ __half g_Ph [(long)BB*HH*SS*KK];

__device__ __half g_wet [512*128];
__device__ __half g_wkvt[LL*1024*512];   // [l][ Wk^T(512) ; Wv^T(512) ][512]
__device__ __half g_wqt [LL*LW];
__device__ __half g_wrt [LL*LW];
__device__ __half g_wot [LL*LW];
__device__ __half g_w1t [LL*LW];
__device__ __half g_w2t [LL*LW];

// ---------------- helpers ------------------------------------------------------
__device__ __forceinline__ uint32_t smem_u32(const void* p) {
    uint32_t a;
    asm("{ .reg .u64 t; cvta.to.shared.u64 t, %1; cvt.u32.u64 %0, t; }"
        : "=r"(a) : "l"(p));
    return a;
}
__device__ __forceinline__ void cp_async16(uint32_t dst, const void* src) {
    asm volatile("cp.async.cg.shared.global [%0], [%1], 16;"
                 :: "r"(dst), "l"(src) : "memory");
}
__device__ __forceinline__ void cp_commit() {
    asm volatile("cp.async.commit_group;" ::: "memory");
}
__device__ __forceinline__ void cp_wait0() {
    asm volatile("cp.async.wait_group 0;" ::: "memory");
}
__device__ __forceinline__ void cp_wait1() {
    asm volatile("cp.async.wait_group 1;" ::: "memory");
}
__device__ __forceinline__ void mma_f16(float* d, const uint32_t* a, const uint32_t* b) {
    asm volatile(
        "mma.sync.aligned.m16n8k16.row.col.f32.f16.f16.f32 "
        "{%0,%1,%2,%3}, {%4,%5,%6,%7}, {%8,%9}, {%0,%1,%2,%3};"
        : "+f"(d[0]), "+f"(d[1]), "+f"(d[2]), "+f"(d[3])
        : "r"(a[0]), "r"(a[1]), "r"(a[2]), "r"(a[3]), "r"(b[0]), "r"(b[1]));
}
#define LDM_X4(d0, d1, d2, d3, addr) \
    asm volatile("ldmatrix.sync.aligned.m8n8.x4.shared.b16 {%0,%1,%2,%3}, [%4];" \
                 : "=r"(d0), "=r"(d1), "=r"(d2), "=r"(d3) : "r"(addr))

__device__ __forceinline__ float gelu_f(float x) {
    return 0.5f * x * (1.0f + tanhf(0.7978845608028654f * (x + 0.044715f * x * x * x)));
}

#define KC      64
#define HROW_B  144

// ==== shared GEMM machinery macros =============================================
#define GEMM_CORE_DECL                                                          \
    const int lane = tid & 31, w = tid >> 5;                                    \
    const int g = lane >> 2, t4 = lane & 3;                                     \
    const int wm = (w & 3) * 32;                                                \
    const int seg = lane >> 3, rr = lane & 7;

// ---------------- generic fp16 GEMM (encoder / Wo / FF / probs@V) --------------
template<int NTILE, int EPI, int OUTH, int TRIM>
__global__ __launch_bounds__(256)
void hgemm(const __half* __restrict__ A, long a_o, long a_i, int lda,
           const __half* __restrict__ B, long b_o, long b_i, int ldb,
           void* __restrict__ Cv, long c_o, long c_i, int ldc,
           const float* __restrict__ bias, const float* __restrict__ resid,
           int Hd, int Kd) {
    extern __shared__ __align__(16) char smemc[];
    const uint32_t sbase = smem_u32(smemc);
    constexpr int ABUF_B  = 128 * HROW_B;
    constexpr int BBUF_B  = NTILE * HROW_B;
    constexpr int STAGE_B = ABUF_B + BBUF_B;
    constexpr int NT      = NTILE / 16;

    const int tid = threadIdx.x;
    const int z = blockIdx.z;
    const int m0 = blockIdx.y * 128;
    const int n0 = blockIdx.x * NTILE;

    const long aoff = ((long)(z / Hd)) * a_o + (long)(z % Hd) * a_i;
    const long boff = ((long)(z / Hd)) * b_o + (long)(z % Hd) * b_i;
    const long coff = ((long)(z / Hd)) * c_o + (long)(z % Hd) * c_i;
    const __half* Ap = A + aoff + (long)m0 * lda;
    const __half* Bp = B + boff + (long)n0 * ldb;

    GEMM_CORE_DECL
    const int wn = (w >> 2) * (NTILE / 2);
    const uint32_t a_lm = (uint32_t)((wm + (seg & 1) * 8 + rr) * HROW_B + (seg >> 1) * 16);
    const uint32_t b_lm = (uint32_t)(ABUF_B + (wn + (seg >> 1) * 8 + rr) * HROW_B
                                     + (seg & 1) * 16);

    auto issue_stage = [&](int c, int s) {
        uint32_t sa = sbase + (uint32_t)(s * STAGE_B);
        uint32_t sb = sa + (uint32_t)ABUF_B;
#pragma unroll
        for (int i = 0; i < 4; i++) {
            int idx = tid + i * 256;
            int row = idx >> 3, sg = idx & 7;
            cp_async16(sa + (uint32_t)(row * HROW_B + sg * 16),
                       Ap + (long)row * lda + c * KC + sg * 8);
        }
#pragma unroll
        for (int i = 0; i < NTILE / 32; i++) {
            int idx = tid + i * 256;
            int row = idx >> 3, sg = idx & 7;
            cp_async16(sb + (uint32_t)(row * HROW_B + sg * 16),
                       Bp + (long)row * ldb + c * KC + sg * 8);
        }
    };

    const int nch = TRIM ? ((MEM_ + m0 + 128) / KC) : (Kd / KC);
    issue_stage(0, 0);
    cp_commit();

    float acc[2][NT][4] = {};

    for (int c = 0; c < nch; c++) {
        if (c + 1 < nch) issue_stage(c + 1, (c + 1) & 1);
        cp_commit();
        cp_wait1();
        __syncthreads();

        const uint32_t stg = sbase + (uint32_t)((c & 1) * STAGE_B);
#pragma unroll
        for (int ks = 0; ks < 4; ks++) {
            const uint32_t k0b = ks * 32;
            uint32_t af[2][4], bf[NT][2];
#pragma unroll
            for (int mt = 0; mt < 2; mt++)
                LDM_X4(af[mt][0], af[mt][1], af[mt][2], af[mt][3],
                       stg + a_lm + mt * 16 * HROW_B + k0b);
#pragma unroll
            for (int np = 0; np < NT / 2; np++)
                LDM_X4(bf[2*np][0], bf[2*np][1], bf[2*np+1][0], bf[2*np+1][1],
                       stg + b_lm + np * 16 * HROW_B + k0b);
#pragma unroll
            for (int mt = 0; mt < 2; mt++)
#pragma unroll
                for (int nt = 0; nt < NT; nt++)
                    mma_f16(acc[mt][nt], af[mt], bf[nt]);
        }
        __syncthreads();
    }

#pragma unroll
    for (int mt = 0; mt < 2; mt++) {
#pragma unroll
        for (int hf = 0; hf < 2; hf++) {
            const int row = m0 + wm + mt * 16 + g + hf * 8;
#pragma unroll
            for (int nt = 0; nt < NT; nt++) {
                const int cn = wn + nt * 8 + t4 * 2;
                float ox = acc[mt][nt][hf * 2 + 0];
                float oy = acc[mt][nt][hf * 2 + 1];
                if (EPI >= 1) {
                    float2 b2 = *(const float2*)(bias + n0 + cn);
                    ox += b2.x; oy += b2.y;
                }
                if (EPI == 2) { ox = gelu_f(ox); oy = gelu_f(oy); }
                if (EPI == 3) {
                    float2 r2 = *(const float2*)(resid + coff + (long)row * ldc + n0 + cn);
                    ox += r2.x; oy += r2.y;
                }
                if (OUTH) {
                    __half* Ch = (__half*)Cv + coff + (long)row * ldc + n0;
                    *(__half2*)(Ch + cn) = __floats2half2_rn(ox, oy);
                } else {
                    float* Cf = (float*)Cv + coff + (long)row * ldc + n0;
                    *(float2*)(Cf + cn) = make_float2(ox, oy);
                }
            }
        }
    }
}

// ---------------- merged K+V projection -----------------------------------------
// A = vk [B*K][E], B = [Wk^T;Wv^T] [1024][512]. n<512 -> kh normal (+bk);
// n>=512 -> vth transposed [b][dh][keys] (+bv). grid (8, 64).
__global__ __launch_bounds__(256)
void hgemm_kv(const __half* __restrict__ A, const __half* __restrict__ B,
              __half* __restrict__ Ck, __half* __restrict__ Cvt,
              const float* __restrict__ bk, const float* __restrict__ bv) {
    extern __shared__ __align__(16) char smemc[];
    const uint32_t sbase = smem_u32(smemc);
    constexpr int ABUF_B  = 128 * HROW_B;
    constexpr int STAGE_B = 2 * ABUF_B;

    const int tid = threadIdx.x;
    const int m0 = blockIdx.y * 128;
    const int n0 = blockIdx.x * 128;
    const __half* Ap = A + (long)m0 * EE;
    const __half* Bp = B + (long)n0 * EE;

    GEMM_CORE_DECL
    const int wn = (w >> 2) * 64;
    const uint32_t a_lm = (uint32_t)((wm + (seg & 1) * 8 + rr) * HROW_B + (seg >> 1) * 16);
    const uint32_t b_lm = (uint32_t)(ABUF_B + (wn + (seg >> 1) * 8 + rr) * HROW_B
                                     + (seg & 1) * 16);

    auto issue_stage = [&](int c, int s) {
        uint32_t sa = sbase + (uint32_t)(s * STAGE_B);
        uint32_t sb = sa + (uint32_t)ABUF_B;
#pragma unroll
        for (int i = 0; i < 4; i++) {
            int idx = tid + i * 256;
            int row = idx >> 3, sg = idx & 7;
            cp_async16(sa + (uint32_t)(row * HROW_B + sg * 16),
                       Ap + (long)row * EE + c * KC + sg * 8);
            cp_async16(sb + (uint32_t)(row * HROW_B + sg * 16),
                       Bp + (long)row * EE + c * KC + sg * 8);
        }
    };

    issue_stage(0, 0);
    cp_commit();
    float acc[2][8][4] = {};
    for (int c = 0; c < 8; c++) {
        if (c + 1 < 8) issue_stage(c + 1, (c + 1) & 1);
        cp_commit();
        cp_wait1();
        __syncthreads();
        const uint32_t stg = sbase + (uint32_t)((c & 1) * STAGE_B);
#pragma unroll
        for (int ks = 0; ks < 4; ks++) {
            const uint32_t k0b = ks * 32;
            uint32_t af[2][4], bf[8][2];
#pragma unroll
            for (int mt = 0; mt < 2; mt++)
                LDM_X4(af[mt][0], af[mt][1], af[mt][2], af[mt][3],
                       stg + a_lm + mt * 16 * HROW_B + k0b);
#pragma unroll
            for (int np = 0; np < 4; np++)
                LDM_X4(bf[2*np][0], bf[2*np][1], bf[2*np+1][0], bf[2*np+1][1],
                       stg + b_lm + np * 16 * HROW_B + k0b);
#pragma unroll
            for (int mt = 0; mt < 2; mt++)
#pragma unroll
                for (int nt = 0; nt < 8; nt++)
                    mma_f16(acc[mt][nt], af[mt], bf[nt]);
        }
        __syncthreads();
    }

    const bool isv = (n0 >= 512);
    const float* bb = isv ? (bv + n0 - 512) : (bk + n0);
#pragma unroll
    for (int mt = 0; mt < 2; mt++) {
#pragma unroll
        for (int hf = 0; hf < 2; hf++) {
            const int row = m0 + wm + mt * 16 + g + hf * 8;
#pragma unroll
            for (int nt = 0; nt < 8; nt++) {
                const int cn = wn + nt * 8 + t4 * 2;
                float2 b2 = *(const float2*)(bb + cn);
                float ox = acc[mt][nt][hf * 2 + 0] + b2.x;
                float oy = acc[mt][nt][hf * 2 + 1] + b2.y;
                if (isv) {
                    int b = row >> 10, key = row & (KK - 1);
                    long i0 = ((long)(b * EE + n0 - 512 + cn)) * KK + key;
                    Cvt[i0]      = __float2half_rn(ox);
                    Cvt[i0 + KK] = __float2half_rn(oy);
                } else {
                    *(__half2*)(Ck + (long)row * EE + n0 + cn) = __floats2half2_rn(ox, oy);
                }
            }
        }
    }
}

// ---------------- merged Q+R projection -----------------------------------------
// grid (4, 8, 9): z<8 -> Q batch z (m tiles 0..3 only), z==8 -> R (8 m tiles).
__global__ __launch_bounds__(256)
void hgemm_qr(const __half* __restrict__ vk, const __half* __restrict__ pe,
              const __half* __restrict__ Wq, const __half* __restrict__ Wr,
              __half* __restrict__ q, __half* __restrict__ r,
              const float* __restrict__ bq) {
    const int z = blockIdx.z;
    const int m0 = blockIdx.y * 128;
    const bool isr = (z == 8);
    if (!isr && blockIdx.y >= 4) return;

    extern __shared__ __align__(16) char smemc[];
    const uint32_t sbase = smem_u32(smemc);
    constexpr int ABUF_B  = 128 * HROW_B;
    constexpr int STAGE_B = 2 * ABUF_B;

    const int tid = threadIdx.x;
    const int n0 = blockIdx.x * 128;
    const __half* Ap = (isr ? pe : (vk + (long)MEM_ * EE + (long)z * KK * EE))
                       + (long)m0 * EE;
    const __half* Bp = (isr ? Wr : Wq) + (long)n0 * EE;
    __half* Cb = isr ? (r + (long)m0 * EE) : (q + (long)z * SS * EE + (long)m0 * EE);

    GEMM_CORE_DECL
    const int wn = (w >> 2) * 64;
    const uint32_t a_lm = (uint32_t)((wm + (seg & 1) * 8 + rr) * HROW_B + (seg >> 1) * 16);
    const uint32_t b_lm = (uint32_t)(ABUF_B + (wn + (seg >> 1) * 8 + rr) * HROW_B
                                     + (seg & 1) * 16);

    auto issue_stage = [&](int c, int s) {
        uint32_t sa = sbase + (uint32_t)(s * STAGE_B);
        uint32_t sb = sa + (uint32_t)ABUF_B;
#pragma unroll
        for (int i = 0; i < 4; i++) {
            int idx = tid + i * 256;
            int row = idx >> 3, sg = idx & 7;
            cp_async16(sa + (uint32_t)(row * HROW_B + sg * 16),
                       Ap + (long)row * EE + c * KC + sg * 8);
            cp_async16(sb + (uint32_t)(row * HROW_B + sg * 16),
                       Bp + (long)row * EE + c * KC + sg * 8);
        }
    };

    issue_stage(0, 0);
    cp_commit();
    float acc[2][8][4] = {};
    for (int c = 0; c < 8; c++) {
        if (c + 1 < 8) issue_stage(c + 1, (c + 1) & 1);
        cp_commit();
        cp_wait1();
        __syncthreads();
        const uint32_t stg = sbase + (uint32_t)((c & 1) * STAGE_B);
#pragma unroll
        for (int ks = 0; ks < 4; ks++) {
            const uint32_t k0b = ks * 32;
            uint32_t af[2][4], bf[8][2];
#pragma unroll
            for (int mt = 0; mt < 2; mt++)
                LDM_X4(af[mt][0], af[mt][1], af[mt][2], af[mt][3],
                       stg + a_lm + mt * 16 * HROW_B + k0b);
#pragma unroll
            for (int np = 0; np < 4; np++)
                LDM_X4(bf[2*np][0], bf[2*np][1], bf[2*np+1][0], bf[2*np+1][1],
                       stg + b_lm + np * 16 * HROW_B + k0b);
#pragma unroll
            for (int mt = 0; mt < 2; mt++)
#pragma unroll
                for (int nt = 0; nt < 8; nt++)
                    mma_f16(acc[mt][nt], af[mt], bf[nt]);
        }
        __syncthreads();
    }

#pragma unroll
    for (int mt = 0; mt < 2; mt++) {
#pragma unroll
        for (int hf = 0; hf < 2; hf++) {
            const int rl = wm + mt * 16 + g + hf * 8;
#pragma unroll
            for (int nt = 0; nt < 8; nt++) {
                const int cn = wn + nt * 8 + t4 * 2;
                float ox = acc[mt][nt][hf * 2 + 0];
                float oy = acc[mt][nt][hf * 2 + 1];
                if (!isr) {
                    float2 b2 = *(const float2*)(bq + n0 + cn);
                    ox += b2.x; oy += b2.y;
                }
                *(__half2*)(Cb + (long)rl * EE + n0 + cn) = __floats2half2_rn(ox, oy);
            }
        }
    }
}

// ---------------- merged AC+P score GEMM ----------------------------------------
// grid (8, 4, 128): z<64 -> AC (B=k), z>=64 -> P (B=r). 0.125*q@B^T + colbias.
__global__ __launch_bounds__(256)
void hgemm_qk2(const __half* __restrict__ q,
               const __half* __restrict__ k, const __half* __restrict__ r,
               __half* __restrict__ sc, __half* __restrict__ P,
               const float* __restrict__ cu, const float* __restrict__ cv) {
    const int m0 = blockIdx.y * 128;
    const int n0 = blockIdx.x * 128;
    const int z = blockIdx.z;
    const int task = z >> 6, zz = z & 63;
    if (task == 0) { if (n0 >= MEM_ + m0 + 128) return; }
    else           { if (n0 + 127 < (SS - 1) - (m0 + 127)) return; }

    extern __shared__ __align__(16) char smemc[];
    const uint32_t sbase = smem_u32(smemc);
    constexpr int ABUF_B = 128 * HROW_B;

    const int tid = threadIdx.x;
    const int bb = zz >> 3, hh = zz & 7;

    const __half* Ap = q + (long)bb * SS * EE + hh * DH_ + (long)m0 * EE;
    const __half* Bp = (task ? (r + hh * DH_)
                             : (k + (long)bb * KK * EE + hh * DH_)) + (long)n0 * EE;
    __half* C = (task ? P : sc) + ((long)zz * SS) * KK;
    const float* cbp = (task ? (cv + hh * KK) : (cu + (long)zz * KK)) + n0;

    GEMM_CORE_DECL
    const int wn = (w >> 2) * 64;
    const uint32_t a_lm = (uint32_t)((wm + (seg & 1) * 8 + rr) * HROW_B + (seg >> 1) * 16);
    const uint32_t b_lm = (uint32_t)(ABUF_B + (wn + (seg >> 1) * 8 + rr) * HROW_B
                                     + (seg & 1) * 16);

#pragma unroll
    for (int i = 0; i < 4; i++) {
        int idx = tid + i * 256;
        int row = idx >> 3, sg = idx & 7;
        cp_async16(sbase + (uint32_t)(row * HROW_B + sg * 16),
                   Ap + (long)row * EE + sg * 8);
        cp_async16(sbase + (uint32_t)(ABUF_B + row * HROW_B + sg * 16),
                   Bp + (long)row * EE + sg * 8);
    }
    cp_commit();
    cp_wait0();
    __syncthreads();

    float acc[2][8][4] = {};
#pragma unroll
    for (int ks = 0; ks < 4; ks++) {
        const uint32_t k0b = ks * 32;
        uint32_t af[2][4], bf[8][2];
#pragma unroll
        for (int mt = 0; mt < 2; mt++)
            LDM_X4(af[mt][0], af[mt][1], af[mt][2], af[mt][3],
                   sbase + a_lm + mt * 16 * HROW_B + k0b);
#pragma unroll
        for (int np = 0; np < 4; np++)
            LDM_X4(bf[2*np][0], bf[2*np][1], bf[2*np+1][0], bf[2*np+1][1],
                   sbase + b_lm + np * 16 * HROW_B + k0b);
#pragma unroll
        for (int mt = 0; mt < 2; mt++)
#pragma unroll
            for (int nt = 0; nt < 8; nt++)
                mma_f16(acc[mt][nt], af[mt], bf[nt]);
    }

#pragma unroll
    for (int mt = 0; mt < 2; mt++) {
#pragma unroll
        for (int hf = 0; hf < 2; hf++) {
            const int row = m0 + wm + mt * 16 + g + hf * 8;
            __half* Cr = C + (long)row * KK + n0;
#pragma unroll
            for (int nt = 0; nt < 8; nt++) {
                const int cn = wn + nt * 8 + t4 * 2;
                float2 b2 = *(const float2*)(cbp + cn);
                *(__half2*)(Cr + cn) = __floats2half2_rn(
                    acc[mt][nt][hf * 2 + 0] * 0.125f + b2.x,
                    acc[mt][nt][hf * 2 + 1] * 0.125f + b2.y);
            }
        }
    }
}

// ---------------- weight transpose + convert ------------------------------------
__global__ __launch_bounds__(256)
void w_tr(const float* __restrict__ W, __half* __restrict__ Wt,
          int K, int N, long wstride, long tstride) {
    __shared__ float t[32][33];
    const float* Wl = W + (long)blockIdx.z * wstride;
    __half* Wtl = Wt + (long)blockIdx.z * tstride;
    int k0 = blockIdx.y * 32, n0 = blockIdx.x * 32;
    int tid = threadIdx.x;
#pragma unroll
    for (int i = 0; i < 4; i++) {
        int idx = tid + i * 256;
        int r = idx >> 5, c = idx & 31;
        t[r][c] = Wl[(long)(k0 + r) * N + n0 + c];
    }
    __syncthreads();
#pragma unroll
    for (int i = 0; i < 4; i++) {
        int idx = tid + i * 256;
        int r = idx >> 5, c = idx & 31;
        Wtl[(long)(n0 + r) * K + k0 + c] = __float2half_rn(t[c][r]);
    }
}

__global__ void conv_half(const float* __restrict__ in, __half* __restrict__ outp) {
    int idx = blockIdx.x * 256 + threadIdx.x;
    outp[idx] = __float2half_rn(in[idx]);
}

__global__ void pe_kernel(__half* __restrict__ pe) {
    int idx = blockIdx.x * 256 + threadIdx.x;
    int m = idx >> 9, c = idx & 511;
    double pos  = (double)(KK - m);
    int    t2   = c & 255;
    double invf = exp(-((double)(2 * t2) / 512.0) * log(10000.0));
    double a    = pos * invf;
    pe[idx] = __float2half_rn((float)((c < 256) ? sin(a) : cos(a)));
}

// ---------------- layer norm (fp32 in, half out) --------------------------------
__device__ __forceinline__ void ln_row_h(const float* __restrict__ src,
                                         __half* __restrict__ dst,
                                         const float* __restrict__ g,
                                         const float* __restrict__ be, int lane) {
    float4 vals[4];
    float s = 0.f, ss = 0.f;
#pragma unroll
    for (int t = 0; t < 4; t++) {
        vals[t] = *(const float4*)(src + lane * 4 + t * 128);
        s  += vals[t].x + vals[t].y + vals[t].z + vals[t].w;
        ss += vals[t].x*vals[t].x + vals[t].y*vals[t].y
            + vals[t].z*vals[t].z + vals[t].w*vals[t].w;
    }
#pragma unroll
    for (int o = 16; o; o >>= 1) {
        s  += __shfl_xor_sync(0xffffffffu, s,  o);
        ss += __shfl_xor_sync(0xffffffffu, ss, o);
    }
    float mean = s * (1.f / 512.f);
    float var  = ss * (1.f / 512.f) - mean * mean;
    float rstd = rsqrtf(var + 1e-6f);
#pragma unroll
    for (int t = 0; t < 4; t++) {
        int e = lane * 4 + t * 128;
        float ox = (vals[t].x - mean) * rstd * g[e+0] + be[e+0];
        float oy = (vals[t].y - mean) * rstd * g[e+1] + be[e+1];
        float oz = (vals[t].z - mean) * rstd * g[e+2] + be[e+2];
        float ow = (vals[t].w - mean) * rstd * g[e+3] + be[e+3];
        *(__half2*)(dst + e)     = __floats2half2_rn(ox, oy);
        *(__half2*)(dst + e + 2) = __floats2half2_rn(oz, ow);
    }
}

__global__ void ln_concat_k(const float* __restrict__ mem, const float* __restrict__ x,
                            const float* __restrict__ gam, const float* __restrict__ bet,
                            __half* __restrict__ out, int l) {
    int row  = blockIdx.x * 8 + (threadIdx.x >> 5);
    int lane = threadIdx.x & 31;
    int b = row >> 10, j = row & 1023;
    const float* src = (j < MEM_)
        ? (mem + ((long)(b * MEM_ + j) * LL + l) * EE)
        : (x   +  (long)(b * SS + (j - MEM_)) * EE);
    ln_row_h(src, out + (long)row * EE, gam + l * EE, bet + l * EE, lane);
}

__global__ void ln_plain_k(const float* __restrict__ in,
                           const float* __restrict__ gam, const float* __restrict__ bet,
                           __half* __restrict__ out, int l) {
    int row  = blockIdx.x * 8 + (threadIdx.x >> 5);
    int lane = threadIdx.x & 31;
    ln_row_h(in + (long)row * EE, out + (long)row * EE, gam + l * EE, bet + l * EE, lane);
}

// ---------------- merged column-bias prep ---------------------------------------
// grid (KK/8, BB+1): y<BB -> cu from k; y==BB -> cv from r.
__global__ __launch_bounds__(256)
void bias_uk2(const __half* __restrict__ kmat, const __half* __restrict__ rmat,
              const float* __restrict__ uvec, const float* __restrict__ vvec,
              float* __restrict__ cu, float* __restrict__ cv) {
    int y = blockIdx.y;
    int j = blockIdx.x * 8 + (threadIdx.x >> 5);
    int lane = threadIdx.x & 31;
    const bool isv = (y == BB);
    const __half* krow = (isv ? rmat : (kmat + (long)y * KK * EE)) + (long)j * EE;
    const float* uv = isv ? vvec : uvec;
    float* orow = isv ? cv : (cu + (long)y * HH * KK);
#pragma unroll
    for (int h = 0; h < HH; h++) {
        float s = __half2float(krow[h * 64 + lane])      * uv[h * 64 + lane]
                + __half2float(krow[h * 64 + lane + 32]) * uv[h * 64 + lane + 32];
#pragma unroll
        for (int o = 16; o; o >>= 1) s += __shfl_xor_sync(0xffffffffu, s, o);
        if (lane == 0) orow[h * KK + j] = 0.125f * s;
    }
}

// ---------------- masked rel-shift softmax (half2 vectorized) -------------------
__global__ __launch_bounds__(256)
void softmax_k(__half* __restrict__ sc, const __half* __restrict__ P) {
    long row = (long)blockIdx.x * 8 + (threadIdx.x >> 5);
    int lane = threadIdx.x & 31;
    int i = (int)(row & (SS - 1));
    int jmax = MEM_ + i;
    int nfill = (MEM_ + (i | 127) + 1) >> 5;   // 32-col blocks to write
    __half* srow = sc + row * KK;
    const __half* prow = P + row * KK + (SS - 1 - i);
    float v[32];
    float mx = -1e30f;
#pragma unroll
    for (int t = 0; t < 16; t++) {
        int j2 = t * 64 + lane * 2;
        float x0 = -1e30f, x1 = -1e30f;
        if (j2 + 1 <= jmax) {
            float2 s2 = __half22float2(*(const __half2*)(srow + j2));
            x0 = s2.x + __half2float(prow[j2]);
            x1 = s2.y + __half2float(prow[j2 + 1]);
        } else if (j2 <= jmax) {
            x0 = __half2float(srow[j2]) + __half2float(prow[j2]);
        }
        v[2*t] = x0; v[2*t+1] = x1;
        mx = fmaxf(mx, fmaxf(x0, x1));
    }
#pragma unroll
    for (int o = 16; o; o >>= 1) mx = fmaxf(mx, __shfl_xor_sync(0xffffffffu, mx, o));
    float s = 0.f;
#pragma unroll
    for (int t = 0; t < 32; t++) {
        float e = (v[t] > -1e29f) ? __expf(v[t] - mx) : 0.f;
        v[t] = e; s += e;
    }
#pragma unroll
    for (int o = 16; o; o >>= 1) s += __shfl_xor_sync(0xffffffffu, s, o);
    float inv = 1.f / s;
#pragma unroll
    for (int t = 0; t < 16; t++) {
        int j2 = t * 64 + lane * 2;
        if ((j2 >> 5) < nfill)
            *(__half2*)(srow + j2) = __floats2half2_rn(v[2*t] * inv, v[2*t+1] * inv);
    }
}

// ---------------- host orchestration --------------------------------------------
#define SM128 (2 * (128 + 128) * HROW_B)
#define SM64  (2 * (128 + 64)  * HROW_B)
#define SMQK  (2 * 128 * HROW_B)

extern "C" void kernel_launch(void* const* d_in, const int* in_sizes, int n_in,
                              void* d_out, int out_size) {
    (void)in_sizes; (void)n_in; (void)out_size;
    const float* obs    = (const float*)d_in[0];
    const float* mems   = (const float*)d_in[1];
    const float* W_enc  = (const float*)d_in[3];
    const float* b_enc  = (const float*)d_in[4];
    const float* ln1_s  = (const float*)d_in[5];
    const float* ln1_b  = (const float*)d_in[6];
    const float* Wq     = (const float*)d_in[7];
    const float* bq     = (const float*)d_in[8];
    const float* Wk     = (const float*)d_in[9];
    const float* bk     = (const float*)d_in[10];
    const float* Wv     = (const float*)d_in[11];
    const float* bv     = (const float*)d_in[12];
    const float* Wr     = (const float*)d_in[13];
    const float* ub     = (const float*)d_in[14];
    const float* vbias  = (const float*)d_in[15];
    const float* Wo     = (const float*)d_in[16];
    const float* bo     = (const float*)d_in[17];
    const float* ln2_s  = (const float*)d_in[18];
    const float* ln2_b  = (const float*)d_in[19];
    const float* W1     = (const float*)d_in[20];
    const float* b1     = (const float*)d_in[21];
    const float* W2     = (const float*)d_in[22];
    const float* b2     = (const float*)d_in[23];
    float* out = (float*)d_out;

    float *px, *ph, *pcu, *pcv;
    __half *pobsh, *pvkh, *pqh, *pkh, *pvth, *poh, *prh, *ppeh, *phnh, *pth, *psch, *pPh;
    __half *pwet, *pwkvt, *pwqt, *pwrt, *pwot, *pw1t, *pw2t;
    cudaGetSymbolAddress((void**)&px,   g_x);
    cudaGetSymbolAddress((void**)&ph,   g_h);
    cudaGetSymbolAddress((void**)&pcu,  g_cu);
    cudaGetSymbolAddress((void**)&pcv,  g_cv);
    cudaGetSymbolAddress((void**)&pobsh,g_obsh);
    cudaGetSymbolAddress((void**)&pvkh, g_vkh);
    cudaGetSymbolAddress((void**)&pqh,  g_qh);
    cudaGetSymbolAddress((void**)&pkh,  g_kh);
    cudaGetSymbolAddress((void**)&pvth, g_vth);
    cudaGetSymbolAddress((void**)&poh,  g_oh);
    cudaGetSymbolAddress((void**)&prh,  g_rh);
    cudaGetSymbolAddress((void**)&ppeh, g_peh);
    cudaGetSymbolAddress((void**)&phnh, g_hnh);
    cudaGetSymbolAddress((void**)&pth,  g_th);
    cudaGetSymbolAddress((void**)&psch, g_sch);
    cudaGetSymbolAddress((void**)&pPh,  g_Ph);
    cudaGetSymbolAddress((void**)&pwet, g_wet);
    cudaGetSymbolAddress((void**)&pwkvt,g_wkvt);
    cudaGetSymbolAddress((void**)&pwqt, g_wqt);
    cudaGetSymbolAddress((void**)&pwrt, g_wrt);
    cudaGetSymbolAddress((void**)&pwot, g_wot);
    cudaGetSymbolAddress((void**)&pw1t, g_w1t);
    cudaGetSymbolAddress((void**)&pw2t, g_w2t);

    cudaFuncSetAttribute(hgemm<128,1,0,0>, cudaFuncAttributeMaxDynamicSharedMemorySize, SM128);
    cudaFuncSetAttribute(hgemm<128,3,0,0>, cudaFuncAttributeMaxDynamicSharedMemorySize, SM128);
    cudaFuncSetAttribute(hgemm<128,2,1,0>, cudaFuncAttributeMaxDynamicSharedMemorySize, SM128);
    cudaFuncSetAttribute(hgemm<64,0,1,1>,  cudaFuncAttributeMaxDynamicSharedMemorySize, SM64);
    cudaFuncSetAttribute(hgemm_kv,  cudaFuncAttributeMaxDynamicSharedMemorySize, SM128);
    cudaFuncSetAttribute(hgemm_qr,  cudaFuncAttributeMaxDynamicSharedMemorySize, SM128);
    cudaFuncSetAttribute(hgemm_qk2, cudaFuncAttributeMaxDynamicSharedMemorySize, SMQK);

    const long SE = (long)SS * EE, KE = (long)KK * EE, SK = (long)SS * KK;
    const long HSK = (long)HH * SK;
    const long EK = (long)EE * KK;
    const long LKV = (long)1024 * 512;

    // ---- one-time conversions ----
    conv_half<<<(BB * SS * OBS_) / 256, 256>>>(obs, pobsh);
    w_tr<<<dim3(16, 4, 1),  256>>>(W_enc, pwet, OBS_, EE, 0, 0);
    w_tr<<<dim3(16, 16, LL), 256>>>(Wk, pwkvt,                 EE, EE, (long)LW, LKV);
    w_tr<<<dim3(16, 16, LL), 256>>>(Wv, pwkvt + (long)512*512, EE, EE, (long)LW, LKV);
    w_tr<<<dim3(16, 16, LL), 256>>>(Wq, pwqt, EE, EE, (long)LW, (long)LW);
    w_tr<<<dim3(16, 16, LL), 256>>>(Wr, pwrt, EE, EE, (long)LW, (long)LW);
    w_tr<<<dim3(16, 16, LL), 256>>>(Wo, pwot, EE, EE, (long)LW, (long)LW);
    w_tr<<<dim3(16, 16, LL), 256>>>(W1, pw1t, EE, EE, (long)LW, (long)LW);
    w_tr<<<dim3(16, 16, LL), 256>>>(W2, pw2t, EE, EE, (long)LW, (long)LW);
    pe_kernel<<<(KK * EE) / 256, 256>>>(ppeh);

    // encoder
    hgemm<128,1,0,0><<<dim3(4, 32, 1), 256, SM128>>>(
        pobsh, 0, 0, OBS_, pwet, 0, 0, OBS_, px, 0, 0, EE,
        b_enc, nullptr, 1, OBS_);

    for (int l = 0; l < LL; l++) {
        ln_concat_k<<<(BB * KK) / 8, 256>>>(mems, px, ln1_s, ln1_b, pvkh, l);

        hgemm_kv<<<dim3(8, 64), 256, SM128>>>(
            pvkh, pwkvt + (long)l * LKV, pkh, pvth, bk + l * EE, bv + l * EE);
        hgemm_qr<<<dim3(4, 8, 9), 256, SM128>>>(
            pvkh, ppeh, pwqt + (long)l * LW, pwrt + (long)l * LW,
            pqh, prh, bq + l * EE);

        bias_uk2<<<dim3(KK / 8, BB + 1), 256>>>(
            pkh, prh, ub + (long)l * EE, vbias + (long)l * EE, pcu, pcv);

        hgemm_qk2<<<dim3(8, 4, 128), 256, SMQK>>>(
            pqh, pkh, prh, psch, pPh, pcu, pcv);

        softmax_k<<<(BB * HH * SS) / 8, 256>>>(psch, pPh);

        hgemm<64,0,1,1><<<dim3(1, 4, BB * HH), 256, SM64>>>(
            psch, HSK, SK, KK, pvth, EK, (long)64 * KK, KK,
            poh, SE, 64, EE, nullptr, nullptr, HH, KK);

        hgemm<128,3,0,0><<<dim3(4, 32, 1), 256, SM128>>>(
            poh, 0, 0, EE, pwot + (long)l * LW, 0, 0, EE, ph, 0, 0, EE,
            bo + l * EE, px, 1, EE);
        ln_plain_k<<<(BB * SS) / 8, 256>>>(ph, ln2_s, ln2_b, phnh, l);
        hgemm<128,2,1,0><<<dim3(4, 32, 1), 256, SM128>>>(
            phnh, 0, 0, EE, pw1t + (long)l * LW, 0, 0, EE, pth, 0, 0, EE,
            b1 + l * EE, nullptr, 1, EE);
        float* xo = (l == LL - 1) ? out : px;
        hgemm<128,3,0,0><<<dim3(4, 32, 1), 256, SM128>>>(
            pth, 0, 0, EE, pw2t + (long)l * LW, 0, 0, EE, xo, 0, 0, EE,
            b2 + l * EE, ph, 1, EE);
    }
}

// round 17
// speedup vs baseline: 1.8927x; 1.0144x over previous
#include <cuda_runtime.h>
#include <cuda_fp16.h>
#include <cstdint>

// Shapes (fixed)
#define BB   8
#define SS   512
#define MEM_ 512
#define LL   4
#define EE   512
#define HH   8
#define DH_  64
#define OBS_ 128
#define KK   1024
#define LW   (EE*EE)

// ---------------- scratch ------------------------------------------------------
__device__ float  g_x [BB*SS*EE];
__device__ float  g_h [BB*SS*EE];
__device__ float  g_cu[BB*HH*KK];
__device__ float  g_cv[HH*KK];

__device__ __half g_obsh[BB*SS*OBS_];
__device__ __half g_vkh[BB*KK*EE];
__device__ __half g_qh [BB*SS*EE];
__device__ __half g_kh [BB*KK*EE];
__device__ __half g_vth[(long)BB*EE*KK];
__device__ __half g_oh [BB*SS*EE];
__device__ __half g_rh [KK*EE];
__device__ __half g_peh[KK*EE];
__device__ __half g_hnh[BB*SS*EE];
__device__ __half g_th [BB*SS*EE];
__device__ __half g_sch[(long)BB*HH*SS*KK];
__device__ __half g_Ph [(long)BB*HH*SS*KK];

__device__ __half g_wet [512*128];
__device__ __half g_wkvt[LL*1024*512];   // [l][ Wk^T(512) ; Wv^T(512) ][512]
__device__ __half g_wqt [LL*LW];
__device__ __half g_wrt [LL*LW];
__device__ __half g_wot [LL*LW];
__device__ __half g_w1t [LL*LW];
__device__ __half g_w2t [LL*LW];

// ---------------- helpers ------------------------------------------------------
__device__ __forceinline__ uint32_t smem_u32(const void* p) {
    uint32_t a;
    asm("{ .reg .u64 t; cvta.to.shared.u64 t, %1; cvt.u32.u64 %0, t; }"
        : "=r"(a) : "l"(p));
    return a;
}
__device__ __forceinline__ void cp_async16(uint32_t dst, const void* src) {
    asm volatile("cp.async.cg.shared.global [%0], [%1], 16;"
                 :: "r"(dst), "l"(src) : "memory");
}
__device__ __forceinline__ void cp_commit() {
    asm volatile("cp.async.commit_group;" ::: "memory");
}
__device__ __forceinline__ void cp_wait0() {
    asm volatile("cp.async.wait_group 0;" ::: "memory");
}
__device__ __forceinline__ void cp_wait1() {
    asm volatile("cp.async.wait_group 1;" ::: "memory");
}
__device__ __forceinline__ void mma_f16(float* d, const uint32_t* a, const uint32_t* b) {
    asm volatile(
        "mma.sync.aligned.m16n8k16.row.col.f32.f16.f16.f32 "
        "{%0,%1,%2,%3}, {%4,%5,%6,%7}, {%8,%9}, {%0,%1,%2,%3};"
        : "+f"(d[0]), "+f"(d[1]), "+f"(d[2]), "+f"(d[3])
        : "r"(a[0]), "r"(a[1]), "r"(a[2]), "r"(a[3]), "r"(b[0]), "r"(b[1]));
}
#define LDM_X4(d0, d1, d2, d3, addr) \
    asm volatile("ldmatrix.sync.aligned.m8n8.x4.shared.b16 {%0,%1,%2,%3}, [%4];" \
                 : "=r"(d0), "=r"(d1), "=r"(d2), "=r"(d3) : "r"(addr))

__device__ __forceinline__ float gelu_f(float x) {
    return 0.5f * x * (1.0f + tanhf(0.7978845608028654f * (x + 0.044715f * x * x * x)));
}

#define KC      64
#define HROW_B  144

#define GEMM_CORE_DECL                                                          \
    const int lane = tid & 31, w = tid >> 5;                                    \
    const int g = lane >> 2, t4 = lane & 3;                                     \
    const int wm = (w & 3) * 32;                                                \
    const int seg = lane >> 3, rr = lane & 7;

// ---------------- generic fp16 GEMM (encoder / Wo / FF / probs@V) --------------
template<int NTILE, int EPI, int OUTH, int TRIM>
__global__ __launch_bounds__(256)
void hgemm(const __half* __restrict__ A, long a_o, long a_i, int lda,
           const __half* __restrict__ B, long b_o, long b_i, int ldb,
           void* __restrict__ Cv, long c_o, long c_i, int ldc,
           const float* __restrict__ bias, const float* __restrict__ resid,
           int Hd, int Kd) {
    extern __shared__ __align__(16) char smemc[];
    const uint32_t sbase = smem_u32(smemc);
    constexpr int ABUF_B  = 128 * HROW_B;
    constexpr int BBUF_B  = NTILE * HROW_B;
    constexpr int STAGE_B = ABUF_B + BBUF_B;
    constexpr int NT      = NTILE / 16;

    const int tid = threadIdx.x;
    const int z = blockIdx.z;
    const int m0 = blockIdx.y * 128;
    const int n0 = blockIdx.x * NTILE;

    const long aoff = ((long)(z / Hd)) * a_o + (long)(z % Hd) * a_i;
    const long boff = ((long)(z / Hd)) * b_o + (long)(z % Hd) * b_i;
    const long coff = ((long)(z / Hd)) * c_o + (long)(z % Hd) * c_i;
    const __half* Ap = A + aoff + (long)m0 * lda;
    const __half* Bp = B + boff + (long)n0 * ldb;

    GEMM_CORE_DECL
    const int wn = (w >> 2) * (NTILE / 2);
    const uint32_t a_lm = (uint32_t)((wm + (seg & 1) * 8 + rr) * HROW_B + (seg >> 1) * 16);
    const uint32_t b_lm = (uint32_t)(ABUF_B + (wn + (seg >> 1) * 8 + rr) * HROW_B
                                     + (seg & 1) * 16);

    auto issue_stage = [&](int c, int s) {
        uint32_t sa = sbase + (uint32_t)(s * STAGE_B);
        uint32_t sb = sa + (uint32_t)ABUF_B;
#pragma unroll
        for (int i = 0; i < 4; i++) {
            int idx = tid + i * 256;
            int row = idx >> 3, sg = idx & 7;
            cp_async16(sa + (uint32_t)(row * HROW_B + sg * 16),
                       Ap + (long)row * lda + c * KC + sg * 8);
        }
#pragma unroll
        for (int i = 0; i < NTILE / 32; i++) {
            int idx = tid + i * 256;
            int row = idx >> 3, sg = idx & 7;
            cp_async16(sb + (uint32_t)(row * HROW_B + sg * 16),
                       Bp + (long)row * ldb + c * KC + sg * 8);
        }
    };

    const int nch = TRIM ? ((MEM_ + m0 + 128) / KC) : (Kd / KC);
    issue_stage(0, 0);
    cp_commit();

    float acc[2][NT][4] = {};

    for (int c = 0; c < nch; c++) {
        if (c + 1 < nch) issue_stage(c + 1, (c + 1) & 1);
        cp_commit();
        cp_wait1();
        __syncthreads();

        const uint32_t stg = sbase + (uint32_t)((c & 1) * STAGE_B);
#pragma unroll
        for (int ks = 0; ks < 4; ks++) {
            const uint32_t k0b = ks * 32;
            uint32_t af[2][4], bf[NT][2];
#pragma unroll
            for (int mt = 0; mt < 2; mt++)
                LDM_X4(af[mt][0], af[mt][1], af[mt][2], af[mt][3],
                       stg + a_lm + mt * 16 * HROW_B + k0b);
#pragma unroll
            for (int np = 0; np < NT / 2; np++)
                LDM_X4(bf[2*np][0], bf[2*np][1], bf[2*np+1][0], bf[2*np+1][1],
                       stg + b_lm + np * 16 * HROW_B + k0b);
#pragma unroll
            for (int mt = 0; mt < 2; mt++)
#pragma unroll
                for (int nt = 0; nt < NT; nt++)
                    mma_f16(acc[mt][nt], af[mt], bf[nt]);
        }
        __syncthreads();
    }

#pragma unroll
    for (int mt = 0; mt < 2; mt++) {
#pragma unroll
        for (int hf = 0; hf < 2; hf++) {
            const int row = m0 + wm + mt * 16 + g + hf * 8;
#pragma unroll
            for (int nt = 0; nt < NT; nt++) {
                const int cn = wn + nt * 8 + t4 * 2;
                float ox = acc[mt][nt][hf * 2 + 0];
                float oy = acc[mt][nt][hf * 2 + 1];
                if (EPI >= 1) {
                    float2 b2 = *(const float2*)(bias + n0 + cn);
                    ox += b2.x; oy += b2.y;
                }
                if (EPI == 2) { ox = gelu_f(ox); oy = gelu_f(oy); }
                if (EPI == 3) {
                    float2 r2 = *(const float2*)(resid + coff + (long)row * ldc + n0 + cn);
                    ox += r2.x; oy += r2.y;
                }
                if (OUTH) {
                    __half* Ch = (__half*)Cv + coff + (long)row * ldc + n0;
                    *(__half2*)(Ch + cn) = __floats2half2_rn(ox, oy);
                } else {
                    float* Cf = (float*)Cv + coff + (long)row * ldc + n0;
                    *(float2*)(Cf + cn) = make_float2(ox, oy);
                }
            }
        }
    }
}

// ---------------- merged K+V projection -----------------------------------------
__global__ __launch_bounds__(256)
void hgemm_kv(const __half* __restrict__ A, const __half* __restrict__ B,
              __half* __restrict__ Ck, __half* __restrict__ Cvt,
              const float* __restrict__ bk, const float* __restrict__ bv) {
    extern __shared__ __align__(16) char smemc[];
    const uint32_t sbase = smem_u32(smemc);
    constexpr int ABUF_B  = 128 * HROW_B;
    constexpr int STAGE_B = 2 * ABUF_B;

    const int tid = threadIdx.x;
    const int m0 = blockIdx.y * 128;
    const int n0 = blockIdx.x * 128;
    const __half* Ap = A + (long)m0 * EE;
    const __half* Bp = B + (long)n0 * EE;

    GEMM_CORE_DECL
    const int wn = (w >> 2) * 64;
    const uint32_t a_lm = (uint32_t)((wm + (seg & 1) * 8 + rr) * HROW_B + (seg >> 1) * 16);
    const uint32_t b_lm = (uint32_t)(ABUF_B + (wn + (seg >> 1) * 8 + rr) * HROW_B
                                     + (seg & 1) * 16);

    auto issue_stage = [&](int c, int s) {
        uint32_t sa = sbase + (uint32_t)(s * STAGE_B);
        uint32_t sb = sa + (uint32_t)ABUF_B;
#pragma unroll
        for (int i = 0; i < 4; i++) {
            int idx = tid + i * 256;
            int row = idx >> 3, sg = idx & 7;
            cp_async16(sa + (uint32_t)(row * HROW_B + sg * 16),
                       Ap + (long)row * EE + c * KC + sg * 8);
            cp_async16(sb + (uint32_t)(row * HROW_B + sg * 16),
                       Bp + (long)row * EE + c * KC + sg * 8);
        }
    };

    issue_stage(0, 0);
    cp_commit();
    float acc[2][8][4] = {};
    for (int c = 0; c < 8; c++) {
        if (c + 1 < 8) issue_stage(c + 1, (c + 1) & 1);
        cp_commit();
        cp_wait1();
        __syncthreads();
        const uint32_t stg = sbase + (uint32_t)((c & 1) * STAGE_B);
#pragma unroll
        for (int ks = 0; ks < 4; ks++) {
            const uint32_t k0b = ks * 32;
            uint32_t af[2][4], bf[8][2];
#pragma unroll
            for (int mt = 0; mt < 2; mt++)
                LDM_X4(af[mt][0], af[mt][1], af[mt][2], af[mt][3],
                       stg + a_lm + mt * 16 * HROW_B + k0b);
#pragma unroll
            for (int np = 0; np < 4; np++)
                LDM_X4(bf[2*np][0], bf[2*np][1], bf[2*np+1][0], bf[2*np+1][1],
                       stg + b_lm + np * 16 * HROW_B + k0b);
#pragma unroll
            for (int mt = 0; mt < 2; mt++)
#pragma unroll
                for (int nt = 0; nt < 8; nt++)
                    mma_f16(acc[mt][nt], af[mt], bf[nt]);
        }
        __syncthreads();
    }

    const bool isv = (n0 >= 512);
    const float* bb = isv ? (bv + n0 - 512) : (bk + n0);
#pragma unroll
    for (int mt = 0; mt < 2; mt++) {
#pragma unroll
        for (int hf = 0; hf < 2; hf++) {
            const int row = m0 + wm + mt * 16 + g + hf * 8;
#pragma unroll
            for (int nt = 0; nt < 8; nt++) {
                const int cn = wn + nt * 8 + t4 * 2;
                float2 b2 = *(const float2*)(bb + cn);
                float ox = acc[mt][nt][hf * 2 + 0] + b2.x;
                float oy = acc[mt][nt][hf * 2 + 1] + b2.y;
                if (isv) {
                    int b = row >> 10, key = row & (KK - 1);
                    long i0 = ((long)(b * EE + n0 - 512 + cn)) * KK + key;
                    Cvt[i0]      = __float2half_rn(ox);
                    Cvt[i0 + KK] = __float2half_rn(oy);
                } else {
                    *(__half2*)(Ck + (long)row * EE + n0 + cn) = __floats2half2_rn(ox, oy);
                }
            }
        }
    }
}

// ---------------- merged Q+R projection -----------------------------------------
__global__ __launch_bounds__(256)
void hgemm_qr(const __half* __restrict__ vk, const __half* __restrict__ pe,
              const __half* __restrict__ Wq, const __half* __restrict__ Wr,
              __half* __restrict__ q, __half* __restrict__ r,
              const float* __restrict__ bq) {
    const int z = blockIdx.z;
    const int m0 = blockIdx.y * 128;
    const bool isr = (z == 8);
    if (!isr && blockIdx.y >= 4) return;

    extern __shared__ __align__(16) char smemc[];
    const uint32_t sbase = smem_u32(smemc);
    constexpr int ABUF_B  = 128 * HROW_B;
    constexpr int STAGE_B = 2 * ABUF_B;

    const int tid = threadIdx.x;
    const int n0 = blockIdx.x * 128;
    const __half* Ap = (isr ? pe : (vk + (long)MEM_ * EE + (long)z * KK * EE))
                       + (long)m0 * EE;
    const __half* Bp = (isr ? Wr : Wq) + (long)n0 * EE;
    __half* Cb = isr ? (r + (long)m0 * EE) : (q + (long)z * SS * EE + (long)m0 * EE);

    GEMM_CORE_DECL
    const int wn = (w >> 2) * 64;
    const uint32_t a_lm = (uint32_t)((wm + (seg & 1) * 8 + rr) * HROW_B + (seg >> 1) * 16);
    const uint32_t b_lm = (uint32_t)(ABUF_B + (wn + (seg >> 1) * 8 + rr) * HROW_B
                                     + (seg & 1) * 16);

    auto issue_stage = [&](int c, int s) {
        uint32_t sa = sbase + (uint32_t)(s * STAGE_B);
        uint32_t sb = sa + (uint32_t)ABUF_B;
#pragma unroll
        for (int i = 0; i < 4; i++) {
            int idx = tid + i * 256;
            int row = idx >> 3, sg = idx & 7;
            cp_async16(sa + (uint32_t)(row * HROW_B + sg * 16),
                       Ap + (long)row * EE + c * KC + sg * 8);
            cp_async16(sb + (uint32_t)(row * HROW_B + sg * 16),
                       Bp + (long)row * EE + c * KC + sg * 8);
        }
    };

    issue_stage(0, 0);
    cp_commit();
    float acc[2][8][4] = {};
    for (int c = 0; c < 8; c++) {
        if (c + 1 < 8) issue_stage(c + 1, (c + 1) & 1);
        cp_commit();
        cp_wait1();
        __syncthreads();
        const uint32_t stg = sbase + (uint32_t)((c & 1) * STAGE_B);
#pragma unroll
        for (int ks = 0; ks < 4; ks++) {
            const uint32_t k0b = ks * 32;
            uint32_t af[2][4], bf[8][2];
#pragma unroll
            for (int mt = 0; mt < 2; mt++)
                LDM_X4(af[mt][0], af[mt][1], af[mt][2], af[mt][3],
                       stg + a_lm + mt * 16 * HROW_B + k0b);
#pragma unroll
            for (int np = 0; np < 4; np++)
                LDM_X4(bf[2*np][0], bf[2*np][1], bf[2*np+1][0], bf[2*np+1][1],
                       stg + b_lm + np * 16 * HROW_B + k0b);
#pragma unroll
            for (int mt = 0; mt < 2; mt++)
#pragma unroll
                for (int nt = 0; nt < 8; nt++)
                    mma_f16(acc[mt][nt], af[mt], bf[nt]);
        }
        __syncthreads();
    }

#pragma unroll
    for (int mt = 0; mt < 2; mt++) {
#pragma unroll
        for (int hf = 0; hf < 2; hf++) {
            const int rl = wm + mt * 16 + g + hf * 8;
#pragma unroll
            for (int nt = 0; nt < 8; nt++) {
                const int cn = wn + nt * 8 + t4 * 2;
                float ox = acc[mt][nt][hf * 2 + 0];
                float oy = acc[mt][nt][hf * 2 + 1];
                if (!isr) {
                    float2 b2 = *(const float2*)(bq + n0 + cn);
                    ox += b2.x; oy += b2.y;
                }
                *(__half2*)(Cb + (long)rl * EE + n0 + cn) = __floats2half2_rn(ox, oy);
            }
        }
    }
}

// ---------------- merged AC+P score GEMM ----------------------------------------
__global__ __launch_bounds__(256)
void hgemm_qk2(const __half* __restrict__ q,
               const __half* __restrict__ k, const __half* __restrict__ r,
               __half* __restrict__ sc, __half* __restrict__ P,
               const float* __restrict__ cu, const float* __restrict__ cv) {
    const int m0 = blockIdx.y * 128;
    const int n0 = blockIdx.x * 128;
    const int z = blockIdx.z;
    const int task = z >> 6, zz = z & 63;
    if (task == 0) { if (n0 >= MEM_ + m0 + 128) return; }
    else           { if (n0 + 127 < (SS - 1) - (m0 + 127)) return; }

    extern __shared__ __align__(16) char smemc[];
    const uint32_t sbase = smem_u32(smemc);
    constexpr int ABUF_B = 128 * HROW_B;

    const int tid = threadIdx.x;
    const int bb = zz >> 3, hh = zz & 7;

    const __half* Ap = q + (long)bb * SS * EE + hh * DH_ + (long)m0 * EE;
    const __half* Bp = (task ? (r + hh * DH_)
                             : (k + (long)bb * KK * EE + hh * DH_)) + (long)n0 * EE;
    __half* C = (task ? P : sc) + ((long)zz * SS) * KK;
    const float* cbp = (task ? (cv + hh * KK) : (cu + (long)zz * KK)) + n0;

    GEMM_CORE_DECL
    const int wn = (w >> 2) * 64;
    const uint32_t a_lm = (uint32_t)((wm + (seg & 1) * 8 + rr) * HROW_B + (seg >> 1) * 16);
    const uint32_t b_lm = (uint32_t)(ABUF_B + (wn + (seg >> 1) * 8 + rr) * HROW_B
                                     + (seg & 1) * 16);

#pragma unroll
    for (int i = 0; i < 4; i++) {
        int idx = tid + i * 256;
        int row = idx >> 3, sg = idx & 7;
        cp_async16(sbase + (uint32_t)(row * HROW_B + sg * 16),
                   Ap + (long)row * EE + sg * 8);
        cp_async16(sbase + (uint32_t)(ABUF_B + row * HROW_B + sg * 16),
                   Bp + (long)row * EE + sg * 8);
    }
    cp_commit();
    cp_wait0();
    __syncthreads();

    float acc[2][8][4] = {};
#pragma unroll
    for (int ks = 0; ks < 4; ks++) {
        const uint32_t k0b = ks * 32;
        uint32_t af[2][4], bf[8][2];
#pragma unroll
        for (int mt = 0; mt < 2; mt++)
            LDM_X4(af[mt][0], af[mt][1], af[mt][2], af[mt][3],
                   sbase + a_lm + mt * 16 * HROW_B + k0b);
#pragma unroll
        for (int np = 0; np < 4; np++)
            LDM_X4(bf[2*np][0], bf[2*np][1], bf[2*np+1][0], bf[2*np+1][1],
                   sbase + b_lm + np * 16 * HROW_B + k0b);
#pragma unroll
        for (int mt = 0; mt < 2; mt++)
#pragma unroll
            for (int nt = 0; nt < 8; nt++)
                mma_f16(acc[mt][nt], af[mt], bf[nt]);
    }

#pragma unroll
    for (int mt = 0; mt < 2; mt++) {
#pragma unroll
        for (int hf = 0; hf < 2; hf++) {
            const int row = m0 + wm + mt * 16 + g + hf * 8;
            __half* Cr = C + (long)row * KK + n0;
#pragma unroll
            for (int nt = 0; nt < 8; nt++) {
                const int cn = wn + nt * 8 + t4 * 2;
                float2 b2 = *(const float2*)(cbp + cn);
                *(__half2*)(Cr + cn) = __floats2half2_rn(
                    acc[mt][nt][hf * 2 + 0] * 0.125f + b2.x,
                    acc[mt][nt][hf * 2 + 1] * 0.125f + b2.y);
            }
        }
    }
}

// ---------------- batched 512x512 weight transpose+convert (one launch) --------
struct WTab {
    const float* s[7];
    __half*      d[7];
    long         dstride[7];
};
__global__ __launch_bounds__(256)
void w_tr_all(WTab tab) {
    __shared__ float t[64][65];
    const int z = blockIdx.z;
    const int wi = z >> 2, l = z & 3;
    const float* W = tab.s[wi] + (long)l * LW;
    __half* Wt = tab.d[wi] + (long)l * tab.dstride[wi];
    const int k0 = blockIdx.y * 64, n0 = blockIdx.x * 64;
    const int tid = threadIdx.x;
    // load 64x64 fp32 tile (float4)
#pragma unroll
    for (int i = 0; i < 4; i++) {
        int idx = tid + i * 256;
        int r = idx >> 4, c4 = (idx & 15) * 4;
        float4 v = *(const float4*)(W + (long)(k0 + r) * EE + n0 + c4);
        t[r][c4+0] = v.x; t[r][c4+1] = v.y; t[r][c4+2] = v.z; t[r][c4+3] = v.w;
    }
    __syncthreads();
    // store transposed as half2
#pragma unroll
    for (int i = 0; i < 8; i++) {
        int idx = tid + i * 256;
        int r = idx >> 5, c2 = (idx & 31) * 2;
        *(__half2*)(Wt + (long)(n0 + r) * EE + k0 + c2) =
            __floats2half2_rn(t[c2][r], t[c2 + 1][r]);
    }
}

// encoder weight (128x512) transpose
__global__ __launch_bounds__(256)
void w_tr(const float* __restrict__ W, __half* __restrict__ Wt, int K, int N) {
    __shared__ float t[32][33];
    int k0 = blockIdx.y * 32, n0 = blockIdx.x * 32;
    int tid = threadIdx.x;
#pragma unroll
    for (int i = 0; i < 4; i++) {
        int idx = tid + i * 256;
        int r = idx >> 5, c = idx & 31;
        t[r][c] = W[(long)(k0 + r) * N + n0 + c];
    }
    __syncthreads();
#pragma unroll
    for (int i = 0; i < 4; i++) {
        int idx = tid + i * 256;
        int r = idx >> 5, c = idx & 31;
        Wt[(long)(n0 + r) * K + k0 + c] = __float2half_rn(t[c][r]);
    }
}

__global__ void conv_half(const float* __restrict__ in, __half* __restrict__ outp) {
    int idx = blockIdx.x * 256 + threadIdx.x;       // processes 4 elems
    float4 v = *(const float4*)(in + idx * 4);
    *(__half2*)(outp + idx * 4)     = __floats2half2_rn(v.x, v.y);
    *(__half2*)(outp + idx * 4 + 2) = __floats2half2_rn(v.z, v.w);
}

__global__ void pe_kernel(__half* __restrict__ pe) {
    int idx = blockIdx.x * 256 + threadIdx.x;
    int m = idx >> 9, c = idx & 511;
    double pos  = (double)(KK - m);
    int    t2   = c & 255;
    double invf = exp(-((double)(2 * t2) / 512.0) * log(10000.0));
    double a    = pos * invf;
    pe[idx] = __float2half_rn((float)((c < 256) ? sin(a) : cos(a)));
}

// ---------------- layer norm (fp32 in, half out) --------------------------------
__device__ __forceinline__ void ln_row_h(const float* __restrict__ src,
                                         __half* __restrict__ dst,
                                         const float* __restrict__ g,
                                         const float* __restrict__ be, int lane) {
    float4 vals[4];
    float s = 0.f, ss = 0.f;
#pragma unroll
    for (int t = 0; t < 4; t++) {
        vals[t] = *(const float4*)(src + lane * 4 + t * 128);
        s  += vals[t].x + vals[t].y + vals[t].z + vals[t].w;
        ss += vals[t].x*vals[t].x + vals[t].y*vals[t].y
            + vals[t].z*vals[t].z + vals[t].w*vals[t].w;
    }
#pragma unroll
    for (int o = 16; o; o >>= 1) {
        s  += __shfl_xor_sync(0xffffffffu, s,  o);
        ss += __shfl_xor_sync(0xffffffffu, ss, o);
    }
    float mean = s * (1.f / 512.f);
    float var  = ss * (1.f / 512.f) - mean * mean;
    float rstd = rsqrtf(var + 1e-6f);
#pragma unroll
    for (int t = 0; t < 4; t++) {
        int e = lane * 4 + t * 128;
        float ox = (vals[t].x - mean) * rstd * g[e+0] + be[e+0];
        float oy = (vals[t].y - mean) * rstd * g[e+1] + be[e+1];
        float oz = (vals[t].z - mean) * rstd * g[e+2] + be[e+2];
        float ow = (vals[t].w - mean) * rstd * g[e+3] + be[e+3];
        *(__half2*)(dst + e)     = __floats2half2_rn(ox, oy);
        *(__half2*)(dst + e + 2) = __floats2half2_rn(oz, ow);
    }
}

__global__ void ln_concat_k(const float* __restrict__ mem, const float* __restrict__ x,
                            const float* __restrict__ gam, const float* __restrict__ bet,
                            __half* __restrict__ out, int l) {
    int row  = blockIdx.x * 8 + (threadIdx.x >> 5);
    int lane = threadIdx.x & 31;
    int b = row >> 10, j = row & 1023;
    const float* src = (j < MEM_)
        ? (mem + ((long)(b * MEM_ + j) * LL + l) * EE)
        : (x   +  (long)(b * SS + (j - MEM_)) * EE);
    ln_row_h(src, out + (long)row * EE, gam + l * EE, bet + l * EE, lane);
}

__global__ void ln_plain_k(const float* __restrict__ in,
                           const float* __restrict__ gam, const float* __restrict__ bet,
                           __half* __restrict__ out, int l) {
    int row  = blockIdx.x * 8 + (threadIdx.x >> 5);
    int lane = threadIdx.x & 31;
    ln_row_h(in + (long)row * EE, out + (long)row * EE, gam + l * EE, bet + l * EE, lane);
}

// ---------------- merged column-bias prep ---------------------------------------
__global__ __launch_bounds__(256)
void bias_uk2(const __half* __restrict__ kmat, const __half* __restrict__ rmat,
              const float* __restrict__ uvec, const float* __restrict__ vvec,
              float* __restrict__ cu, float* __restrict__ cv) {
    int y = blockIdx.y;
    int j = blockIdx.x * 8 + (threadIdx.x >> 5);
    int lane = threadIdx.x & 31;
    const bool isv = (y == BB);
    const __half* krow = (isv ? rmat : (kmat + (long)y * KK * EE)) + (long)j * EE;
    const float* uv = isv ? vvec : uvec;
    float* orow = isv ? cv : (cu + (long)y * HH * KK);
#pragma unroll
    for (int h = 0; h < HH; h++) {
        float s = __half2float(krow[h * 64 + lane])      * uv[h * 64 + lane]
                + __half2float(krow[h * 64 + lane + 32]) * uv[h * 64 + lane + 32];
#pragma unroll
        for (int o = 16; o; o >>= 1) s += __shfl_xor_sync(0xffffffffu, s, o);
        if (lane == 0) orow[h * KK + j] = 0.125f * s;
    }
}

// ---------------- masked rel-shift softmax (half2 vectorized) -------------------
__global__ __launch_bounds__(256)
void softmax_k(__half* __restrict__ sc, const __half* __restrict__ P) {
    long row = (long)blockIdx.x * 8 + (threadIdx.x >> 5);
    int lane = threadIdx.x & 31;
    int i = (int)(row & (SS - 1));
    int jmax = MEM_ + i;
    int nfill = (MEM_ + (i | 127) + 1) >> 5;
    __half* srow = sc + row * KK;
    const __half* prow = P + row * KK + (SS - 1 - i);
    float v[32];
    float mx = -1e30f;
#pragma unroll
    for (int t = 0; t < 16; t++) {
        int j2 = t * 64 + lane * 2;
        float x0 = -1e30f, x1 = -1e30f;
        if (j2 + 1 <= jmax) {
            float2 s2 = __half22float2(*(const __half2*)(srow + j2));
            x0 = s2.x + __half2float(prow[j2]);
            x1 = s2.y + __half2float(prow[j2 + 1]);
        } else if (j2 <= jmax) {
            x0 = __half2float(srow[j2]) + __half2float(prow[j2]);
        }
        v[2*t] = x0; v[2*t+1] = x1;
        mx = fmaxf(mx, fmaxf(x0, x1));
    }
#pragma unroll
    for (int o = 16; o; o >>= 1) mx = fmaxf(mx, __shfl_xor_sync(0xffffffffu, mx, o));
    float s = 0.f;
#pragma unroll
    for (int t = 0; t < 32; t++) {
        float e = (v[t] > -1e29f) ? __expf(v[t] - mx) : 0.f;
        v[t] = e; s += e;
    }
#pragma unroll
    for (int o = 16; o; o >>= 1) s += __shfl_xor_sync(0xffffffffu, s, o);
    float inv = 1.f / s;
#pragma unroll
    for (int t = 0; t < 16; t++) {
        int j2 = t * 64 + lane * 2;
        if ((j2 >> 5) < nfill)
            *(__half2*)(srow + j2) = __floats2half2_rn(v[2*t] * inv, v[2*t+1] * inv);
    }
}

// ---------------- host orchestration --------------------------------------------
#define SM128 (2 * (128 + 128) * HROW_B)
#define SM64  (2 * (128 + 64)  * HROW_B)
#define SMQK  (2 * 128 * HROW_B)

extern "C" void kernel_launch(void* const* d_in, const int* in_sizes, int n_in,
                              void* d_out, int out_size) {
    (void)in_sizes; (void)n_in; (void)out_size;
    const float* obs    = (const float*)d_in[0];
    const float* mems   = (const float*)d_in[1];
    const float* W_enc  = (const float*)d_in[3];
    const float* b_enc  = (const float*)d_in[4];
    const float* ln1_s  = (const float*)d_in[5];
    const float* ln1_b  = (const float*)d_in[6];
    const float* Wq     = (const float*)d_in[7];
    const float* bq     = (const float*)d_in[8];
    const float* Wk     = (const float*)d_in[9];
    const float* bk     = (const float*)d_in[10];
    const float* Wv     = (const float*)d_in[11];
    const float* bv     = (const float*)d_in[12];
    const float* Wr     = (const float*)d_in[13];
    const float* ub     = (const float*)d_in[14];
    const float* vbias  = (const float*)d_in[15];
    const float* Wo     = (const float*)d_in[16];
    const float* bo     = (const float*)d_in[17];
    const float* ln2_s  = (const float*)d_in[18];
    const float* ln2_b  = (const float*)d_in[19];
    const float* W1     = (const float*)d_in[20];
    const float* b1     = (const float*)d_in[21];
    const float* W2     = (const float*)d_in[22];
    const float* b2     = (const float*)d_in[23];
    float* out = (float*)d_out;

    float *px, *ph, *pcu, *pcv;
    __half *pobsh, *pvkh, *pqh, *pkh, *pvth, *poh, *prh, *ppeh, *phnh, *pth, *psch, *pPh;
    __half *pwet, *pwkvt, *pwqt, *pwrt, *pwot, *pw1t, *pw2t;
    cudaGetSymbolAddress((void**)&px,   g_x);
    cudaGetSymbolAddress((void**)&ph,   g_h);
    cudaGetSymbolAddress((void**)&pcu,  g_cu);
    cudaGetSymbolAddress((void**)&pcv,  g_cv);
    cudaGetSymbolAddress((void**)&pobsh,g_obsh);
    cudaGetSymbolAddress((void**)&pvkh, g_vkh);
    cudaGetSymbolAddress((void**)&pqh,  g_qh);
    cudaGetSymbolAddress((void**)&pkh,  g_kh);
    cudaGetSymbolAddress((void**)&pvth, g_vth);
    cudaGetSymbolAddress((void**)&poh,  g_oh);
    cudaGetSymbolAddress((void**)&prh,  g_rh);
    cudaGetSymbolAddress((void**)&ppeh, g_peh);
    cudaGetSymbolAddress((void**)&phnh, g_hnh);
    cudaGetSymbolAddress((void**)&pth,  g_th);
    cudaGetSymbolAddress((void**)&psch, g_sch);
    cudaGetSymbolAddress((void**)&pPh,  g_Ph);
    cudaGetSymbolAddress((void**)&pwet, g_wet);
    cudaGetSymbolAddress((void**)&pwkvt,g_wkvt);
    cudaGetSymbolAddress((void**)&pwqt, g_wqt);
    cudaGetSymbolAddress((void**)&pwrt, g_wrt);
    cudaGetSymbolAddress((void**)&pwot, g_wot);
    cudaGetSymbolAddress((void**)&pw1t, g_w1t);
    cudaGetSymbolAddress((void**)&pw2t, g_w2t);

    cudaFuncSetAttribute(hgemm<128,1,0,0>, cudaFuncAttributeMaxDynamicSharedMemorySize, SM128);
    cudaFuncSetAttribute(hgemm<128,3,0,0>, cudaFuncAttributeMaxDynamicSharedMemorySize, SM128);
    cudaFuncSetAttribute(hgemm<128,2,1,0>, cudaFuncAttributeMaxDynamicSharedMemorySize, SM128);
    cudaFuncSetAttribute(hgemm<64,0,1,1>,  cudaFuncAttributeMaxDynamicSharedMemorySize, SM64);
    cudaFuncSetAttribute(hgemm_kv,  cudaFuncAttributeMaxDynamicSharedMemorySize, SM128);
    cudaFuncSetAttribute(hgemm_qr,  cudaFuncAttributeMaxDynamicSharedMemorySize, SM128);
    cudaFuncSetAttribute(hgemm_qk2, cudaFuncAttributeMaxDynamicSharedMemorySize, SMQK);

    const long SE = (long)SS * EE, KE = (long)KK * EE, SK = (long)SS * KK;
    const long HSK = (long)HH * SK;
    const long EK = (long)EE * KK;
    const long LKV = (long)1024 * 512;

    // ---- one-time conversions (2 launches + pe + conv) ----
    conv_half<<<(BB * SS * OBS_) / 1024, 256>>>(obs, pobsh);
    w_tr<<<dim3(16, 4), 256>>>(W_enc, pwet, OBS_, EE);
    WTab tab;
    tab.s[0] = Wk; tab.d[0] = pwkvt;                  tab.dstride[0] = LKV;
    tab.s[1] = Wv; tab.d[1] = pwkvt + (long)512*512;  tab.dstride[1] = LKV;
    tab.s[2] = Wq; tab.d[2] = pwqt;  tab.dstride[2] = LW;
    tab.s[3] = Wr; tab.d[3] = pwrt;  tab.dstride[3] = LW;
    tab.s[4] = Wo; tab.d[4] = pwot;  tab.dstride[4] = LW;
    tab.s[5] = W1; tab.d[5] = pw1t;  tab.dstride[5] = LW;
    tab.s[6] = W2; tab.d[6] = pw2t;  tab.dstride[6] = LW;
    w_tr_all<<<dim3(8, 8, 28), 256>>>(tab);
    pe_kernel<<<(KK * EE) / 256, 256>>>(ppeh);

    // encoder
    hgemm<128,1,0,0><<<dim3(4, 32, 1), 256, SM128>>>(
        pobsh, 0, 0, OBS_, pwet, 0, 0, OBS_, px, 0, 0, EE,
        b_enc, nullptr, 1, OBS_);

    for (int l = 0; l < LL; l++) {
        ln_concat_k<<<(BB * KK) / 8, 256>>>(mems, px, ln1_s, ln1_b, pvkh, l);

        hgemm_kv<<<dim3(8, 64), 256, SM128>>>(
            pvkh, pwkvt + (long)l * LKV, pkh, pvth, bk + l * EE, bv + l * EE);
        hgemm_qr<<<dim3(4, 8, 9), 256, SM128>>>(
            pvkh, ppeh, pwqt + (long)l * LW, pwrt + (long)l * LW,
            pqh, prh, bq + l * EE);

        bias_uk2<<<dim3(KK / 8, BB + 1), 256>>>(
            pkh, prh, ub + (long)l * EE, vbias + (long)l * EE, pcu, pcv);

        hgemm_qk2<<<dim3(8, 4, 128), 256, SMQK>>>(
            pqh, pkh, prh, psch, pPh, pcu, pcv);

        softmax_k<<<(BB * HH * SS) / 8, 256>>>(psch, pPh);

        hgemm<64,0,1,1><<<dim3(1, 4, BB * HH), 256, SM64>>>(
            psch, HSK, SK, KK, pvth, EK, (long)64 * KK, KK,
            poh, SE, 64, EE, nullptr, nullptr, HH, KK);

        hgemm<128,3,0,0><<<dim3(4, 32, 1), 256, SM128>>>(
            poh, 0, 0, EE, pwot + (long)l * LW, 0, 0, EE, ph, 0, 0, EE,
            bo + l * EE, px, 1, EE);
        ln_plain_k<<<(BB * SS) / 8, 256>>>(ph, ln2_s, ln2_b, phnh, l);
        hgemm<128,2,1,0><<<dim3(4, 32, 1), 256, SM128>>>(
            phnh, 0, 0, EE, pw1t + (long)l * LW, 0, 0, EE, pth, 0, 0, EE,
            b1 + l * EE, nullptr, 1, EE);
        float* xo = (l == LL - 1) ? out : px;
        hgemm<128,3,0,0><<<dim3(4, 32, 1), 256, SM128>>>(
            pth, 0, 0, EE, pw2t + (long)l * LW, 0, 0, EE, xo, 0, 0, EE,
            b2 + l * EE, ph, 1, EE);
    }
}